// round 2
// baseline (speedup 1.0000x reference)
#include <cuda_runtime.h>
#include <math.h>

#define DIMC   1024
#define NSEQ   2048
#define BATCH  2
#define NHEADS 16
#define HD     64
#define MROWS  (BATCH * NSEQ)     // 4096
#define BHNUM  (BATCH * NHEADS)   // 32

// Scratch (static device globals — no allocation allowed)
__device__ float g_qn[(size_t)MROWS * DIMC];
__device__ float g_kn[(size_t)MROWS * DIMC];
__device__ float g_vn[(size_t)MROWS * DIMC];
__device__ float g_qh[(size_t)MROWS * DIMC];   // [bh][n][64]
__device__ float g_oh[(size_t)MROWS * DIMC];   // [bh][n][64]

// ---------------------------------------------------------------------------
// LayerNorm: one block per row of 1024, 256 threads, 1 float4 per thread.
// ---------------------------------------------------------------------------
__global__ void __launch_bounds__(256) ln_kernel(const float* __restrict__ x,
                                                 const float* __restrict__ g,
                                                 const float* __restrict__ b,
                                                 float* __restrict__ y) {
    const int row = blockIdx.x;
    const int tid = threadIdx.x;
    const float4 v = reinterpret_cast<const float4*>(x + (size_t)row * DIMC)[tid];
    float s  = v.x + v.y + v.z + v.w;
    float ss = v.x * v.x + v.y * v.y + v.z * v.z + v.w * v.w;
#pragma unroll
    for (int off = 16; off > 0; off >>= 1) {
        s  += __shfl_xor_sync(0xffffffffu, s, off);
        ss += __shfl_xor_sync(0xffffffffu, ss, off);
    }
    __shared__ float rs[8], rss[8];
    if ((tid & 31) == 0) { rs[tid >> 5] = s; rss[tid >> 5] = ss; }
    __syncthreads();
    float tot = 0.f, totss = 0.f;
#pragma unroll
    for (int i = 0; i < 8; i++) { tot += rs[i]; totss += rss[i]; }
    const float mean = tot * (1.0f / DIMC);
    const float var  = totss * (1.0f / DIMC) - mean * mean;
    const float rstd = rsqrtf(var + 1e-5f);
    const float4 g4 = reinterpret_cast<const float4*>(g)[tid];
    const float4 b4 = reinterpret_cast<const float4*>(b)[tid];
    float4 o;
    o.x = (v.x - mean) * rstd * g4.x + b4.x;
    o.y = (v.y - mean) * rstd * g4.y + b4.y;
    o.z = (v.z - mean) * rstd * g4.z + b4.z;
    o.w = (v.w - mean) * rstd * g4.w + b4.w;
    reinterpret_cast<float4*>(y + (size_t)row * DIMC)[tid] = o;
}

// ---------------------------------------------------------------------------
// GEMM + bias: C[M=4096, N=1024] = A[4096,1024] @ W[1024,1024] + bias
// 128x128 block tile, BK=8, 256 threads, 8x8 per-thread (split 4+4).
// AHEAD: A is in [bh][n][64] head layout (read side).
// CHEAD: C is written to [bh][n][64] head layout (write side).
// ---------------------------------------------------------------------------
template <bool AHEAD, bool CHEAD>
__global__ void __launch_bounds__(256) gemm_bias_kernel(const float* __restrict__ A,
                                                        const float* __restrict__ W,
                                                        const float* __restrict__ bias,
                                                        float* __restrict__ C) {
    __shared__ float As[8][132];   // transposed A tile, padded: conflict-free
    __shared__ float Bs[8][128];
    const int tid  = threadIdx.x;
    const int bm   = blockIdx.y * 128;
    const int bn   = blockIdx.x * 128;
    const int tm   = (tid >> 4) * 4;   // 0..60
    const int tn   = (tid & 15) * 4;   // 0..60
    const int arow = tid >> 1;
    const int acb  = (tid & 1) * 4;
    const int brow = tid >> 5;
    const int bcol = (tid & 31) * 4;

    float acc[8][8];
#pragma unroll
    for (int i = 0; i < 8; i++)
#pragma unroll
        for (int j = 0; j < 8; j++) acc[i][j] = 0.f;

    for (int k0 = 0; k0 < DIMC; k0 += 8) {
        float4 a4;
        {
            const int gr = bm + arow;
            const int gc = k0 + acb;
            const float* ap;
            if (AHEAD) {
                const int bi = gr >> 11, n = gr & (NSEQ - 1);
                const int h = gc >> 6, d = gc & 63;
                ap = A + (((size_t)(bi * NHEADS + h) * NSEQ + n) << 6) + d;
            } else {
                ap = A + (size_t)gr * DIMC + gc;
            }
            a4 = *reinterpret_cast<const float4*>(ap);
        }
        const float4 b4 =
            *reinterpret_cast<const float4*>(W + (size_t)(k0 + brow) * DIMC + bn + bcol);
        As[acb + 0][arow] = a4.x;
        As[acb + 1][arow] = a4.y;
        As[acb + 2][arow] = a4.z;
        As[acb + 3][arow] = a4.w;
        *reinterpret_cast<float4*>(&Bs[brow][bcol]) = b4;
        __syncthreads();
#pragma unroll
        for (int kk = 0; kk < 8; kk++) {
            float ar[8], br[8];
            *reinterpret_cast<float4*>(ar)     = *reinterpret_cast<const float4*>(&As[kk][tm]);
            *reinterpret_cast<float4*>(ar + 4) = *reinterpret_cast<const float4*>(&As[kk][tm + 64]);
            *reinterpret_cast<float4*>(br)     = *reinterpret_cast<const float4*>(&Bs[kk][tn]);
            *reinterpret_cast<float4*>(br + 4) = *reinterpret_cast<const float4*>(&Bs[kk][tn + 64]);
#pragma unroll
            for (int i = 0; i < 8; i++)
#pragma unroll
                for (int j = 0; j < 8; j++) acc[i][j] += ar[i] * br[j];
        }
        __syncthreads();
    }

    float bl[8];
#pragma unroll
    for (int jg = 0; jg < 2; jg++)
        *reinterpret_cast<float4*>(bl + jg * 4) =
            *reinterpret_cast<const float4*>(bias + bn + tn + jg * 64);

#pragma unroll
    for (int i = 0; i < 8; i++) {
        const int r = bm + tm + (i & 3) + (i >> 2) * 64;
#pragma unroll
        for (int jg = 0; jg < 2; jg++) {
            const int c0 = bn + tn + jg * 64;
            float4 o;
            o.x = acc[i][jg * 4 + 0] + bl[jg * 4 + 0];
            o.y = acc[i][jg * 4 + 1] + bl[jg * 4 + 1];
            o.z = acc[i][jg * 4 + 2] + bl[jg * 4 + 2];
            o.w = acc[i][jg * 4 + 3] + bl[jg * 4 + 3];
            if (CHEAD) {
                const int bi = r >> 11, n = r & (NSEQ - 1);
                const int h = c0 >> 6, d = c0 & 63;
                *reinterpret_cast<float4*>(C + (((size_t)(bi * NHEADS + h) * NSEQ + n) << 6) + d) = o;
            } else {
                *reinterpret_cast<float4*>(C + (size_t)r * DIMC + c0) = o;
            }
        }
    }
}

// ---------------------------------------------------------------------------
// Flash attention: per (b,h), BQ=BK=64, 256 threads in 16x16, 4x4 micro-tile.
// Q/K smem rows XOR-swizzled so the strided row reads (rows 4t+j) are
// conflict-free without padding. V/P tiles use the natural [row][d] layout.
// ---------------------------------------------------------------------------
__device__ __forceinline__ int ksw(int row, int col) {
    return row * 64 + (col ^ (((row >> 2) & 7) << 2));
}

__global__ void __launch_bounds__(256) flash_kernel(const float* __restrict__ Q,
                                                    const float* __restrict__ K,
                                                    const float* __restrict__ V,
                                                    float* __restrict__ O) {
    extern __shared__ float smx[];
    float* Qs = smx;          // 64x64 swizzled (pre-scaled by SCALE)
    float* Ks = Qs + 4096;    // 64x64 swizzled
    float* Vs = Ks + 4096;    // 64x64 plain
    float* Ps = Vs + 4096;    // 64x64 plain
    const int tid = threadIdx.x;
    const int ty4 = (tid >> 4) * 4;
    const int tx4 = (tid & 15) * 4;
    const size_t base = (size_t)blockIdx.y * NSEQ * HD;
    const int q0 = blockIdx.x * 64;
    const float scale = 0.125f;   // 64^-0.5

#pragma unroll
    for (int it = 0; it < 4; it++) {
        const int s = tid + it * 256;
        const int row = s >> 4;
        const int d4 = (s & 15) * 4;
        float4 v = *reinterpret_cast<const float4*>(Q + base + (size_t)(q0 + row) * HD + d4);
        v.x *= scale; v.y *= scale; v.z *= scale; v.w *= scale;
        *reinterpret_cast<float4*>(&Qs[ksw(row, d4)]) = v;
    }

    float m_i[4], l_i[4], o_acc[4][4];
#pragma unroll
    for (int i = 0; i < 4; i++) {
        m_i[i] = -1e30f;
        l_i[i] = 0.f;
#pragma unroll
        for (int j = 0; j < 4; j++) o_acc[i][j] = 0.f;
    }

    for (int kt = 0; kt < NSEQ / 64; kt++) {
        __syncthreads();   // prev AV done before overwriting tiles
        const int kbase = kt * 64;
#pragma unroll
        for (int it = 0; it < 4; it++) {
            const int s = tid + it * 256;
            const int row = s >> 4;
            const int d4 = (s & 15) * 4;
            const float4 kv4 =
                *reinterpret_cast<const float4*>(K + base + (size_t)(kbase + row) * HD + d4);
            *reinterpret_cast<float4*>(&Ks[ksw(row, d4)]) = kv4;
            const float4 vv4 =
                *reinterpret_cast<const float4*>(V + base + (size_t)(kbase + row) * HD + d4);
            *reinterpret_cast<float4*>(&Vs[row * 64 + d4]) = vv4;
        }
        __syncthreads();

        float s4[4][4];
#pragma unroll
        for (int i = 0; i < 4; i++)
#pragma unroll
            for (int j = 0; j < 4; j++) s4[i][j] = 0.f;

#pragma unroll
        for (int d = 0; d < 64; d += 4) {
            float4 qf[4], kf[4];
#pragma unroll
            for (int i = 0; i < 4; i++)
                qf[i] = *reinterpret_cast<const float4*>(&Qs[ksw(ty4 + i, d)]);
#pragma unroll
            for (int j = 0; j < 4; j++)
                kf[j] = *reinterpret_cast<const float4*>(&Ks[ksw(tx4 + j, d)]);
#pragma unroll
            for (int i = 0; i < 4; i++)
#pragma unroll
                for (int j = 0; j < 4; j++)
                    s4[i][j] += qf[i].x * kf[j].x + qf[i].y * kf[j].y +
                                qf[i].z * kf[j].z + qf[i].w * kf[j].w;
        }

#pragma unroll
        for (int i = 0; i < 4; i++) {
            float rm = fmaxf(fmaxf(s4[i][0], s4[i][1]), fmaxf(s4[i][2], s4[i][3]));
#pragma unroll
            for (int off = 1; off < 16; off <<= 1)
                rm = fmaxf(rm, __shfl_xor_sync(0xffffffffu, rm, off, 16));
            const float mnew = fmaxf(m_i[i], rm);
            const float corr = __expf(m_i[i] - mnew);
            m_i[i] = mnew;
            float rsum = 0.f;
#pragma unroll
            for (int j = 0; j < 4; j++) {
                const float p = __expf(s4[i][j] - mnew);
                s4[i][j] = p;
                rsum += p;
            }
#pragma unroll
            for (int off = 1; off < 16; off <<= 1)
                rsum += __shfl_xor_sync(0xffffffffu, rsum, off, 16);
            l_i[i] = l_i[i] * corr + rsum;
#pragma unroll
            for (int j = 0; j < 4; j++) o_acc[i][j] *= corr;
            float4 pv;
            pv.x = s4[i][0]; pv.y = s4[i][1]; pv.z = s4[i][2]; pv.w = s4[i][3];
            *reinterpret_cast<float4*>(&Ps[(ty4 + i) * 64 + tx4]) = pv;
        }
        __syncthreads();

#pragma unroll
        for (int kv = 0; kv < 64; kv += 4) {
            float4 vf[4];
#pragma unroll
            for (int kk = 0; kk < 4; kk++)
                vf[kk] = *reinterpret_cast<const float4*>(&Vs[(kv + kk) * 64 + tx4]);
#pragma unroll
            for (int i = 0; i < 4; i++) {
                const float4 pf = *reinterpret_cast<const float4*>(&Ps[(ty4 + i) * 64 + kv]);
                o_acc[i][0] += pf.x * vf[0].x + pf.y * vf[1].x + pf.z * vf[2].x + pf.w * vf[3].x;
                o_acc[i][1] += pf.x * vf[0].y + pf.y * vf[1].y + pf.z * vf[2].y + pf.w * vf[3].y;
                o_acc[i][2] += pf.x * vf[0].z + pf.y * vf[1].z + pf.z * vf[2].z + pf.w * vf[3].z;
                o_acc[i][3] += pf.x * vf[0].w + pf.y * vf[1].w + pf.z * vf[2].w + pf.w * vf[3].w;
            }
        }
    }

#pragma unroll
    for (int i = 0; i < 4; i++) {
        const float inv = 1.0f / l_i[i];
        float4 o;
        o.x = o_acc[i][0] * inv;
        o.y = o_acc[i][1] * inv;
        o.z = o_acc[i][2] * inv;
        o.w = o_acc[i][3] * inv;
        *reinterpret_cast<float4*>(O + base + (size_t)(q0 + ty4 + i) * HD + tx4) = o;
    }
}

// ---------------------------------------------------------------------------
extern "C" void kernel_launch(void* const* d_in, const int* in_sizes, int n_in,
                              void* d_out, int out_size) {
    const float* q    = (const float*)d_in[0];
    const float* k    = (const float*)d_in[1];
    const float* v    = (const float*)d_in[2];
    const float* gq   = (const float*)d_in[3];
    const float* bqln = (const float*)d_in[4];
    const float* gk   = (const float*)d_in[5];
    const float* bkln = (const float*)d_in[6];
    const float* gv   = (const float*)d_in[7];
    const float* bvln = (const float*)d_in[8];
    const float* Wq   = (const float*)d_in[9];
    const float* bq   = (const float*)d_in[10];
    const float* Wk   = (const float*)d_in[11];
    const float* bk   = (const float*)d_in[12];
    const float* Wv   = (const float*)d_in[13];
    const float* bv   = (const float*)d_in[14];
    const float* Wp   = (const float*)d_in[15];
    const float* bp   = (const float*)d_in[16];

    float* out = (float*)d_out;
    float* kh  = out + (size_t)MROWS * DIMC;      // [B,H,N,hd] output 2
    float* vh  = kh + (size_t)MROWS * DIMC;       // [B,H,N,hd] output 3

    float *qn, *kn, *vn, *qh, *oh;
    cudaGetSymbolAddress((void**)&qn, g_qn);
    cudaGetSymbolAddress((void**)&kn, g_kn);
    cudaGetSymbolAddress((void**)&vn, g_vn);
    cudaGetSymbolAddress((void**)&qh, g_qh);
    cudaGetSymbolAddress((void**)&oh, g_oh);

    ln_kernel<<<MROWS, 256>>>(q, gq, bqln, qn);
    ln_kernel<<<MROWS, 256>>>(k, gk, bkln, kn);
    ln_kernel<<<MROWS, 256>>>(v, gv, bvln, vn);

    dim3 gg(DIMC / 128, MROWS / 128);   // (8, 32)
    gemm_bias_kernel<false, true><<<gg, 256>>>(qn, Wq, bq, qh);
    gemm_bias_kernel<false, true><<<gg, 256>>>(kn, Wk, bk, kh);
    gemm_bias_kernel<false, true><<<gg, 256>>>(vn, Wv, bv, vh);

    cudaFuncSetAttribute(flash_kernel, cudaFuncAttributeMaxDynamicSharedMemorySize, 65536);
    flash_kernel<<<dim3(NSEQ / 64, BHNUM), 256, 65536>>>(qh, kh, vh, oh);

    gemm_bias_kernel<true, false><<<gg, 256>>>(oh, Wp, bp, out);
}

// round 5
// speedup vs baseline: 1.4155x; 1.4155x over previous
#include <cuda_runtime.h>
#include <cuda_bf16.h>
#include <cstdint>
#include <math.h>

#define DIMC   1024
#define NSEQ   2048
#define BATCH  2
#define NHEADS 16
#define HD     64
#define MROWS  (BATCH * NSEQ)     // 4096
#define BHNUM  (BATCH * NHEADS)   // 32

// ---------------------------------------------------------------------------
// Scratch (static device globals — no runtime allocation allowed)
// ---------------------------------------------------------------------------
__device__ __nv_bfloat16 g_ln_hi[3ull * MROWS * DIMC];
__device__ __nv_bfloat16 g_ln_lo[3ull * MROWS * DIMC];
__device__ __nv_bfloat16 g_wt_hi[4ull * DIMC * DIMC];    // W transposed [N][K]
__device__ __nv_bfloat16 g_wt_lo[4ull * DIMC * DIMC];
__device__ __nv_bfloat16 g_os_hi[(size_t)MROWS * DIMC];
__device__ __nv_bfloat16 g_os_lo[(size_t)MROWS * DIMC];
__device__ float g_qh[(size_t)MROWS * DIMC];             // [bh][n][64]
__device__ float g_oh[(size_t)MROWS * DIMC];             // [bh][n][64]

// ---------------------------------------------------------------------------
// PTX helpers (baseline ISA only — no sm_103a-specific features)
// ---------------------------------------------------------------------------
__device__ __forceinline__ void cp16(uint32_t s, const void* g) {
    asm volatile("cp.async.cg.shared.global [%0], [%1], 16;\n"
                 :: "r"(s), "l"(__cvta_generic_to_global(g)) : "memory");
}
#define CP_COMMIT() asm volatile("cp.async.commit_group;\n" ::: "memory")
#define CP_WAIT(n)  asm volatile("cp.async.wait_group %0;\n" :: "n"(n) : "memory")

__device__ __forceinline__ void ldmx4(uint32_t* r, uint32_t addr) {
    asm volatile("ldmatrix.sync.aligned.m8n8.x4.shared.b16 {%0,%1,%2,%3}, [%4];"
                 : "=r"(r[0]), "=r"(r[1]), "=r"(r[2]), "=r"(r[3]) : "r"(addr));
}

__device__ __forceinline__ void mma16816(float* c, const uint32_t* a, const uint32_t* b) {
    asm volatile("mma.sync.aligned.m16n8k16.row.col.f32.bf16.bf16.f32 "
                 "{%0,%1,%2,%3}, {%4,%5,%6,%7}, {%8,%9}, {%0,%1,%2,%3};"
                 : "+f"(c[0]), "+f"(c[1]), "+f"(c[2]), "+f"(c[3])
                 : "r"(a[0]), "r"(a[1]), "r"(a[2]), "r"(a[3]), "r"(b[0]), "r"(b[1]));
}

// ---------------------------------------------------------------------------
// LayerNorm + bf16 split: hi = bf16(y), lo = bf16(y - hi)
// ---------------------------------------------------------------------------
__global__ void __launch_bounds__(256) ln_split_kernel(const float* __restrict__ x,
                                                       const float* __restrict__ g,
                                                       const float* __restrict__ b,
                                                       __nv_bfloat16* __restrict__ hi,
                                                       __nv_bfloat16* __restrict__ lo) {
    const int row = blockIdx.x;
    const int tid = threadIdx.x;
    const float4 v = reinterpret_cast<const float4*>(x + (size_t)row * DIMC)[tid];
    float s  = v.x + v.y + v.z + v.w;
    float ss = v.x * v.x + v.y * v.y + v.z * v.z + v.w * v.w;
#pragma unroll
    for (int off = 16; off > 0; off >>= 1) {
        s  += __shfl_xor_sync(0xffffffffu, s, off);
        ss += __shfl_xor_sync(0xffffffffu, ss, off);
    }
    __shared__ float rs[8], rss[8];
    if ((tid & 31) == 0) { rs[tid >> 5] = s; rss[tid >> 5] = ss; }
    __syncthreads();
    float tot = 0.f, totss = 0.f;
#pragma unroll
    for (int i = 0; i < 8; i++) { tot += rs[i]; totss += rss[i]; }
    const float mean = tot * (1.0f / DIMC);
    const float var  = totss * (1.0f / DIMC) - mean * mean;
    const float rstd = rsqrtf(var + 1e-5f);
    const float4 g4 = reinterpret_cast<const float4*>(g)[tid];
    const float4 b4 = reinterpret_cast<const float4*>(b)[tid];
    float o[4];
    o[0] = (v.x - mean) * rstd * g4.x + b4.x;
    o[1] = (v.y - mean) * rstd * g4.y + b4.y;
    o[2] = (v.z - mean) * rstd * g4.z + b4.z;
    o[3] = (v.w - mean) * rstd * g4.w + b4.w;
    __nv_bfloat16 h[4], l[4];
#pragma unroll
    for (int i = 0; i < 4; i++) {
        h[i] = __float2bfloat16(o[i]);
        l[i] = __float2bfloat16(o[i] - __bfloat162float(h[i]));
    }
    __nv_bfloat162* H = reinterpret_cast<__nv_bfloat162*>(hi + (size_t)row * DIMC);
    __nv_bfloat162* L = reinterpret_cast<__nv_bfloat162*>(lo + (size_t)row * DIMC);
    H[tid * 2]     = __halves2bfloat162(h[0], h[1]);
    H[tid * 2 + 1] = __halves2bfloat162(h[2], h[3]);
    L[tid * 2]     = __halves2bfloat162(l[0], l[1]);
    L[tid * 2 + 1] = __halves2bfloat162(l[2], l[3]);
}

// ---------------------------------------------------------------------------
// Weight transpose + split: Wt[n][k] = split(W[k][n]); 4 weights via z.
// ---------------------------------------------------------------------------
__global__ void __launch_bounds__(256) wsplit_kernel(const float* __restrict__ W0,
                                                     const float* __restrict__ W1,
                                                     const float* __restrict__ W2,
                                                     const float* __restrict__ W3,
                                                     __nv_bfloat16* __restrict__ hi,
                                                     __nv_bfloat16* __restrict__ lo) {
    const int z = blockIdx.z;
    const float* W = (z == 0) ? W0 : (z == 1) ? W1 : (z == 2) ? W2 : W3;
    const size_t ob = (size_t)z * DIMC * DIMC;
    __shared__ float t[32][33];
    const int tx = threadIdx.x, ty = threadIdx.y;
    const int n0 = blockIdx.x * 32, k0 = blockIdx.y * 32;
#pragma unroll
    for (int r = 0; r < 4; r++)
        t[ty + 8 * r][tx] = W[(size_t)(k0 + ty + 8 * r) * DIMC + n0 + tx];
    __syncthreads();
#pragma unroll
    for (int r = 0; r < 4; r++) {
        const float x = t[tx][ty + 8 * r];
        const __nv_bfloat16 h = __float2bfloat16(x);
        const __nv_bfloat16 l = __float2bfloat16(x - __bfloat162float(h));
        const size_t o = ob + (size_t)(n0 + ty + 8 * r) * DIMC + k0 + tx;
        hi[o] = h;
        lo[o] = l;
    }
}

// ---------------------------------------------------------------------------
// Attention-out split: head layout [bh][n][64] -> row-major split bf16
// ---------------------------------------------------------------------------
__global__ void __launch_bounds__(256) oh_split_kernel(const float* __restrict__ oh,
                                                       __nv_bfloat16* __restrict__ hi,
                                                       __nv_bfloat16* __restrict__ lo) {
    const int r = blockIdx.x;
    const int c4 = threadIdx.x * 4;
    const int b = r >> 11, n = r & (NSEQ - 1);
    const int h = c4 >> 6, d = c4 & 63;
    const float4 v = *reinterpret_cast<const float4*>(
        oh + (((size_t)(b * NHEADS + h) * NSEQ + n) << 6) + d);
    float o[4] = {v.x, v.y, v.z, v.w};
    __nv_bfloat16 hh[4], ll[4];
#pragma unroll
    for (int i = 0; i < 4; i++) {
        hh[i] = __float2bfloat16(o[i]);
        ll[i] = __float2bfloat16(o[i] - __bfloat162float(hh[i]));
    }
    __nv_bfloat162* H = reinterpret_cast<__nv_bfloat162*>(hi + (size_t)r * DIMC + c4);
    __nv_bfloat162* L = reinterpret_cast<__nv_bfloat162*>(lo + (size_t)r * DIMC + c4);
    H[0] = __halves2bfloat162(hh[0], hh[1]);
    H[1] = __halves2bfloat162(hh[2], hh[3]);
    L[0] = __halves2bfloat162(ll[0], ll[1]);
    L[1] = __halves2bfloat162(ll[2], ll[3]);
}

// ---------------------------------------------------------------------------
// mma.sync bf16 GEMM, 3x split: C[4096,1024] = A @ Wt^T + bias (fp32 out).
// 128x128 tile, BK=32, 8 warps (2x4), warp tile 64x32, cp.async double-buffer.
// smem rows padded to 40 bf16 (80B): 16B-aligned, ldmatrix phase-conflict-free.
// ---------------------------------------------------------------------------
#define PADK   40
#define TILE_B (128 * PADK * 2)      // 10240 bytes per tile
#define STAGE_B (4 * TILE_B)         // Ahi,Alo,Bhi,Blo = 40960
#define GEMM_SMEM (2 * STAGE_B)      // 81920

__device__ __forceinline__ void load_stage(uint32_t st,
                                           const __nv_bfloat16* Ahi, const __nv_bfloat16* Alo,
                                           const __nv_bfloat16* Bhi, const __nv_bfloat16* Blo,
                                           int bm, int bn, int k0, int tid) {
#pragma unroll
    for (int it = 0; it < 2; it++) {
        const int idx = tid + it * 256;           // 0..511
        const int row = idx >> 2, seg = idx & 3;  // 128 rows x 4 segs of 8 bf16
        const uint32_t so = (uint32_t)(row * 80 + seg * 16);
        const size_t ga = (size_t)(bm + row) * DIMC + k0 + seg * 8;
        const size_t gb = (size_t)(bn + row) * DIMC + k0 + seg * 8;
        cp16(st + 0 * TILE_B + so, Ahi + ga);
        cp16(st + 1 * TILE_B + so, Alo + ga);
        cp16(st + 2 * TILE_B + so, Bhi + gb);
        cp16(st + 3 * TILE_B + so, Blo + gb);
    }
    CP_COMMIT();
}

template <bool CHEAD>
__global__ void __launch_bounds__(256, 1) mma_gemm(
    const __nv_bfloat16* __restrict__ Ahi_base, const __nv_bfloat16* __restrict__ Alo_base,
    const __nv_bfloat16* __restrict__ Bhi_base, const __nv_bfloat16* __restrict__ Blo_base,
    const float* b0, const float* b1, const float* b2,
    float* C0, float* C1, float* C2) {
    extern __shared__ __align__(128) char smem[];
    const uint32_t sbase = (uint32_t)__cvta_generic_to_shared(smem);
    const int tid = threadIdx.x, wid = tid >> 5, lane = tid & 31;
    const int z = blockIdx.z;
    const __nv_bfloat16* Ahi = Ahi_base + (size_t)z * MROWS * DIMC;
    const __nv_bfloat16* Alo = Alo_base + (size_t)z * MROWS * DIMC;
    const __nv_bfloat16* Bhi = Bhi_base + (size_t)z * DIMC * DIMC;
    const __nv_bfloat16* Blo = Blo_base + (size_t)z * DIMC * DIMC;
    const float* bias = (z == 0) ? b0 : (z == 1) ? b1 : b2;
    float* C = (z == 0) ? C0 : (z == 1) ? C1 : C2;
    const int bm = blockIdx.y * 128;
    const int bn = blockIdx.x * 128;
    const int wr = wid >> 2;          // 0..1 -> m offset 64*wr
    const int wc = wid & 3;           // 0..3 -> n offset 32*wc

    float acc[4][4][4];
#pragma unroll
    for (int i = 0; i < 4; i++)
#pragma unroll
        for (int j = 0; j < 4; j++)
#pragma unroll
            for (int t = 0; t < 4; t++) acc[i][j][t] = 0.f;

    // ldmatrix source addresses (within a tile, before tile-base offset):
    // A frag mf: lane<16: row = wr*64+mf*16+lane, colB = h*32
    //            lane>=16: row = wr*64+mf*16+lane-16, colB = h*32+16
    const int a_r = wr * 64 + (lane & 15);
    const uint32_t a_off0 = (uint32_t)(a_r * 80 + ((lane >> 4) << 4));
    // B frag pair nf2: lanes0-7: n=wc*32+nf2*16+l, k+0 | 8-15: same n, k+8
    //                  16-23: n+8, k+0 | 24-31: n+8, k+8
    const int b_n = wc * 32 + (lane & 7) + ((lane >> 4) << 3);
    const uint32_t b_off0 = (uint32_t)(b_n * 80 + (((lane >> 3) & 1) << 4));

    load_stage(sbase, Ahi, Alo, Bhi, Blo, bm, bn, 0, tid);
    load_stage(sbase + STAGE_B, Ahi, Alo, Bhi, Blo, bm, bn, 32, tid);

    for (int i = 0; i < 32; i++) {
        if (i < 31) { CP_WAIT(1); } else { CP_WAIT(0); }
        __syncthreads();
        const uint32_t st = sbase + (uint32_t)(i & 1) * STAGE_B;
#pragma unroll
        for (int h = 0; h < 2; h++) {
            const uint32_t hb = (uint32_t)(h * 32);
            uint32_t ah[4][4], al[4][4];
#pragma unroll
            for (int mf = 0; mf < 4; mf++) {
                const uint32_t ao = a_off0 + hb + (uint32_t)(mf * 16 * 80);
                ldmx4(ah[mf], st + 0 * TILE_B + ao);
                ldmx4(al[mf], st + 1 * TILE_B + ao);
            }
            uint32_t bh[4][2], bl[4][2];
#pragma unroll
            for (int nf2 = 0; nf2 < 2; nf2++) {
                const uint32_t bo = b_off0 + hb + (uint32_t)(nf2 * 16 * 80);
                uint32_t r4[4];
                ldmx4(r4, st + 2 * TILE_B + bo);
                bh[nf2 * 2][0] = r4[0]; bh[nf2 * 2][1] = r4[1];
                bh[nf2 * 2 + 1][0] = r4[2]; bh[nf2 * 2 + 1][1] = r4[3];
                ldmx4(r4, st + 3 * TILE_B + bo);
                bl[nf2 * 2][0] = r4[0]; bl[nf2 * 2][1] = r4[1];
                bl[nf2 * 2 + 1][0] = r4[2]; bl[nf2 * 2 + 1][1] = r4[3];
            }
#pragma unroll
            for (int mf = 0; mf < 4; mf++)
#pragma unroll
                for (int nf = 0; nf < 4; nf++) {
                    mma16816(acc[mf][nf], ah[mf], bh[nf]);
                    mma16816(acc[mf][nf], ah[mf], bl[nf]);
                    mma16816(acc[mf][nf], al[mf], bh[nf]);
                }
        }
        __syncthreads();
        if (i + 2 < 32)
            load_stage(st, Ahi, Alo, Bhi, Blo, bm, bn, (i + 2) * 32, tid);
    }

    // Epilogue: thread t of warp owns rows (t/4, t/4+8), cols (t%4)*2..+1 per frag
    const int lr = lane >> 2, lc = (lane & 3) * 2;
#pragma unroll
    for (int mf = 0; mf < 4; mf++) {
#pragma unroll
        for (int nf = 0; nf < 4; nf++) {
            const int col = bn + wc * 32 + nf * 8 + lc;
            const float bx = bias[col], by = bias[col + 1];
            const int r0 = bm + wr * 64 + mf * 16 + lr;
#pragma unroll
            for (int half = 0; half < 2; half++) {
                const int r = r0 + half * 8;
                float* dst;
                if (CHEAD) {
                    const int b = r >> 11, n = r & (NSEQ - 1);
                    const int hh = col >> 6, d0 = col & 63;
                    dst = C + (((size_t)(b * NHEADS + hh) * NSEQ + n) << 6) + d0;
                } else {
                    dst = C + (size_t)r * DIMC + col;
                }
                float2 o;
                o.x = acc[mf][nf][half * 2 + 0] + bx;
                o.y = acc[mf][nf][half * 2 + 1] + by;
                *reinterpret_cast<float2*>(dst) = o;
            }
        }
    }
}

// ---------------------------------------------------------------------------
// Flash attention (fp32 SIMT — next round's target)
// ---------------------------------------------------------------------------
__device__ __forceinline__ int ksw(int row, int col) {
    return row * 64 + (col ^ (((row >> 2) & 7) << 2));
}

__global__ void __launch_bounds__(256) flash_kernel(const float* __restrict__ Q,
                                                    const float* __restrict__ K,
                                                    const float* __restrict__ V,
                                                    float* __restrict__ O) {
    extern __shared__ float smx[];
    float* Qs = smx;
    float* Ks = Qs + 4096;
    float* Vs = Ks + 4096;
    float* Ps = Vs + 4096;
    const int tid = threadIdx.x;
    const int ty4 = (tid >> 4) * 4;
    const int tx4 = (tid & 15) * 4;
    const size_t base = (size_t)blockIdx.y * NSEQ * HD;
    const int q0 = blockIdx.x * 64;
    const float scale = 0.125f;

#pragma unroll
    for (int it = 0; it < 4; it++) {
        const int s = tid + it * 256;
        const int row = s >> 4;
        const int d4 = (s & 15) * 4;
        float4 v = *reinterpret_cast<const float4*>(Q + base + (size_t)(q0 + row) * HD + d4);
        v.x *= scale; v.y *= scale; v.z *= scale; v.w *= scale;
        *reinterpret_cast<float4*>(&Qs[ksw(row, d4)]) = v;
    }

    float m_i[4], l_i[4], o_acc[4][4];
#pragma unroll
    for (int i = 0; i < 4; i++) {
        m_i[i] = -1e30f;
        l_i[i] = 0.f;
#pragma unroll
        for (int j = 0; j < 4; j++) o_acc[i][j] = 0.f;
    }

    for (int kt = 0; kt < NSEQ / 64; kt++) {
        __syncthreads();
        const int kbase = kt * 64;
#pragma unroll
        for (int it = 0; it < 4; it++) {
            const int s = tid + it * 256;
            const int row = s >> 4;
            const int d4 = (s & 15) * 4;
            const float4 kv4 =
                *reinterpret_cast<const float4*>(K + base + (size_t)(kbase + row) * HD + d4);
            *reinterpret_cast<float4*>(&Ks[ksw(row, d4)]) = kv4;
            const float4 vv4 =
                *reinterpret_cast<const float4*>(V + base + (size_t)(kbase + row) * HD + d4);
            *reinterpret_cast<float4*>(&Vs[row * 64 + d4]) = vv4;
        }
        __syncthreads();

        float s4[4][4];
#pragma unroll
        for (int i = 0; i < 4; i++)
#pragma unroll
            for (int j = 0; j < 4; j++) s4[i][j] = 0.f;

#pragma unroll
        for (int d = 0; d < 64; d += 4) {
            float4 qf[4], kf[4];
#pragma unroll
            for (int i = 0; i < 4; i++)
                qf[i] = *reinterpret_cast<const float4*>(&Qs[ksw(ty4 + i, d)]);
#pragma unroll
            for (int j = 0; j < 4; j++)
                kf[j] = *reinterpret_cast<const float4*>(&Ks[ksw(tx4 + j, d)]);
#pragma unroll
            for (int i = 0; i < 4; i++)
#pragma unroll
                for (int j = 0; j < 4; j++)
                    s4[i][j] += qf[i].x * kf[j].x + qf[i].y * kf[j].y +
                                qf[i].z * kf[j].z + qf[i].w * kf[j].w;
        }

#pragma unroll
        for (int i = 0; i < 4; i++) {
            float rm = fmaxf(fmaxf(s4[i][0], s4[i][1]), fmaxf(s4[i][2], s4[i][3]));
#pragma unroll
            for (int off = 1; off < 16; off <<= 1)
                rm = fmaxf(rm, __shfl_xor_sync(0xffffffffu, rm, off, 16));
            const float mnew = fmaxf(m_i[i], rm);
            const float corr = __expf(m_i[i] - mnew);
            m_i[i] = mnew;
            float rsum = 0.f;
#pragma unroll
            for (int j = 0; j < 4; j++) {
                const float p = __expf(s4[i][j] - mnew);
                s4[i][j] = p;
                rsum += p;
            }
#pragma unroll
            for (int off = 1; off < 16; off <<= 1)
                rsum += __shfl_xor_sync(0xffffffffu, rsum, off, 16);
            l_i[i] = l_i[i] * corr + rsum;
#pragma unroll
            for (int j = 0; j < 4; j++) o_acc[i][j] *= corr;
            float4 pv;
            pv.x = s4[i][0]; pv.y = s4[i][1]; pv.z = s4[i][2]; pv.w = s4[i][3];
            *reinterpret_cast<float4*>(&Ps[(ty4 + i) * 64 + tx4]) = pv;
        }
        __syncthreads();

#pragma unroll
        for (int kv = 0; kv < 64; kv += 4) {
            float4 vf[4];
#pragma unroll
            for (int kk = 0; kk < 4; kk++)
                vf[kk] = *reinterpret_cast<const float4*>(&Vs[(kv + kk) * 64 + tx4]);
#pragma unroll
            for (int i = 0; i < 4; i++) {
                const float4 pf = *reinterpret_cast<const float4*>(&Ps[(ty4 + i) * 64 + kv]);
                o_acc[i][0] += pf.x * vf[0].x + pf.y * vf[1].x + pf.z * vf[2].x + pf.w * vf[3].x;
                o_acc[i][1] += pf.x * vf[0].y + pf.y * vf[1].y + pf.z * vf[2].y + pf.w * vf[3].y;
                o_acc[i][2] += pf.x * vf[0].z + pf.y * vf[1].z + pf.z * vf[2].z + pf.w * vf[3].z;
                o_acc[i][3] += pf.x * vf[0].w + pf.y * vf[1].w + pf.z * vf[2].w + pf.w * vf[3].w;
            }
        }
    }

#pragma unroll
    for (int i = 0; i < 4; i++) {
        const float inv = 1.0f / l_i[i];
        float4 o;
        o.x = o_acc[i][0] * inv;
        o.y = o_acc[i][1] * inv;
        o.z = o_acc[i][2] * inv;
        o.w = o_acc[i][3] * inv;
        *reinterpret_cast<float4*>(O + base + (size_t)(q0 + ty4 + i) * HD + tx4) = o;
    }
}

// ---------------------------------------------------------------------------
extern "C" void kernel_launch(void* const* d_in, const int* in_sizes, int n_in,
                              void* d_out, int out_size) {
    const float* q    = (const float*)d_in[0];
    const float* k    = (const float*)d_in[1];
    const float* v    = (const float*)d_in[2];
    const float* gq   = (const float*)d_in[3];
    const float* bqln = (const float*)d_in[4];
    const float* gk   = (const float*)d_in[5];
    const float* bkln = (const float*)d_in[6];
    const float* gv   = (const float*)d_in[7];
    const float* bvln = (const float*)d_in[8];
    const float* Wq   = (const float*)d_in[9];
    const float* bq   = (const float*)d_in[10];
    const float* Wk   = (const float*)d_in[11];
    const float* bk   = (const float*)d_in[12];
    const float* Wv   = (const float*)d_in[13];
    const float* bv   = (const float*)d_in[14];
    const float* Wp   = (const float*)d_in[15];
    const float* bp   = (const float*)d_in[16];

    float* out = (float*)d_out;
    float* kh  = out + (size_t)MROWS * DIMC;
    float* vh  = kh + (size_t)MROWS * DIMC;

    __nv_bfloat16 *lnhi, *lnlo, *wthi, *wtlo, *oshi, *oslo;
    float *qh, *oh;
    cudaGetSymbolAddress((void**)&lnhi, g_ln_hi);
    cudaGetSymbolAddress((void**)&lnlo, g_ln_lo);
    cudaGetSymbolAddress((void**)&wthi, g_wt_hi);
    cudaGetSymbolAddress((void**)&wtlo, g_wt_lo);
    cudaGetSymbolAddress((void**)&oshi, g_os_hi);
    cudaGetSymbolAddress((void**)&oslo, g_os_lo);
    cudaGetSymbolAddress((void**)&qh, g_qh);
    cudaGetSymbolAddress((void**)&oh, g_oh);

    // 1) LayerNorm + split
    ln_split_kernel<<<MROWS, 256>>>(q, gq, bqln, lnhi, lnlo);
    ln_split_kernel<<<MROWS, 256>>>(k, gk, bkln, lnhi + (size_t)MROWS * DIMC,
                                    lnlo + (size_t)MROWS * DIMC);
    ln_split_kernel<<<MROWS, 256>>>(v, gv, bvln, lnhi + 2ull * MROWS * DIMC,
                                    lnlo + 2ull * MROWS * DIMC);

    // 2) Weight transpose + split
    wsplit_kernel<<<dim3(32, 32, 4), dim3(32, 8)>>>(Wq, Wk, Wv, Wp, wthi, wtlo);

    // 3) Fused QKV projection (tensor cores via mma.sync)
    cudaFuncSetAttribute(mma_gemm<true>, cudaFuncAttributeMaxDynamicSharedMemorySize, GEMM_SMEM);
    cudaFuncSetAttribute(mma_gemm<false>, cudaFuncAttributeMaxDynamicSharedMemorySize, GEMM_SMEM);
    mma_gemm<true><<<dim3(8, 32, 3), 256, GEMM_SMEM>>>(
        lnhi, lnlo, wthi, wtlo, bq, bk, bv, qh, kh, vh);

    // 4) Attention
    cudaFuncSetAttribute(flash_kernel, cudaFuncAttributeMaxDynamicSharedMemorySize, 65536);
    flash_kernel<<<dim3(NSEQ / 64, BHNUM), 256, 65536>>>(qh, kh, vh, oh);

    // 5) Split attention output, project
    oh_split_kernel<<<MROWS, 256>>>(oh, oshi, oslo);
    mma_gemm<false><<<dim3(8, 32, 1), 256, GEMM_SMEM>>>(
        oshi, oslo, wthi + 3ull * DIMC * DIMC, wtlo + 3ull * DIMC * DIMC,
        bp, bp, bp, out, out, out);
}

// round 7
// speedup vs baseline: 2.6749x; 1.8897x over previous
#include <cuda_runtime.h>
#include <cuda_bf16.h>
#include <cstdint>
#include <math.h>

#define DIMC   1024
#define NSEQ   2048
#define BATCH  2
#define NHEADS 16
#define HD     64
#define MROWS  (BATCH * NSEQ)     // 4096
#define BHNUM  (BATCH * NHEADS)   // 32
#define SLOT   ((size_t)BHNUM * NSEQ * HD)   // elements per q/k/v slot

// ---------------------------------------------------------------------------
// Scratch (static device globals — no runtime allocation allowed)
// ---------------------------------------------------------------------------
__device__ __nv_bfloat16 g_ln_hi[3ull * MROWS * DIMC];
__device__ __nv_bfloat16 g_ln_lo[3ull * MROWS * DIMC];
__device__ __nv_bfloat16 g_wt_hi[4ull * DIMC * DIMC];    // W transposed [N][K]
__device__ __nv_bfloat16 g_wt_lo[4ull * DIMC * DIMC];
__device__ __nv_bfloat16 g_fh_hi[3ull * SLOT];           // q(head,scaled)/k(head)/vT
__device__ __nv_bfloat16 g_fh_lo[3ull * SLOT];
__device__ __nv_bfloat16 g_os_hi[(size_t)MROWS * DIMC];  // flash out split (row-major)
__device__ __nv_bfloat16 g_os_lo[(size_t)MROWS * DIMC];
__device__ float g_dummy[(size_t)MROWS * DIMC];          // unused fp32 sink for z=0

// ---------------------------------------------------------------------------
// PTX helpers (baseline ISA only)
// ---------------------------------------------------------------------------
__device__ __forceinline__ void cp16(uint32_t s, const void* g) {
    asm volatile("cp.async.cg.shared.global [%0], [%1], 16;\n"
                 :: "r"(s), "l"(__cvta_generic_to_global(g)) : "memory");
}
#define CP_COMMIT() asm volatile("cp.async.commit_group;\n" ::: "memory")
#define CP_WAIT(n)  asm volatile("cp.async.wait_group %0;\n" :: "n"(n) : "memory")

__device__ __forceinline__ void ldmx4(uint32_t* r, uint32_t addr) {
    asm volatile("ldmatrix.sync.aligned.m8n8.x4.shared.b16 {%0,%1,%2,%3}, [%4];"
                 : "=r"(r[0]), "=r"(r[1]), "=r"(r[2]), "=r"(r[3]) : "r"(addr));
}

__device__ __forceinline__ void mma16816(float* c, const uint32_t* a, const uint32_t* b) {
    asm volatile("mma.sync.aligned.m16n8k16.row.col.f32.bf16.bf16.f32 "
                 "{%0,%1,%2,%3}, {%4,%5,%6,%7}, {%8,%9}, {%0,%1,%2,%3};"
                 : "+f"(c[0]), "+f"(c[1]), "+f"(c[2]), "+f"(c[3])
                 : "r"(a[0]), "r"(a[1]), "r"(a[2]), "r"(a[3]), "r"(b[0]), "r"(b[1]));
}

__device__ __forceinline__ uint32_t pack_bf16x2(float a, float b) {
    __nv_bfloat162 t = __floats2bfloat162_rn(a, b);
    return *reinterpret_cast<uint32_t*>(&t);
}

// ---------------------------------------------------------------------------
// LayerNorm + bf16 split
// ---------------------------------------------------------------------------
__global__ void __launch_bounds__(256) ln_split_kernel(const float* __restrict__ x,
                                                       const float* __restrict__ g,
                                                       const float* __restrict__ b,
                                                       __nv_bfloat16* __restrict__ hi,
                                                       __nv_bfloat16* __restrict__ lo) {
    const int row = blockIdx.x;
    const int tid = threadIdx.x;
    const float4 v = reinterpret_cast<const float4*>(x + (size_t)row * DIMC)[tid];
    float s  = v.x + v.y + v.z + v.w;
    float ss = v.x * v.x + v.y * v.y + v.z * v.z + v.w * v.w;
#pragma unroll
    for (int off = 16; off > 0; off >>= 1) {
        s  += __shfl_xor_sync(0xffffffffu, s, off);
        ss += __shfl_xor_sync(0xffffffffu, ss, off);
    }
    __shared__ float rs[8], rss[8];
    if ((tid & 31) == 0) { rs[tid >> 5] = s; rss[tid >> 5] = ss; }
    __syncthreads();
    float tot = 0.f, totss = 0.f;
#pragma unroll
    for (int i = 0; i < 8; i++) { tot += rs[i]; totss += rss[i]; }
    const float mean = tot * (1.0f / DIMC);
    const float var  = totss * (1.0f / DIMC) - mean * mean;
    const float rstd = rsqrtf(var + 1e-5f);
    const float4 g4 = reinterpret_cast<const float4*>(g)[tid];
    const float4 b4 = reinterpret_cast<const float4*>(b)[tid];
    float o[4];
    o[0] = (v.x - mean) * rstd * g4.x + b4.x;
    o[1] = (v.y - mean) * rstd * g4.y + b4.y;
    o[2] = (v.z - mean) * rstd * g4.z + b4.z;
    o[3] = (v.w - mean) * rstd * g4.w + b4.w;
    __nv_bfloat16 h[4], l[4];
#pragma unroll
    for (int i = 0; i < 4; i++) {
        h[i] = __float2bfloat16(o[i]);
        l[i] = __float2bfloat16(o[i] - __bfloat162float(h[i]));
    }
    __nv_bfloat162* H = reinterpret_cast<__nv_bfloat162*>(hi + (size_t)row * DIMC);
    __nv_bfloat162* L = reinterpret_cast<__nv_bfloat162*>(lo + (size_t)row * DIMC);
    H[tid * 2]     = __halves2bfloat162(h[0], h[1]);
    H[tid * 2 + 1] = __halves2bfloat162(h[2], h[3]);
    L[tid * 2]     = __halves2bfloat162(l[0], l[1]);
    L[tid * 2 + 1] = __halves2bfloat162(l[2], l[3]);
}

// ---------------------------------------------------------------------------
// Weight transpose + split
// ---------------------------------------------------------------------------
__global__ void __launch_bounds__(256) wsplit_kernel(const float* __restrict__ W0,
                                                     const float* __restrict__ W1,
                                                     const float* __restrict__ W2,
                                                     const float* __restrict__ W3,
                                                     __nv_bfloat16* __restrict__ hi,
                                                     __nv_bfloat16* __restrict__ lo) {
    const int z = blockIdx.z;
    const float* W = (z == 0) ? W0 : (z == 1) ? W1 : (z == 2) ? W2 : W3;
    const size_t ob = (size_t)z * DIMC * DIMC;
    __shared__ float t[32][33];
    const int tx = threadIdx.x, ty = threadIdx.y;
    const int n0 = blockIdx.x * 32, k0 = blockIdx.y * 32;
#pragma unroll
    for (int r = 0; r < 4; r++)
        t[ty + 8 * r][tx] = W[(size_t)(k0 + ty + 8 * r) * DIMC + n0 + tx];
    __syncthreads();
#pragma unroll
    for (int r = 0; r < 4; r++) {
        const float x = t[tx][ty + 8 * r];
        const __nv_bfloat16 h = __float2bfloat16(x);
        const __nv_bfloat16 l = __float2bfloat16(x - __bfloat162float(h));
        const size_t o = ob + (size_t)(n0 + ty + 8 * r) * DIMC + k0 + tx;
        hi[o] = h;
        lo[o] = l;
    }
}

// ---------------------------------------------------------------------------
// mma.sync bf16 GEMM, 3x split. CHEAD epilogue also emits bf16 hi/lo for flash:
//   z=0: q head layout, pre-scaled by 0.125 (no fp32 write)
//   z=1: k head layout + fp32 kh
//   z=2: v TRANSPOSED [bh][hd][seq] + fp32 vh
// ---------------------------------------------------------------------------
#define PADK   40
#define TILE_B (128 * PADK * 2)
#define STAGE_B (4 * TILE_B)
#define GEMM_SMEM (2 * STAGE_B)

__device__ __forceinline__ void load_stage(uint32_t st,
                                           const __nv_bfloat16* Ahi, const __nv_bfloat16* Alo,
                                           const __nv_bfloat16* Bhi, const __nv_bfloat16* Blo,
                                           int bm, int bn, int k0, int tid) {
#pragma unroll
    for (int it = 0; it < 2; it++) {
        const int idx = tid + it * 256;
        const int row = idx >> 2, seg = idx & 3;
        const uint32_t so = (uint32_t)(row * 80 + seg * 16);
        const size_t ga = (size_t)(bm + row) * DIMC + k0 + seg * 8;
        const size_t gb = (size_t)(bn + row) * DIMC + k0 + seg * 8;
        cp16(st + 0 * TILE_B + so, Ahi + ga);
        cp16(st + 1 * TILE_B + so, Alo + ga);
        cp16(st + 2 * TILE_B + so, Bhi + gb);
        cp16(st + 3 * TILE_B + so, Blo + gb);
    }
    CP_COMMIT();
}

template <bool CHEAD>
__global__ void __launch_bounds__(256, 1) mma_gemm(
    const __nv_bfloat16* __restrict__ Ahi_base, const __nv_bfloat16* __restrict__ Alo_base,
    const __nv_bfloat16* __restrict__ Bhi_base, const __nv_bfloat16* __restrict__ Blo_base,
    const float* b0, const float* b1, const float* b2,
    float* C0, float* C1, float* C2,
    __nv_bfloat16* FHhi, __nv_bfloat16* FHlo) {
    extern __shared__ __align__(128) char smem[];
    const uint32_t sbase = (uint32_t)__cvta_generic_to_shared(smem);
    const int tid = threadIdx.x, wid = tid >> 5, lane = tid & 31;
    const int z = blockIdx.z;
    const __nv_bfloat16* Ahi = Ahi_base + (size_t)z * MROWS * DIMC;
    const __nv_bfloat16* Alo = Alo_base + (size_t)z * MROWS * DIMC;
    const __nv_bfloat16* Bhi = Bhi_base + (size_t)z * DIMC * DIMC;
    const __nv_bfloat16* Blo = Blo_base + (size_t)z * DIMC * DIMC;
    const float* bias = (z == 0) ? b0 : (z == 1) ? b1 : b2;
    float* C = (z == 0) ? C0 : (z == 1) ? C1 : C2;
    const int bm = blockIdx.y * 128;
    const int bn = blockIdx.x * 128;
    const int wr = wid >> 2;
    const int wc = wid & 3;

    float acc[4][4][4];
#pragma unroll
    for (int i = 0; i < 4; i++)
#pragma unroll
        for (int j = 0; j < 4; j++)
#pragma unroll
            for (int t = 0; t < 4; t++) acc[i][j][t] = 0.f;

    const int a_r = wr * 64 + (lane & 15);
    const uint32_t a_off0 = (uint32_t)(a_r * 80 + ((lane >> 4) << 4));
    const int b_n = wc * 32 + (lane & 7) + ((lane >> 4) << 3);
    const uint32_t b_off0 = (uint32_t)(b_n * 80 + (((lane >> 3) & 1) << 4));

    load_stage(sbase, Ahi, Alo, Bhi, Blo, bm, bn, 0, tid);
    load_stage(sbase + STAGE_B, Ahi, Alo, Bhi, Blo, bm, bn, 32, tid);

    for (int i = 0; i < 32; i++) {
        if (i < 31) { CP_WAIT(1); } else { CP_WAIT(0); }
        __syncthreads();
        const uint32_t st = sbase + (uint32_t)(i & 1) * STAGE_B;
#pragma unroll
        for (int h = 0; h < 2; h++) {
            const uint32_t hb = (uint32_t)(h * 32);
            uint32_t ah[4][4], al[4][4];
#pragma unroll
            for (int mf = 0; mf < 4; mf++) {
                const uint32_t ao = a_off0 + hb + (uint32_t)(mf * 16 * 80);
                ldmx4(ah[mf], st + 0 * TILE_B + ao);
                ldmx4(al[mf], st + 1 * TILE_B + ao);
            }
            uint32_t bh[4][2], bl[4][2];
#pragma unroll
            for (int nf2 = 0; nf2 < 2; nf2++) {
                const uint32_t bo = b_off0 + hb + (uint32_t)(nf2 * 16 * 80);
                uint32_t r4[4];
                ldmx4(r4, st + 2 * TILE_B + bo);
                bh[nf2 * 2][0] = r4[0]; bh[nf2 * 2][1] = r4[1];
                bh[nf2 * 2 + 1][0] = r4[2]; bh[nf2 * 2 + 1][1] = r4[3];
                ldmx4(r4, st + 3 * TILE_B + bo);
                bl[nf2 * 2][0] = r4[0]; bl[nf2 * 2][1] = r4[1];
                bl[nf2 * 2 + 1][0] = r4[2]; bl[nf2 * 2 + 1][1] = r4[3];
            }
#pragma unroll
            for (int mf = 0; mf < 4; mf++)
#pragma unroll
                for (int nf = 0; nf < 4; nf++) {
                    mma16816(acc[mf][nf], ah[mf], bh[nf]);
                    mma16816(acc[mf][nf], ah[mf], bl[nf]);
                    mma16816(acc[mf][nf], al[mf], bh[nf]);
                }
        }
        __syncthreads();
        if (i + 2 < 32)
            load_stage(st, Ahi, Alo, Bhi, Blo, bm, bn, (i + 2) * 32, tid);
    }

    const int lr = lane >> 2, lc = (lane & 3) * 2;
#pragma unroll
    for (int mf = 0; mf < 4; mf++) {
#pragma unroll
        for (int nf = 0; nf < 4; nf++) {
            const int col = bn + wc * 32 + nf * 8 + lc;
            const float bx = bias[col], by = bias[col + 1];
            const int r0 = bm + wr * 64 + mf * 16 + lr;
#pragma unroll
            for (int half = 0; half < 2; half++) {
                const int r = r0 + half * 8;
                const float a = acc[mf][nf][half * 2 + 0] + bx;
                const float c2 = acc[mf][nf][half * 2 + 1] + by;
                if (CHEAD) {
                    const int b = r >> 11, n = r & (NSEQ - 1);
                    const int hh = col >> 6, d0 = col & 63;
                    const size_t hoff = (((size_t)(b * NHEADS + hh) * NSEQ + n) << 6) + d0;
                    if (z == 0) {
                        const float sa = a * 0.125f, sb = c2 * 0.125f;
                        const __nv_bfloat162 h2 = __floats2bfloat162_rn(sa, sb);
                        const float2 f = __bfloat1622float2(h2);
                        const __nv_bfloat162 l2 = __floats2bfloat162_rn(sa - f.x, sb - f.y);
                        *reinterpret_cast<__nv_bfloat162*>(FHhi + hoff) = h2;
                        *reinterpret_cast<__nv_bfloat162*>(FHlo + hoff) = l2;
                    } else if (z == 1) {
                        float2 o; o.x = a; o.y = c2;
                        *reinterpret_cast<float2*>(C + hoff) = o;
                        const __nv_bfloat162 h2 = __floats2bfloat162_rn(a, c2);
                        const float2 f = __bfloat1622float2(h2);
                        const __nv_bfloat162 l2 = __floats2bfloat162_rn(a - f.x, c2 - f.y);
                        *reinterpret_cast<__nv_bfloat162*>(FHhi + SLOT + hoff) = h2;
                        *reinterpret_cast<__nv_bfloat162*>(FHlo + SLOT + hoff) = l2;
                    } else {
                        float2 o; o.x = a; o.y = c2;
                        *reinterpret_cast<float2*>(C + hoff) = o;
                        const __nv_bfloat16 ha = __float2bfloat16(a);
                        const __nv_bfloat16 hb2 = __float2bfloat16(c2);
                        const __nv_bfloat16 la = __float2bfloat16(a - __bfloat162float(ha));
                        const __nv_bfloat16 lb = __float2bfloat16(c2 - __bfloat162float(hb2));
                        const size_t tb = ((size_t)(b * NHEADS + hh) * HD + d0) * NSEQ + n;
                        FHhi[2 * SLOT + tb] = ha;
                        FHhi[2 * SLOT + tb + NSEQ] = hb2;
                        FHlo[2 * SLOT + tb] = la;
                        FHlo[2 * SLOT + tb + NSEQ] = lb;
                    }
                } else {
                    float2 o; o.x = a; o.y = c2;
                    *reinterpret_cast<float2*>(C + (size_t)r * DIMC + col) = o;
                }
            }
        }
    }
}

// ---------------------------------------------------------------------------
// Flash attention on tensor cores.
// CTA: 128 q-rows, 8 warps (16 rows each, full 64 cols). BK=64, double-buffered.
// Tiles: 64 cols bf16 = 128B data per row, pitch 144B (odd multiple of 16B ->
// ldmatrix phase-conflict-free, cp.async 16B-aligned, offsets in bounds).
// ---------------------------------------------------------------------------
#define FPITCH  144                      // bytes per row
#define FQ_B    (128 * FPITCH)           // 18432 per Q tile
#define FT_B    (64 * FPITCH)            // 9216 per K/V tile
#define FSTG_B  (4 * FT_B)               // 36864 per stage (Khi,Klo,Vhi,Vlo)
#define FLASH_SMEM (2 * FQ_B + 2 * FSTG_B)   // 110592

__device__ __forceinline__ void load_kv(uint32_t st,
                                        const __nv_bfloat16* khi, const __nv_bfloat16* klo,
                                        const __nv_bfloat16* vthi, const __nv_bfloat16* vtlo,
                                        int bh, int kt, int tid) {
#pragma unroll
    for (int it = 0; it < 2; it++) {
        const int idx = tid + it * 256;            // 0..511
        const int row = idx >> 3, seg = idx & 7;   // 64 rows x 8 segs of 16B
        const uint32_t so = (uint32_t)(row * FPITCH + seg * 16);
        const size_t gk = (size_t)bh * NSEQ * HD + (size_t)(kt * 64 + row) * HD + seg * 8;
        const size_t gv = ((size_t)bh * HD + row) * NSEQ + kt * 64 + seg * 8;
        cp16(st + 0 * FT_B + so, khi + gk);
        cp16(st + 1 * FT_B + so, klo + gk);
        cp16(st + 2 * FT_B + so, vthi + gv);
        cp16(st + 3 * FT_B + so, vtlo + gv);
    }
    CP_COMMIT();
}

__global__ void __launch_bounds__(256, 1) flash_mma(
    const __nv_bfloat16* __restrict__ FHhi, const __nv_bfloat16* __restrict__ FHlo,
    __nv_bfloat16* __restrict__ Ohi, __nv_bfloat16* __restrict__ Olo) {
    extern __shared__ __align__(128) char smem[];
    const uint32_t sbase = (uint32_t)__cvta_generic_to_shared(smem);
    const int tid = threadIdx.x, wid = tid >> 5, lane = tid & 31;
    const int bh = blockIdx.y;
    const int q0 = blockIdx.x * 128;

    const __nv_bfloat16* qhi = FHhi;
    const __nv_bfloat16* qlo = FHlo;
    const __nv_bfloat16* khi = FHhi + SLOT;
    const __nv_bfloat16* klo = FHlo + SLOT;
    const __nv_bfloat16* vthi = FHhi + 2 * SLOT;
    const __nv_bfloat16* vtlo = FHlo + 2 * SLOT;

    // Q tiles -> smem (128 rows x 8 segs, hi + lo)
#pragma unroll
    for (int it = 0; it < 4; it++) {
        const int idx = tid + it * 256;            // 0..1023
        const int row = idx >> 3, seg = idx & 7;
        const uint32_t so = (uint32_t)(row * FPITCH + seg * 16);
        const size_t gq = (size_t)bh * NSEQ * HD + (size_t)(q0 + row) * HD + seg * 8;
        cp16(sbase + so, qhi + gq);
        cp16(sbase + FQ_B + so, qlo + gq);
    }
    CP_COMMIT();
    const uint32_t stg0 = sbase + 2 * FQ_B;
    load_kv(stg0, khi, klo, vthi, vtlo, bh, 0, tid);
    load_kv(stg0 + FSTG_B, khi, klo, vthi, vtlo, bh, 1, tid);

    CP_WAIT(2);   // Q group complete
    __syncthreads();

    // Q fragments (A operand), 4 k16 frags, hi+lo
    uint32_t qfh[4][4], qfl[4][4];
    {
        const int a_r = wid * 16 + (lane & 15);
        const uint32_t a0 = (uint32_t)(a_r * FPITCH + ((lane >> 4) << 4));
#pragma unroll
        for (int kf = 0; kf < 4; kf++) {
            ldmx4(qfh[kf], sbase + a0 + kf * 32);
            ldmx4(qfl[kf], sbase + FQ_B + a0 + kf * 32);
        }
    }

    const uint32_t b_off0 =
        (uint32_t)(((lane & 7) + ((lane >> 4) << 3)) * FPITCH + (((lane >> 3) & 1) << 4));

    float o[8][4];
#pragma unroll
    for (int nf = 0; nf < 8; nf++)
#pragma unroll
        for (int t = 0; t < 4; t++) o[nf][t] = 0.f;
    float mA = -1e30f, mB = -1e30f, lA = 0.f, lB = 0.f;

    for (int kt = 0; kt < NSEQ / 64; kt++) {
        if (kt < NSEQ / 64 - 1) { CP_WAIT(1); } else { CP_WAIT(0); }
        __syncthreads();
        const uint32_t st = stg0 + (uint32_t)(kt & 1) * FSTG_B;

        // ---- S = Q K^T (Q pre-scaled by 0.125) ----
        float s[8][4];
#pragma unroll
        for (int nf = 0; nf < 8; nf++)
#pragma unroll
            for (int t = 0; t < 4; t++) s[nf][t] = 0.f;
#pragma unroll
        for (int kf = 0; kf < 4; kf++) {
#pragma unroll
            for (int nf2 = 0; nf2 < 4; nf2++) {
                const uint32_t bo = b_off0 + (uint32_t)(nf2 * 16 * FPITCH) + kf * 32;
                uint32_t kh4[4], kl4[4];
                ldmx4(kh4, st + 0 * FT_B + bo);
                ldmx4(kl4, st + 1 * FT_B + bo);
                mma16816(s[nf2 * 2], qfh[kf], &kh4[0]);
                mma16816(s[nf2 * 2], qfh[kf], &kl4[0]);
                mma16816(s[nf2 * 2], qfl[kf], &kh4[0]);
                mma16816(s[nf2 * 2 + 1], qfh[kf], &kh4[2]);
                mma16816(s[nf2 * 2 + 1], qfh[kf], &kl4[2]);
                mma16816(s[nf2 * 2 + 1], qfl[kf], &kh4[2]);
            }
        }

        // ---- online softmax (rows rA = lane>>2, rB = rA+8) ----
        float rmA = -1e30f, rmB = -1e30f;
#pragma unroll
        for (int nf = 0; nf < 8; nf++) {
            rmA = fmaxf(rmA, fmaxf(s[nf][0], s[nf][1]));
            rmB = fmaxf(rmB, fmaxf(s[nf][2], s[nf][3]));
        }
        rmA = fmaxf(rmA, __shfl_xor_sync(0xffffffffu, rmA, 1, 4));
        rmA = fmaxf(rmA, __shfl_xor_sync(0xffffffffu, rmA, 2, 4));
        rmB = fmaxf(rmB, __shfl_xor_sync(0xffffffffu, rmB, 1, 4));
        rmB = fmaxf(rmB, __shfl_xor_sync(0xffffffffu, rmB, 2, 4));
        const float mnA = fmaxf(mA, rmA);
        const float mnB = fmaxf(mB, rmB);
        const float cA = __expf(mA - mnA);
        const float cB = __expf(mB - mnB);
        mA = mnA; mB = mnB;
        float sumA = 0.f, sumB = 0.f;
#pragma unroll
        for (int nf = 0; nf < 8; nf++) {
            s[nf][0] = __expf(s[nf][0] - mnA);
            s[nf][1] = __expf(s[nf][1] - mnA);
            s[nf][2] = __expf(s[nf][2] - mnB);
            s[nf][3] = __expf(s[nf][3] - mnB);
            sumA += s[nf][0] + s[nf][1];
            sumB += s[nf][2] + s[nf][3];
        }
        sumA += __shfl_xor_sync(0xffffffffu, sumA, 1, 4);
        sumA += __shfl_xor_sync(0xffffffffu, sumA, 2, 4);
        sumB += __shfl_xor_sync(0xffffffffu, sumB, 1, 4);
        sumB += __shfl_xor_sync(0xffffffffu, sumB, 2, 4);
        lA = lA * cA + sumA;
        lB = lB * cB + sumB;
#pragma unroll
        for (int nf = 0; nf < 8; nf++) {
            o[nf][0] *= cA; o[nf][1] *= cA;
            o[nf][2] *= cB; o[nf][3] *= cB;
        }

        // ---- O += P V^T (register repack C-frag -> A-frag, hi/lo split) ----
#pragma unroll
        for (int kf = 0; kf < 4; kf++) {
            uint32_t pah[4], pal[4];
#pragma unroll
            for (int blk = 0; blk < 2; blk++) {
                const float p0 = s[2 * kf + blk][0], p1 = s[2 * kf + blk][1];
                const float p2 = s[2 * kf + blk][2], p3 = s[2 * kf + blk][3];
                const __nv_bfloat162 h01 = __floats2bfloat162_rn(p0, p1);
                const __nv_bfloat162 h23 = __floats2bfloat162_rn(p2, p3);
                const float2 f01 = __bfloat1622float2(h01);
                const float2 f23 = __bfloat1622float2(h23);
                pah[blk * 2 + 0] = *reinterpret_cast<const uint32_t*>(&h01);
                pah[blk * 2 + 1] = *reinterpret_cast<const uint32_t*>(&h23);
                pal[blk * 2 + 0] = pack_bf16x2(p0 - f01.x, p1 - f01.y);
                pal[blk * 2 + 1] = pack_bf16x2(p2 - f23.x, p3 - f23.y);
            }
#pragma unroll
            for (int nf2 = 0; nf2 < 4; nf2++) {
                const uint32_t bo = b_off0 + (uint32_t)(nf2 * 16 * FPITCH) + kf * 32;
                uint32_t vh4[4], vl4[4];
                ldmx4(vh4, st + 2 * FT_B + bo);
                ldmx4(vl4, st + 3 * FT_B + bo);
                mma16816(o[nf2 * 2], pah, &vh4[0]);
                mma16816(o[nf2 * 2], pah, &vl4[0]);
                mma16816(o[nf2 * 2], pal, &vh4[0]);
                mma16816(o[nf2 * 2 + 1], pah, &vh4[2]);
                mma16816(o[nf2 * 2 + 1], pah, &vl4[2]);
                mma16816(o[nf2 * 2 + 1], pal, &vh4[2]);
            }
        }

        __syncthreads();
        if (kt + 2 < NSEQ / 64)
            load_kv(st, khi, klo, vthi, vtlo, bh, kt + 2, tid);
    }

    // ---- finalize + store split bf16 row-major [b*2048+n][h*64+d] ----
    const float invA = 1.0f / lA;
    const float invB = 1.0f / lB;
    const int b = bh >> 4, h = bh & 15;
    const int rA = q0 + wid * 16 + (lane >> 2);
    const int rB = rA + 8;
    const size_t baseA = ((size_t)(b * NSEQ + rA)) * DIMC + h * 64;
    const size_t baseB = ((size_t)(b * NSEQ + rB)) * DIMC + h * 64;
#pragma unroll
    for (int nf = 0; nf < 8; nf++) {
        const int col = nf * 8 + (lane & 3) * 2;
        const float a0 = o[nf][0] * invA, a1 = o[nf][1] * invA;
        const float b0 = o[nf][2] * invB, b1 = o[nf][3] * invB;
        const __nv_bfloat162 hA = __floats2bfloat162_rn(a0, a1);
        const float2 fA = __bfloat1622float2(hA);
        const __nv_bfloat162 lA2 = __floats2bfloat162_rn(a0 - fA.x, a1 - fA.y);
        const __nv_bfloat162 hB = __floats2bfloat162_rn(b0, b1);
        const float2 fB = __bfloat1622float2(hB);
        const __nv_bfloat162 lB2 = __floats2bfloat162_rn(b0 - fB.x, b1 - fB.y);
        *reinterpret_cast<__nv_bfloat162*>(Ohi + baseA + col) = hA;
        *reinterpret_cast<__nv_bfloat162*>(Olo + baseA + col) = lA2;
        *reinterpret_cast<__nv_bfloat162*>(Ohi + baseB + col) = hB;
        *reinterpret_cast<__nv_bfloat162*>(Olo + baseB + col) = lB2;
    }
}

// ---------------------------------------------------------------------------
extern "C" void kernel_launch(void* const* d_in, const int* in_sizes, int n_in,
                              void* d_out, int out_size) {
    const float* q    = (const float*)d_in[0];
    const float* k    = (const float*)d_in[1];
    const float* v    = (const float*)d_in[2];
    const float* gq   = (const float*)d_in[3];
    const float* bqln = (const float*)d_in[4];
    const float* gk   = (const float*)d_in[5];
    const float* bkln = (const float*)d_in[6];
    const float* gv   = (const float*)d_in[7];
    const float* bvln = (const float*)d_in[8];
    const float* Wq   = (const float*)d_in[9];
    const float* bq   = (const float*)d_in[10];
    const float* Wk   = (const float*)d_in[11];
    const float* bk   = (const float*)d_in[12];
    const float* Wv   = (const float*)d_in[13];
    const float* bv   = (const float*)d_in[14];
    const float* Wp   = (const float*)d_in[15];
    const float* bp   = (const float*)d_in[16];

    float* out = (float*)d_out;
    float* kh  = out + (size_t)MROWS * DIMC;
    float* vh  = kh + (size_t)MROWS * DIMC;

    __nv_bfloat16 *lnhi, *lnlo, *wthi, *wtlo, *fhhi, *fhlo, *oshi, *oslo;
    float* dummy;
    cudaGetSymbolAddress((void**)&lnhi, g_ln_hi);
    cudaGetSymbolAddress((void**)&lnlo, g_ln_lo);
    cudaGetSymbolAddress((void**)&wthi, g_wt_hi);
    cudaGetSymbolAddress((void**)&wtlo, g_wt_lo);
    cudaGetSymbolAddress((void**)&fhhi, g_fh_hi);
    cudaGetSymbolAddress((void**)&fhlo, g_fh_lo);
    cudaGetSymbolAddress((void**)&oshi, g_os_hi);
    cudaGetSymbolAddress((void**)&oslo, g_os_lo);
    cudaGetSymbolAddress((void**)&dummy, g_dummy);

    // 1) LayerNorm + split
    ln_split_kernel<<<MROWS, 256>>>(q, gq, bqln, lnhi, lnlo);
    ln_split_kernel<<<MROWS, 256>>>(k, gk, bkln, lnhi + (size_t)MROWS * DIMC,
                                    lnlo + (size_t)MROWS * DIMC);
    ln_split_kernel<<<MROWS, 256>>>(v, gv, bvln, lnhi + 2ull * MROWS * DIMC,
                                    lnlo + 2ull * MROWS * DIMC);

    // 2) Weight transpose + split
    wsplit_kernel<<<dim3(32, 32, 4), dim3(32, 8)>>>(Wq, Wk, Wv, Wp, wthi, wtlo);

    // 3) QKV projection (tensor cores), also emits flash-ready bf16 hi/lo
    cudaFuncSetAttribute(mma_gemm<true>, cudaFuncAttributeMaxDynamicSharedMemorySize, GEMM_SMEM);
    cudaFuncSetAttribute(mma_gemm<false>, cudaFuncAttributeMaxDynamicSharedMemorySize, GEMM_SMEM);
    mma_gemm<true><<<dim3(8, 32, 3), 256, GEMM_SMEM>>>(
        lnhi, lnlo, wthi, wtlo, bq, bk, bv, dummy, kh, vh, fhhi, fhlo);

    // 4) Flash attention on tensor cores -> split bf16 row-major output
    cudaFuncSetAttribute(flash_mma, cudaFuncAttributeMaxDynamicSharedMemorySize, FLASH_SMEM);
    flash_mma<<<dim3(NSEQ / 128, BHNUM), 256, FLASH_SMEM>>>(fhhi, fhlo, oshi, oslo);

    // 5) Output projection
    mma_gemm<false><<<dim3(8, 32, 1), 256, GEMM_SMEM>>>(
        oshi, oslo, wthi + 3ull * DIMC * DIMC, wtlo + 3ull * DIMC * DIMC,
        bp, bp, bp, out, out, out, fhhi, fhlo);
}

// round 9
// speedup vs baseline: 2.7981x; 1.0460x over previous
#include <cuda_runtime.h>
#include <cuda_bf16.h>
#include <cstdint>
#include <math.h>

#define DIMC   1024
#define NSEQ   2048
#define BATCH  2
#define NHEADS 16
#define HD     64
#define MROWS  (BATCH * NSEQ)     // 4096
#define BHNUM  (BATCH * NHEADS)   // 32
#define SLOT   ((size_t)BHNUM * NSEQ * HD)   // elements per q/k/v slot

// ---------------------------------------------------------------------------
// Scratch (static device globals — no runtime allocation allowed)
// ---------------------------------------------------------------------------
__device__ __nv_bfloat16 g_ln_hi[3ull * MROWS * DIMC];
__device__ __nv_bfloat16 g_ln_lo[3ull * MROWS * DIMC];
__device__ __nv_bfloat16 g_wt_hi[4ull * DIMC * DIMC];    // W transposed [N][K]
__device__ __nv_bfloat16 g_wt_lo[4ull * DIMC * DIMC];
__device__ __nv_bfloat16 g_fh_hi[3ull * SLOT];           // q(head,scaled)/k(head)/vT
__device__ __nv_bfloat16 g_fh_lo[3ull * SLOT];
__device__ __nv_bfloat16 g_os_hi[(size_t)MROWS * DIMC];  // flash out split (row-major)
__device__ __nv_bfloat16 g_os_lo[(size_t)MROWS * DIMC];
__device__ float g_dummy[(size_t)MROWS * DIMC];          // unused fp32 sink for z=0

// ---------------------------------------------------------------------------
// PTX helpers (baseline ISA only)
// ---------------------------------------------------------------------------
__device__ __forceinline__ void cp16(uint32_t s, const void* g) {
    asm volatile("cp.async.cg.shared.global [%0], [%1], 16;\n"
                 :: "r"(s), "l"(__cvta_generic_to_global(g)) : "memory");
}
#define CP_COMMIT() asm volatile("cp.async.commit_group;\n" ::: "memory")
#define CP_WAIT(n)  asm volatile("cp.async.wait_group %0;\n" :: "n"(n) : "memory")

__device__ __forceinline__ void ldmx4(uint32_t* r, uint32_t addr) {
    asm volatile("ldmatrix.sync.aligned.m8n8.x4.shared.b16 {%0,%1,%2,%3}, [%4];"
                 : "=r"(r[0]), "=r"(r[1]), "=r"(r[2]), "=r"(r[3]) : "r"(addr));
}

__device__ __forceinline__ void mma16816(float* c, const uint32_t* a, const uint32_t* b) {
    asm volatile("mma.sync.aligned.m16n8k16.row.col.f32.bf16.bf16.f32 "
                 "{%0,%1,%2,%3}, {%4,%5,%6,%7}, {%8,%9}, {%0,%1,%2,%3};"
                 : "+f"(c[0]), "+f"(c[1]), "+f"(c[2]), "+f"(c[3])
                 : "r"(a[0]), "r"(a[1]), "r"(a[2]), "r"(a[3]), "r"(b[0]), "r"(b[1]));
}

__device__ __forceinline__ uint32_t pack_bf16x2(float a, float b) {
    __nv_bfloat162 t = __floats2bfloat162_rn(a, b);
    return *reinterpret_cast<uint32_t*>(&t);
}

// ---------------------------------------------------------------------------
// Fused LayerNorm + bf16 split for q/k/v (z = blockIdx.y)
// ---------------------------------------------------------------------------
__global__ void __launch_bounds__(256) ln_split_fused(
    const float* __restrict__ q, const float* __restrict__ k, const float* __restrict__ v,
    const float* __restrict__ gq, const float* __restrict__ bq,
    const float* __restrict__ gk, const float* __restrict__ bk,
    const float* __restrict__ gv, const float* __restrict__ bv,
    __nv_bfloat16* __restrict__ hi_base, __nv_bfloat16* __restrict__ lo_base) {
    const int z = blockIdx.y;
    const float* x = (z == 0) ? q : (z == 1) ? k : v;
    const float* g = (z == 0) ? gq : (z == 1) ? gk : gv;
    const float* b = (z == 0) ? bq : (z == 1) ? bk : bv;
    __nv_bfloat16* hi = hi_base + (size_t)z * MROWS * DIMC;
    __nv_bfloat16* lo = lo_base + (size_t)z * MROWS * DIMC;

    const int row = blockIdx.x;
    const int tid = threadIdx.x;
    const float4 vv = reinterpret_cast<const float4*>(x + (size_t)row * DIMC)[tid];
    float s  = vv.x + vv.y + vv.z + vv.w;
    float ss = vv.x * vv.x + vv.y * vv.y + vv.z * vv.z + vv.w * vv.w;
#pragma unroll
    for (int off = 16; off > 0; off >>= 1) {
        s  += __shfl_xor_sync(0xffffffffu, s, off);
        ss += __shfl_xor_sync(0xffffffffu, ss, off);
    }
    __shared__ float rs[8], rss[8];
    if ((tid & 31) == 0) { rs[tid >> 5] = s; rss[tid >> 5] = ss; }
    __syncthreads();
    float tot = 0.f, totss = 0.f;
#pragma unroll
    for (int i = 0; i < 8; i++) { tot += rs[i]; totss += rss[i]; }
    const float mean = tot * (1.0f / DIMC);
    const float var  = totss * (1.0f / DIMC) - mean * mean;
    const float rstd = rsqrtf(var + 1e-5f);
    const float4 g4 = reinterpret_cast<const float4*>(g)[tid];
    const float4 b4 = reinterpret_cast<const float4*>(b)[tid];
    float o[4];
    o[0] = (vv.x - mean) * rstd * g4.x + b4.x;
    o[1] = (vv.y - mean) * rstd * g4.y + b4.y;
    o[2] = (vv.z - mean) * rstd * g4.z + b4.z;
    o[3] = (vv.w - mean) * rstd * g4.w + b4.w;
    __nv_bfloat16 h[4], l[4];
#pragma unroll
    for (int i = 0; i < 4; i++) {
        h[i] = __float2bfloat16(o[i]);
        l[i] = __float2bfloat16(o[i] - __bfloat162float(h[i]));
    }
    __nv_bfloat162* H = reinterpret_cast<__nv_bfloat162*>(hi + (size_t)row * DIMC);
    __nv_bfloat162* L = reinterpret_cast<__nv_bfloat162*>(lo + (size_t)row * DIMC);
    H[tid * 2]     = __halves2bfloat162(h[0], h[1]);
    H[tid * 2 + 1] = __halves2bfloat162(h[2], h[3]);
    L[tid * 2]     = __halves2bfloat162(l[0], l[1]);
    L[tid * 2 + 1] = __halves2bfloat162(l[2], l[3]);
}

// ---------------------------------------------------------------------------
// Weight transpose + split
// ---------------------------------------------------------------------------
__global__ void __launch_bounds__(256) wsplit_kernel(const float* __restrict__ W0,
                                                     const float* __restrict__ W1,
                                                     const float* __restrict__ W2,
                                                     const float* __restrict__ W3,
                                                     __nv_bfloat16* __restrict__ hi,
                                                     __nv_bfloat16* __restrict__ lo) {
    const int z = blockIdx.z;
    const float* W = (z == 0) ? W0 : (z == 1) ? W1 : (z == 2) ? W2 : W3;
    const size_t ob = (size_t)z * DIMC * DIMC;
    __shared__ float t[32][33];
    const int tx = threadIdx.x, ty = threadIdx.y;
    const int n0 = blockIdx.x * 32, k0 = blockIdx.y * 32;
#pragma unroll
    for (int r = 0; r < 4; r++)
        t[ty + 8 * r][tx] = W[(size_t)(k0 + ty + 8 * r) * DIMC + n0 + tx];
    __syncthreads();
#pragma unroll
    for (int r = 0; r < 4; r++) {
        const float x = t[tx][ty + 8 * r];
        const __nv_bfloat16 h = __float2bfloat16(x);
        const __nv_bfloat16 l = __float2bfloat16(x - __bfloat162float(h));
        const size_t o = ob + (size_t)(n0 + ty + 8 * r) * DIMC + k0 + tx;
        hi[o] = h;
        lo[o] = l;
    }
}

// ---------------------------------------------------------------------------
// mma.sync bf16 GEMM, 3x split. Tile 128(M) x 256(N), BK=32, 8 warps (2x4),
// warp tile 64x64 (4x8 m16n8 frags). cp.async double-buffer, 80B-pitch smem.
// CHEAD epilogue emits bf16 hi/lo for flash (q scaled / k head / v transposed).
// ---------------------------------------------------------------------------
#define ATILE_B (128 * 80)           // 10240
#define BTILE_B (256 * 80)           // 20480
#define STAGE_B (2 * ATILE_B + 2 * BTILE_B)   // 61440
#define GEMM_SMEM (2 * STAGE_B)               // 122880

__device__ __forceinline__ void load_stage(uint32_t st,
                                           const __nv_bfloat16* Ahi, const __nv_bfloat16* Alo,
                                           const __nv_bfloat16* Bhi, const __nv_bfloat16* Blo,
                                           int bm, int bn, int k0, int tid) {
#pragma unroll
    for (int it = 0; it < 2; it++) {            // A: 128 rows x 4 segs
        const int idx = tid + it * 256;
        const int row = idx >> 2, seg = idx & 3;
        const uint32_t so = (uint32_t)(row * 80 + seg * 16);
        const size_t ga = (size_t)(bm + row) * DIMC + k0 + seg * 8;
        cp16(st + so, Ahi + ga);
        cp16(st + ATILE_B + so, Alo + ga);
    }
#pragma unroll
    for (int it = 0; it < 4; it++) {            // B: 256 rows x 4 segs
        const int idx = tid + it * 256;
        const int row = idx >> 2, seg = idx & 3;
        const uint32_t so = (uint32_t)(row * 80 + seg * 16);
        const size_t gb = (size_t)(bn + row) * DIMC + k0 + seg * 8;
        cp16(st + 2 * ATILE_B + so, Bhi + gb);
        cp16(st + 2 * ATILE_B + BTILE_B + so, Blo + gb);
    }
    CP_COMMIT();
}

template <bool CHEAD>
__global__ void __launch_bounds__(256, 1) mma_gemm(
    const __nv_bfloat16* __restrict__ Ahi_base, const __nv_bfloat16* __restrict__ Alo_base,
    const __nv_bfloat16* __restrict__ Bhi_base, const __nv_bfloat16* __restrict__ Blo_base,
    const float* b0, const float* b1, const float* b2,
    float* C0, float* C1, float* C2,
    __nv_bfloat16* FHhi, __nv_bfloat16* FHlo) {
    extern __shared__ __align__(128) char smem[];
    const uint32_t sbase = (uint32_t)__cvta_generic_to_shared(smem);
    const int tid = threadIdx.x, wid = tid >> 5, lane = tid & 31;
    const int z = blockIdx.z;
    const __nv_bfloat16* Ahi = Ahi_base + (size_t)z * MROWS * DIMC;
    const __nv_bfloat16* Alo = Alo_base + (size_t)z * MROWS * DIMC;
    const __nv_bfloat16* Bhi = Bhi_base + (size_t)z * DIMC * DIMC;
    const __nv_bfloat16* Blo = Blo_base + (size_t)z * DIMC * DIMC;
    const float* bias = (z == 0) ? b0 : (z == 1) ? b1 : b2;
    float* C = (z == 0) ? C0 : (z == 1) ? C1 : C2;
    const int bm = blockIdx.y * 128;
    const int bn = blockIdx.x * 256;
    const int wr = wid >> 2;          // 0..1 -> m offset 64*wr
    const int wc = wid & 3;           // 0..3 -> n offset 64*wc

    float acc[4][8][4];
#pragma unroll
    for (int i = 0; i < 4; i++)
#pragma unroll
        for (int j = 0; j < 8; j++)
#pragma unroll
            for (int t = 0; t < 4; t++) acc[i][j][t] = 0.f;

    const int a_r = wr * 64 + (lane & 15);
    const uint32_t a_off0 = (uint32_t)(a_r * 80 + ((lane >> 4) << 4));
    const int b_n = wc * 64 + (lane & 7) + ((lane >> 4) << 3);
    const uint32_t b_off0 = (uint32_t)(b_n * 80 + (((lane >> 3) & 1) << 4));

    load_stage(sbase, Ahi, Alo, Bhi, Blo, bm, bn, 0, tid);
    load_stage(sbase + STAGE_B, Ahi, Alo, Bhi, Blo, bm, bn, 32, tid);

    for (int i = 0; i < 32; i++) {
        if (i < 31) { CP_WAIT(1); } else { CP_WAIT(0); }
        __syncthreads();
        const uint32_t st = sbase + (uint32_t)(i & 1) * STAGE_B;
#pragma unroll
        for (int h = 0; h < 2; h++) {
            const uint32_t hb = (uint32_t)(h * 32);
            uint32_t ah[4][4], al[4][4];
#pragma unroll
            for (int mf = 0; mf < 4; mf++) {
                const uint32_t ao = a_off0 + hb + (uint32_t)(mf * 16 * 80);
                ldmx4(ah[mf], st + ao);
                ldmx4(al[mf], st + ATILE_B + ao);
            }
            uint32_t bh[8][2], bl[8][2];
#pragma unroll
            for (int nf2 = 0; nf2 < 4; nf2++) {
                const uint32_t bo = b_off0 + hb + (uint32_t)(nf2 * 16 * 80);
                uint32_t r4[4];
                ldmx4(r4, st + 2 * ATILE_B + bo);
                bh[nf2 * 2][0] = r4[0]; bh[nf2 * 2][1] = r4[1];
                bh[nf2 * 2 + 1][0] = r4[2]; bh[nf2 * 2 + 1][1] = r4[3];
                ldmx4(r4, st + 2 * ATILE_B + BTILE_B + bo);
                bl[nf2 * 2][0] = r4[0]; bl[nf2 * 2][1] = r4[1];
                bl[nf2 * 2 + 1][0] = r4[2]; bl[nf2 * 2 + 1][1] = r4[3];
            }
#pragma unroll
            for (int mf = 0; mf < 4; mf++)
#pragma unroll
                for (int nf = 0; nf < 8; nf++) {
                    mma16816(acc[mf][nf], ah[mf], bh[nf]);
                    mma16816(acc[mf][nf], ah[mf], bl[nf]);
                    mma16816(acc[mf][nf], al[mf], bh[nf]);
                }
        }
        __syncthreads();
        if (i + 2 < 32)
            load_stage(st, Ahi, Alo, Bhi, Blo, bm, bn, (i + 2) * 32, tid);
    }

    const int lr = lane >> 2, lc = (lane & 3) * 2;
#pragma unroll
    for (int mf = 0; mf < 4; mf++) {
#pragma unroll
        for (int nf = 0; nf < 8; nf++) {
            const int col = bn + wc * 64 + nf * 8 + lc;
            const float bx = bias[col], by = bias[col + 1];
            const int r0 = bm + wr * 64 + mf * 16 + lr;
#pragma unroll
            for (int half = 0; half < 2; half++) {
                const int r = r0 + half * 8;
                const float a = acc[mf][nf][half * 2 + 0] + bx;
                const float c2 = acc[mf][nf][half * 2 + 1] + by;
                if (CHEAD) {
                    const int b = r >> 11, n = r & (NSEQ - 1);
                    const int hh = col >> 6, d0 = col & 63;
                    const size_t hoff = (((size_t)(b * NHEADS + hh) * NSEQ + n) << 6) + d0;
                    if (z == 0) {
                        const float sa = a * 0.125f, sb = c2 * 0.125f;
                        const __nv_bfloat162 h2 = __floats2bfloat162_rn(sa, sb);
                        const float2 f = __bfloat1622float2(h2);
                        const __nv_bfloat162 l2 = __floats2bfloat162_rn(sa - f.x, sb - f.y);
                        *reinterpret_cast<__nv_bfloat162*>(FHhi + hoff) = h2;
                        *reinterpret_cast<__nv_bfloat162*>(FHlo + hoff) = l2;
                    } else if (z == 1) {
                        float2 o; o.x = a; o.y = c2;
                        *reinterpret_cast<float2*>(C + hoff) = o;
                        const __nv_bfloat162 h2 = __floats2bfloat162_rn(a, c2);
                        const float2 f = __bfloat1622float2(h2);
                        const __nv_bfloat162 l2 = __floats2bfloat162_rn(a - f.x, c2 - f.y);
                        *reinterpret_cast<__nv_bfloat162*>(FHhi + SLOT + hoff) = h2;
                        *reinterpret_cast<__nv_bfloat162*>(FHlo + SLOT + hoff) = l2;
                    } else {
                        float2 o; o.x = a; o.y = c2;
                        *reinterpret_cast<float2*>(C + hoff) = o;
                        const __nv_bfloat16 ha = __float2bfloat16(a);
                        const __nv_bfloat16 hb2 = __float2bfloat16(c2);
                        const __nv_bfloat16 la = __float2bfloat16(a - __bfloat162float(ha));
                        const __nv_bfloat16 lb = __float2bfloat16(c2 - __bfloat162float(hb2));
                        const size_t tb = ((size_t)(b * NHEADS + hh) * HD + d0) * NSEQ + n;
                        FHhi[2 * SLOT + tb] = ha;
                        FHhi[2 * SLOT + tb + NSEQ] = hb2;
                        FHlo[2 * SLOT + tb] = la;
                        FHlo[2 * SLOT + tb + NSEQ] = lb;
                    }
                } else {
                    float2 o; o.x = a; o.y = c2;
                    *reinterpret_cast<float2*>(C + (size_t)r * DIMC + col) = o;
                }
            }
        }
    }
}

// ---------------------------------------------------------------------------
// Flash attention on tensor cores (unchanged from R7 — validated).
// ---------------------------------------------------------------------------
#define FPITCH  144
#define FQ_B    (128 * FPITCH)
#define FT_B    (64 * FPITCH)
#define FSTG_B  (4 * FT_B)
#define FLASH_SMEM (2 * FQ_B + 2 * FSTG_B)   // 110592

__device__ __forceinline__ void load_kv(uint32_t st,
                                        const __nv_bfloat16* khi, const __nv_bfloat16* klo,
                                        const __nv_bfloat16* vthi, const __nv_bfloat16* vtlo,
                                        int bh, int kt, int tid) {
#pragma unroll
    for (int it = 0; it < 2; it++) {
        const int idx = tid + it * 256;
        const int row = idx >> 3, seg = idx & 7;
        const uint32_t so = (uint32_t)(row * FPITCH + seg * 16);
        const size_t gk = (size_t)bh * NSEQ * HD + (size_t)(kt * 64 + row) * HD + seg * 8;
        const size_t gv = ((size_t)bh * HD + row) * NSEQ + kt * 64 + seg * 8;
        cp16(st + 0 * FT_B + so, khi + gk);
        cp16(st + 1 * FT_B + so, klo + gk);
        cp16(st + 2 * FT_B + so, vthi + gv);
        cp16(st + 3 * FT_B + so, vtlo + gv);
    }
    CP_COMMIT();
}

__global__ void __launch_bounds__(256, 1) flash_mma(
    const __nv_bfloat16* __restrict__ FHhi, const __nv_bfloat16* __restrict__ FHlo,
    __nv_bfloat16* __restrict__ Ohi, __nv_bfloat16* __restrict__ Olo) {
    extern __shared__ __align__(128) char smem[];
    const uint32_t sbase = (uint32_t)__cvta_generic_to_shared(smem);
    const int tid = threadIdx.x, wid = tid >> 5, lane = tid & 31;
    const int bh = blockIdx.y;
    const int q0 = blockIdx.x * 128;

    const __nv_bfloat16* qhi = FHhi;
    const __nv_bfloat16* qlo = FHlo;
    const __nv_bfloat16* khi = FHhi + SLOT;
    const __nv_bfloat16* klo = FHlo + SLOT;
    const __nv_bfloat16* vthi = FHhi + 2 * SLOT;
    const __nv_bfloat16* vtlo = FHlo + 2 * SLOT;

#pragma unroll
    for (int it = 0; it < 4; it++) {
        const int idx = tid + it * 256;
        const int row = idx >> 3, seg = idx & 7;
        const uint32_t so = (uint32_t)(row * FPITCH + seg * 16);
        const size_t gq = (size_t)bh * NSEQ * HD + (size_t)(q0 + row) * HD + seg * 8;
        cp16(sbase + so, qhi + gq);
        cp16(sbase + FQ_B + so, qlo + gq);
    }
    CP_COMMIT();
    const uint32_t stg0 = sbase + 2 * FQ_B;
    load_kv(stg0, khi, klo, vthi, vtlo, bh, 0, tid);
    load_kv(stg0 + FSTG_B, khi, klo, vthi, vtlo, bh, 1, tid);

    CP_WAIT(2);
    __syncthreads();

    uint32_t qfh[4][4], qfl[4][4];
    {
        const int a_r = wid * 16 + (lane & 15);
        const uint32_t a0 = (uint32_t)(a_r * FPITCH + ((lane >> 4) << 4));
#pragma unroll
        for (int kf = 0; kf < 4; kf++) {
            ldmx4(qfh[kf], sbase + a0 + kf * 32);
            ldmx4(qfl[kf], sbase + FQ_B + a0 + kf * 32);
        }
    }

    const uint32_t b_off0 =
        (uint32_t)(((lane & 7) + ((lane >> 4) << 3)) * FPITCH + (((lane >> 3) & 1) << 4));

    float o[8][4];
#pragma unroll
    for (int nf = 0; nf < 8; nf++)
#pragma unroll
        for (int t = 0; t < 4; t++) o[nf][t] = 0.f;
    float mA = -1e30f, mB = -1e30f, lA = 0.f, lB = 0.f;

    for (int kt = 0; kt < NSEQ / 64; kt++) {
        if (kt < NSEQ / 64 - 1) { CP_WAIT(1); } else { CP_WAIT(0); }
        __syncthreads();
        const uint32_t st = stg0 + (uint32_t)(kt & 1) * FSTG_B;

        float s[8][4];
#pragma unroll
        for (int nf = 0; nf < 8; nf++)
#pragma unroll
            for (int t = 0; t < 4; t++) s[nf][t] = 0.f;
#pragma unroll
        for (int kf = 0; kf < 4; kf++) {
#pragma unroll
            for (int nf2 = 0; nf2 < 4; nf2++) {
                const uint32_t bo = b_off0 + (uint32_t)(nf2 * 16 * FPITCH) + kf * 32;
                uint32_t kh4[4], kl4[4];
                ldmx4(kh4, st + 0 * FT_B + bo);
                ldmx4(kl4, st + 1 * FT_B + bo);
                mma16816(s[nf2 * 2], qfh[kf], &kh4[0]);
                mma16816(s[nf2 * 2], qfh[kf], &kl4[0]);
                mma16816(s[nf2 * 2], qfl[kf], &kh4[0]);
                mma16816(s[nf2 * 2 + 1], qfh[kf], &kh4[2]);
                mma16816(s[nf2 * 2 + 1], qfh[kf], &kl4[2]);
                mma16816(s[nf2 * 2 + 1], qfl[kf], &kh4[2]);
            }
        }

        float rmA = -1e30f, rmB = -1e30f;
#pragma unroll
        for (int nf = 0; nf < 8; nf++) {
            rmA = fmaxf(rmA, fmaxf(s[nf][0], s[nf][1]));
            rmB = fmaxf(rmB, fmaxf(s[nf][2], s[nf][3]));
        }
        rmA = fmaxf(rmA, __shfl_xor_sync(0xffffffffu, rmA, 1, 4));
        rmA = fmaxf(rmA, __shfl_xor_sync(0xffffffffu, rmA, 2, 4));
        rmB = fmaxf(rmB, __shfl_xor_sync(0xffffffffu, rmB, 1, 4));
        rmB = fmaxf(rmB, __shfl_xor_sync(0xffffffffu, rmB, 2, 4));
        const float mnA = fmaxf(mA, rmA);
        const float mnB = fmaxf(mB, rmB);
        const float cA = __expf(mA - mnA);
        const float cB = __expf(mB - mnB);
        mA = mnA; mB = mnB;
        float sumA = 0.f, sumB = 0.f;
#pragma unroll
        for (int nf = 0; nf < 8; nf++) {
            s[nf][0] = __expf(s[nf][0] - mnA);
            s[nf][1] = __expf(s[nf][1] - mnA);
            s[nf][2] = __expf(s[nf][2] - mnB);
            s[nf][3] = __expf(s[nf][3] - mnB);
            sumA += s[nf][0] + s[nf][1];
            sumB += s[nf][2] + s[nf][3];
        }
        sumA += __shfl_xor_sync(0xffffffffu, sumA, 1, 4);
        sumA += __shfl_xor_sync(0xffffffffu, sumA, 2, 4);
        sumB += __shfl_xor_sync(0xffffffffu, sumB, 1, 4);
        sumB += __shfl_xor_sync(0xffffffffu, sumB, 2, 4);
        lA = lA * cA + sumA;
        lB = lB * cB + sumB;
#pragma unroll
        for (int nf = 0; nf < 8; nf++) {
            o[nf][0] *= cA; o[nf][1] *= cA;
            o[nf][2] *= cB; o[nf][3] *= cB;
        }

#pragma unroll
        for (int kf = 0; kf < 4; kf++) {
            uint32_t pah[4], pal[4];
#pragma unroll
            for (int blk = 0; blk < 2; blk++) {
                const float p0 = s[2 * kf + blk][0], p1 = s[2 * kf + blk][1];
                const float p2 = s[2 * kf + blk][2], p3 = s[2 * kf + blk][3];
                const __nv_bfloat162 h01 = __floats2bfloat162_rn(p0, p1);
                const __nv_bfloat162 h23 = __floats2bfloat162_rn(p2, p3);
                const float2 f01 = __bfloat1622float2(h01);
                const float2 f23 = __bfloat1622float2(h23);
                pah[blk * 2 + 0] = *reinterpret_cast<const uint32_t*>(&h01);
                pah[blk * 2 + 1] = *reinterpret_cast<const uint32_t*>(&h23);
                pal[blk * 2 + 0] = pack_bf16x2(p0 - f01.x, p1 - f01.y);
                pal[blk * 2 + 1] = pack_bf16x2(p2 - f23.x, p3 - f23.y);
            }
#pragma unroll
            for (int nf2 = 0; nf2 < 4; nf2++) {
                const uint32_t bo = b_off0 + (uint32_t)(nf2 * 16 * FPITCH) + kf * 32;
                uint32_t vh4[4], vl4[4];
                ldmx4(vh4, st + 2 * FT_B + bo);
                ldmx4(vl4, st + 3 * FT_B + bo);
                mma16816(o[nf2 * 2], pah, &vh4[0]);
                mma16816(o[nf2 * 2], pah, &vl4[0]);
                mma16816(o[nf2 * 2], pal, &vh4[0]);
                mma16816(o[nf2 * 2 + 1], pah, &vh4[2]);
                mma16816(o[nf2 * 2 + 1], pah, &vl4[2]);
                mma16816(o[nf2 * 2 + 1], pal, &vh4[2]);
            }
        }

        __syncthreads();
        if (kt + 2 < NSEQ / 64)
            load_kv(st, khi, klo, vthi, vtlo, bh, kt + 2, tid);
    }

    const float invA = 1.0f / lA;
    const float invB = 1.0f / lB;
    const int b = bh >> 4, h = bh & 15;
    const int rA = q0 + wid * 16 + (lane >> 2);
    const int rB = rA + 8;
    const size_t baseA = ((size_t)(b * NSEQ + rA)) * DIMC + h * 64;
    const size_t baseB = ((size_t)(b * NSEQ + rB)) * DIMC + h * 64;
#pragma unroll
    for (int nf = 0; nf < 8; nf++) {
        const int col = nf * 8 + (lane & 3) * 2;
        const float a0 = o[nf][0] * invA, a1 = o[nf][1] * invA;
        const float b0 = o[nf][2] * invB, b1 = o[nf][3] * invB;
        const __nv_bfloat162 hA = __floats2bfloat162_rn(a0, a1);
        const float2 fA = __bfloat1622float2(hA);
        const __nv_bfloat162 lA2 = __floats2bfloat162_rn(a0 - fA.x, a1 - fA.y);
        const __nv_bfloat162 hB = __floats2bfloat162_rn(b0, b1);
        const float2 fB = __bfloat1622float2(hB);
        const __nv_bfloat162 lB2 = __floats2bfloat162_rn(b0 - fB.x, b1 - fB.y);
        *reinterpret_cast<__nv_bfloat162*>(Ohi + baseA + col) = hA;
        *reinterpret_cast<__nv_bfloat162*>(Olo + baseA + col) = lA2;
        *reinterpret_cast<__nv_bfloat162*>(Ohi + baseB + col) = hB;
        *reinterpret_cast<__nv_bfloat162*>(Olo + baseB + col) = lB2;
    }
}

// ---------------------------------------------------------------------------
extern "C" void kernel_launch(void* const* d_in, const int* in_sizes, int n_in,
                              void* d_out, int out_size) {
    const float* q    = (const float*)d_in[0];
    const float* k    = (const float*)d_in[1];
    const float* v    = (const float*)d_in[2];
    const float* gq   = (const float*)d_in[3];
    const float* bqln = (const float*)d_in[4];
    const float* gk   = (const float*)d_in[5];
    const float* bkln = (const float*)d_in[6];
    const float* gv   = (const float*)d_in[7];
    const float* bvln = (const float*)d_in[8];
    const float* Wq   = (const float*)d_in[9];
    const float* bq   = (const float*)d_in[10];
    const float* Wk   = (const float*)d_in[11];
    const float* bk   = (const float*)d_in[12];
    const float* Wv   = (const float*)d_in[13];
    const float* bv   = (const float*)d_in[14];
    const float* Wp   = (const float*)d_in[15];
    const float* bp   = (const float*)d_in[16];

    float* out = (float*)d_out;
    float* kh  = out + (size_t)MROWS * DIMC;
    float* vh  = kh + (size_t)MROWS * DIMC;

    __nv_bfloat16 *lnhi, *lnlo, *wthi, *wtlo, *fhhi, *fhlo, *oshi, *oslo;
    float* dummy;
    cudaGetSymbolAddress((void**)&lnhi, g_ln_hi);
    cudaGetSymbolAddress((void**)&lnlo, g_ln_lo);
    cudaGetSymbolAddress((void**)&wthi, g_wt_hi);
    cudaGetSymbolAddress((void**)&wtlo, g_wt_lo);
    cudaGetSymbolAddress((void**)&fhhi, g_fh_hi);
    cudaGetSymbolAddress((void**)&fhlo, g_fh_lo);
    cudaGetSymbolAddress((void**)&oshi, g_os_hi);
    cudaGetSymbolAddress((void**)&oslo, g_os_lo);
    cudaGetSymbolAddress((void**)&dummy, g_dummy);

    // 1) Fused LayerNorm + split (q/k/v in one launch)
    ln_split_fused<<<dim3(MROWS, 3), 256>>>(q, k, v, gq, bqln, gk, bkln, gv, bvln,
                                            lnhi, lnlo);

    // 2) Weight transpose + split
    wsplit_kernel<<<dim3(32, 32, 4), dim3(32, 8)>>>(Wq, Wk, Wv, Wp, wthi, wtlo);

    // 3) QKV projection (tensor cores), emits flash-ready bf16 hi/lo
    cudaFuncSetAttribute(mma_gemm<true>, cudaFuncAttributeMaxDynamicSharedMemorySize, GEMM_SMEM);
    cudaFuncSetAttribute(mma_gemm<false>, cudaFuncAttributeMaxDynamicSharedMemorySize, GEMM_SMEM);
    mma_gemm<true><<<dim3(4, 32, 3), 256, GEMM_SMEM>>>(
        lnhi, lnlo, wthi, wtlo, bq, bk, bv, dummy, kh, vh, fhhi, fhlo);

    // 4) Flash attention on tensor cores -> split bf16 row-major output
    cudaFuncSetAttribute(flash_mma, cudaFuncAttributeMaxDynamicSharedMemorySize, FLASH_SMEM);
    flash_mma<<<dim3(NSEQ / 128, BHNUM), 256, FLASH_SMEM>>>(fhhi, fhlo, oshi, oslo);

    // 5) Output projection
    mma_gemm<false><<<dim3(4, 32, 1), 256, GEMM_SMEM>>>(
        oshi, oslo, wthi + 3ull * DIMC * DIMC, wtlo + 3ull * DIMC * DIMC,
        bp, bp, bp, out, out, out, fhhi, fhlo);
}

// round 10
// speedup vs baseline: 2.8495x; 1.0184x over previous
#include <cuda_runtime.h>
#include <cuda_bf16.h>
#include <cstdint>
#include <math.h>

#define DIMC   1024
#define NSEQ   2048
#define BATCH  2
#define NHEADS 16
#define HD     64
#define MROWS  (BATCH * NSEQ)     // 4096
#define BHNUM  (BATCH * NHEADS)   // 32
#define SLOT   ((size_t)BHNUM * NSEQ * HD)   // elements per q/k/v slot

// ---------------------------------------------------------------------------
// Scratch (static device globals — no runtime allocation allowed)
// ---------------------------------------------------------------------------
__device__ __nv_bfloat16 g_ln_hi[3ull * MROWS * DIMC];
__device__ __nv_bfloat16 g_ln_lo[3ull * MROWS * DIMC];
__device__ __nv_bfloat16 g_wt_hi[4ull * DIMC * DIMC];    // W transposed [N][K]
__device__ __nv_bfloat16 g_wt_lo[4ull * DIMC * DIMC];
__device__ __nv_bfloat16 g_fh_hi[3ull * SLOT];           // q(head,scaled)/k(head)/vT
__device__ __nv_bfloat16 g_fh_lo[3ull * SLOT];
__device__ __nv_bfloat16 g_os_hi[(size_t)MROWS * DIMC];  // flash out split (row-major)
__device__ __nv_bfloat16 g_os_lo[(size_t)MROWS * DIMC];
__device__ float g_dummy[(size_t)MROWS * DIMC];          // unused fp32 sink for z=0

// ---------------------------------------------------------------------------
// PTX helpers (baseline ISA only)
// ---------------------------------------------------------------------------
__device__ __forceinline__ void cp16(uint32_t s, const void* g) {
    asm volatile("cp.async.cg.shared.global [%0], [%1], 16;\n"
                 :: "r"(s), "l"(__cvta_generic_to_global(g)) : "memory");
}
#define CP_COMMIT() asm volatile("cp.async.commit_group;\n" ::: "memory")
#define CP_WAIT(n)  asm volatile("cp.async.wait_group %0;\n" :: "n"(n) : "memory")

__device__ __forceinline__ void ldmx4(uint32_t* r, uint32_t addr) {
    asm volatile("ldmatrix.sync.aligned.m8n8.x4.shared.b16 {%0,%1,%2,%3}, [%4];"
                 : "=r"(r[0]), "=r"(r[1]), "=r"(r[2]), "=r"(r[3]) : "r"(addr));
}

__device__ __forceinline__ void mma16816(float* c, const uint32_t* a, const uint32_t* b) {
    asm volatile("mma.sync.aligned.m16n8k16.row.col.f32.bf16.bf16.f32 "
                 "{%0,%1,%2,%3}, {%4,%5,%6,%7}, {%8,%9}, {%0,%1,%2,%3};"
                 : "+f"(c[0]), "+f"(c[1]), "+f"(c[2]), "+f"(c[3])
                 : "r"(a[0]), "r"(a[1]), "r"(a[2]), "r"(a[3]), "r"(b[0]), "r"(b[1]));
}

__device__ __forceinline__ uint32_t pack_bf16x2(float a, float b) {
    __nv_bfloat162 t = __floats2bfloat162_rn(a, b);
    return *reinterpret_cast<uint32_t*>(&t);
}

// ---------------------------------------------------------------------------
// Fused LayerNorm + bf16 split for q/k/v (z = blockIdx.y)
// ---------------------------------------------------------------------------
__global__ void __launch_bounds__(256) ln_split_fused(
    const float* __restrict__ q, const float* __restrict__ k, const float* __restrict__ v,
    const float* __restrict__ gq, const float* __restrict__ bq,
    const float* __restrict__ gk, const float* __restrict__ bk,
    const float* __restrict__ gv, const float* __restrict__ bv,
    __nv_bfloat16* __restrict__ hi_base, __nv_bfloat16* __restrict__ lo_base) {
    const int z = blockIdx.y;
    const float* x = (z == 0) ? q : (z == 1) ? k : v;
    const float* g = (z == 0) ? gq : (z == 1) ? gk : gv;
    const float* b = (z == 0) ? bq : (z == 1) ? bk : bv;
    __nv_bfloat16* hi = hi_base + (size_t)z * MROWS * DIMC;
    __nv_bfloat16* lo = lo_base + (size_t)z * MROWS * DIMC;

    const int row = blockIdx.x;
    const int tid = threadIdx.x;
    const float4 vv = reinterpret_cast<const float4*>(x + (size_t)row * DIMC)[tid];
    float s  = vv.x + vv.y + vv.z + vv.w;
    float ss = vv.x * vv.x + vv.y * vv.y + vv.z * vv.z + vv.w * vv.w;
#pragma unroll
    for (int off = 16; off > 0; off >>= 1) {
        s  += __shfl_xor_sync(0xffffffffu, s, off);
        ss += __shfl_xor_sync(0xffffffffu, ss, off);
    }
    __shared__ float rs[8], rss[8];
    if ((tid & 31) == 0) { rs[tid >> 5] = s; rss[tid >> 5] = ss; }
    __syncthreads();
    float tot = 0.f, totss = 0.f;
#pragma unroll
    for (int i = 0; i < 8; i++) { tot += rs[i]; totss += rss[i]; }
    const float mean = tot * (1.0f / DIMC);
    const float var  = totss * (1.0f / DIMC) - mean * mean;
    const float rstd = rsqrtf(var + 1e-5f);
    const float4 g4 = reinterpret_cast<const float4*>(g)[tid];
    const float4 b4 = reinterpret_cast<const float4*>(b)[tid];
    float o[4];
    o[0] = (vv.x - mean) * rstd * g4.x + b4.x;
    o[1] = (vv.y - mean) * rstd * g4.y + b4.y;
    o[2] = (vv.z - mean) * rstd * g4.z + b4.z;
    o[3] = (vv.w - mean) * rstd * g4.w + b4.w;
    __nv_bfloat16 h[4], l[4];
#pragma unroll
    for (int i = 0; i < 4; i++) {
        h[i] = __float2bfloat16(o[i]);
        l[i] = __float2bfloat16(o[i] - __bfloat162float(h[i]));
    }
    __nv_bfloat162* H = reinterpret_cast<__nv_bfloat162*>(hi + (size_t)row * DIMC);
    __nv_bfloat162* L = reinterpret_cast<__nv_bfloat162*>(lo + (size_t)row * DIMC);
    H[tid * 2]     = __halves2bfloat162(h[0], h[1]);
    H[tid * 2 + 1] = __halves2bfloat162(h[2], h[3]);
    L[tid * 2]     = __halves2bfloat162(l[0], l[1]);
    L[tid * 2 + 1] = __halves2bfloat162(l[2], l[3]);
}

// ---------------------------------------------------------------------------
// Weight transpose + split
// ---------------------------------------------------------------------------
__global__ void __launch_bounds__(256) wsplit_kernel(const float* __restrict__ W0,
                                                     const float* __restrict__ W1,
                                                     const float* __restrict__ W2,
                                                     const float* __restrict__ W3,
                                                     __nv_bfloat16* __restrict__ hi,
                                                     __nv_bfloat16* __restrict__ lo) {
    const int z = blockIdx.z;
    const float* W = (z == 0) ? W0 : (z == 1) ? W1 : (z == 2) ? W2 : W3;
    const size_t ob = (size_t)z * DIMC * DIMC;
    __shared__ float t[32][33];
    const int tx = threadIdx.x, ty = threadIdx.y;
    const int n0 = blockIdx.x * 32, k0 = blockIdx.y * 32;
#pragma unroll
    for (int r = 0; r < 4; r++)
        t[ty + 8 * r][tx] = W[(size_t)(k0 + ty + 8 * r) * DIMC + n0 + tx];
    __syncthreads();
#pragma unroll
    for (int r = 0; r < 4; r++) {
        const float x = t[tx][ty + 8 * r];
        const __nv_bfloat16 h = __float2bfloat16(x);
        const __nv_bfloat16 l = __float2bfloat16(x - __bfloat162float(h));
        const size_t o = ob + (size_t)(n0 + ty + 8 * r) * DIMC + k0 + tx;
        hi[o] = h;
        lo[o] = l;
    }
}

// ---------------------------------------------------------------------------
// mma.sync bf16 GEMM, 3x split. Tile 128(M) x 256(N), BK=32, 512 threads,
// 16 warps (4x4), warp tile 32x64 (2x8 m16n8 frags). cp.async double-buffer.
// CHEAD epilogue emits bf16 hi/lo for flash (q scaled / k head / v transposed).
// ---------------------------------------------------------------------------
#define ATILE_B (128 * 80)           // 10240
#define BTILE_B (256 * 80)           // 20480
#define STAGE_B (2 * ATILE_B + 2 * BTILE_B)   // 61440
#define GEMM_SMEM (2 * STAGE_B)               // 122880

__device__ __forceinline__ void load_stage(uint32_t st,
                                           const __nv_bfloat16* Ahi, const __nv_bfloat16* Alo,
                                           const __nv_bfloat16* Bhi, const __nv_bfloat16* Blo,
                                           int bm, int bn, int k0, int tid) {
    {                                            // A: 128 rows x 4 segs = 512
        const int row = tid >> 2, seg = tid & 3;
        const uint32_t so = (uint32_t)(row * 80 + seg * 16);
        const size_t ga = (size_t)(bm + row) * DIMC + k0 + seg * 8;
        cp16(st + so, Ahi + ga);
        cp16(st + ATILE_B + so, Alo + ga);
    }
#pragma unroll
    for (int it = 0; it < 2; it++) {             // B: 256 rows x 4 segs = 1024
        const int idx = tid + it * 512;
        const int row = idx >> 2, seg = idx & 3;
        const uint32_t so = (uint32_t)(row * 80 + seg * 16);
        const size_t gb = (size_t)(bn + row) * DIMC + k0 + seg * 8;
        cp16(st + 2 * ATILE_B + so, Bhi + gb);
        cp16(st + 2 * ATILE_B + BTILE_B + so, Blo + gb);
    }
    CP_COMMIT();
}

template <bool CHEAD>
__global__ void __launch_bounds__(512, 1) mma_gemm(
    const __nv_bfloat16* __restrict__ Ahi_base, const __nv_bfloat16* __restrict__ Alo_base,
    const __nv_bfloat16* __restrict__ Bhi_base, const __nv_bfloat16* __restrict__ Blo_base,
    const float* b0, const float* b1, const float* b2,
    float* C0, float* C1, float* C2,
    __nv_bfloat16* FHhi, __nv_bfloat16* FHlo) {
    extern __shared__ __align__(128) char smem[];
    const uint32_t sbase = (uint32_t)__cvta_generic_to_shared(smem);
    const int tid = threadIdx.x, wid = tid >> 5, lane = tid & 31;
    const int z = blockIdx.z;
    const __nv_bfloat16* Ahi = Ahi_base + (size_t)z * MROWS * DIMC;
    const __nv_bfloat16* Alo = Alo_base + (size_t)z * MROWS * DIMC;
    const __nv_bfloat16* Bhi = Bhi_base + (size_t)z * DIMC * DIMC;
    const __nv_bfloat16* Blo = Blo_base + (size_t)z * DIMC * DIMC;
    const float* bias = (z == 0) ? b0 : (z == 1) ? b1 : b2;
    float* C = (z == 0) ? C0 : (z == 1) ? C1 : C2;
    const int bm = blockIdx.y * 128;
    const int bn = blockIdx.x * 256;
    const int wr = wid >> 2;          // 0..3 -> m offset 32*wr
    const int wc = wid & 3;           // 0..3 -> n offset 64*wc

    float acc[2][8][4];
#pragma unroll
    for (int i = 0; i < 2; i++)
#pragma unroll
        for (int j = 0; j < 8; j++)
#pragma unroll
            for (int t = 0; t < 4; t++) acc[i][j][t] = 0.f;

    const int a_r = wr * 32 + (lane & 15);
    const uint32_t a_off0 = (uint32_t)(a_r * 80 + ((lane >> 4) << 4));
    const int b_n = wc * 64 + (lane & 7) + ((lane >> 4) << 3);
    const uint32_t b_off0 = (uint32_t)(b_n * 80 + (((lane >> 3) & 1) << 4));

    load_stage(sbase, Ahi, Alo, Bhi, Blo, bm, bn, 0, tid);
    load_stage(sbase + STAGE_B, Ahi, Alo, Bhi, Blo, bm, bn, 32, tid);

    for (int i = 0; i < 32; i++) {
        if (i < 31) { CP_WAIT(1); } else { CP_WAIT(0); }
        __syncthreads();
        const uint32_t st = sbase + (uint32_t)(i & 1) * STAGE_B;
#pragma unroll
        for (int h = 0; h < 2; h++) {
            const uint32_t hb = (uint32_t)(h * 32);
            uint32_t ah[2][4], al[2][4];
#pragma unroll
            for (int mf = 0; mf < 2; mf++) {
                const uint32_t ao = a_off0 + hb + (uint32_t)(mf * 16 * 80);
                ldmx4(ah[mf], st + ao);
                ldmx4(al[mf], st + ATILE_B + ao);
            }
            uint32_t bh[8][2], bl[8][2];
#pragma unroll
            for (int nf2 = 0; nf2 < 4; nf2++) {
                const uint32_t bo = b_off0 + hb + (uint32_t)(nf2 * 16 * 80);
                uint32_t r4[4];
                ldmx4(r4, st + 2 * ATILE_B + bo);
                bh[nf2 * 2][0] = r4[0]; bh[nf2 * 2][1] = r4[1];
                bh[nf2 * 2 + 1][0] = r4[2]; bh[nf2 * 2 + 1][1] = r4[3];
                ldmx4(r4, st + 2 * ATILE_B + BTILE_B + bo);
                bl[nf2 * 2][0] = r4[0]; bl[nf2 * 2][1] = r4[1];
                bl[nf2 * 2 + 1][0] = r4[2]; bl[nf2 * 2 + 1][1] = r4[3];
            }
#pragma unroll
            for (int mf = 0; mf < 2; mf++)
#pragma unroll
                for (int nf = 0; nf < 8; nf++) {
                    mma16816(acc[mf][nf], ah[mf], bh[nf]);
                    mma16816(acc[mf][nf], ah[mf], bl[nf]);
                    mma16816(acc[mf][nf], al[mf], bh[nf]);
                }
        }
        __syncthreads();
        if (i + 2 < 32)
            load_stage(st, Ahi, Alo, Bhi, Blo, bm, bn, (i + 2) * 32, tid);
    }

    const int lr = lane >> 2, lc = (lane & 3) * 2;
#pragma unroll
    for (int mf = 0; mf < 2; mf++) {
#pragma unroll
        for (int nf = 0; nf < 8; nf++) {
            const int col = bn + wc * 64 + nf * 8 + lc;
            const float bx = bias[col], by = bias[col + 1];
            const int r0 = bm + wr * 32 + mf * 16 + lr;
#pragma unroll
            for (int half = 0; half < 2; half++) {
                const int r = r0 + half * 8;
                const float a = acc[mf][nf][half * 2 + 0] + bx;
                const float c2 = acc[mf][nf][half * 2 + 1] + by;
                if (CHEAD) {
                    const int b = r >> 11, n = r & (NSEQ - 1);
                    const int hh = col >> 6, d0 = col & 63;
                    const size_t hoff = (((size_t)(b * NHEADS + hh) * NSEQ + n) << 6) + d0;
                    if (z == 0) {
                        const float sa = a * 0.125f, sb = c2 * 0.125f;
                        const __nv_bfloat162 h2 = __floats2bfloat162_rn(sa, sb);
                        const float2 f = __bfloat1622float2(h2);
                        const __nv_bfloat162 l2 = __floats2bfloat162_rn(sa - f.x, sb - f.y);
                        *reinterpret_cast<__nv_bfloat162*>(FHhi + hoff) = h2;
                        *reinterpret_cast<__nv_bfloat162*>(FHlo + hoff) = l2;
                    } else if (z == 1) {
                        float2 o; o.x = a; o.y = c2;
                        *reinterpret_cast<float2*>(C + hoff) = o;
                        const __nv_bfloat162 h2 = __floats2bfloat162_rn(a, c2);
                        const float2 f = __bfloat1622float2(h2);
                        const __nv_bfloat162 l2 = __floats2bfloat162_rn(a - f.x, c2 - f.y);
                        *reinterpret_cast<__nv_bfloat162*>(FHhi + SLOT + hoff) = h2;
                        *reinterpret_cast<__nv_bfloat162*>(FHlo + SLOT + hoff) = l2;
                    } else {
                        float2 o; o.x = a; o.y = c2;
                        *reinterpret_cast<float2*>(C + hoff) = o;
                        const __nv_bfloat16 ha = __float2bfloat16(a);
                        const __nv_bfloat16 hb2 = __float2bfloat16(c2);
                        const __nv_bfloat16 la = __float2bfloat16(a - __bfloat162float(ha));
                        const __nv_bfloat16 lb = __float2bfloat16(c2 - __bfloat162float(hb2));
                        const size_t tb = ((size_t)(b * NHEADS + hh) * HD + d0) * NSEQ + n;
                        FHhi[2 * SLOT + tb] = ha;
                        FHhi[2 * SLOT + tb + NSEQ] = hb2;
                        FHlo[2 * SLOT + tb] = la;
                        FHlo[2 * SLOT + tb + NSEQ] = lb;
                    }
                } else {
                    float2 o; o.x = a; o.y = c2;
                    *reinterpret_cast<float2*>(C + (size_t)r * DIMC + col) = o;
                }
            }
        }
    }
}

// ---------------------------------------------------------------------------
// Flash attention on tensor cores. 512 threads (16 warps), BQ=256 (16 q-rows
// per warp — per-warp math identical to the validated R7 version). BK=64,
// double-buffered cp.async. Output: split bf16 row-major.
// ---------------------------------------------------------------------------
#define FPITCH  144
#define FQ_B    (256 * FPITCH)           // 36864 per Q tile (hi or lo)
#define FT_B    (64 * FPITCH)            // 9216 per K/V tile
#define FSTG_B  (4 * FT_B)               // 36864 per stage
#define FLASH_SMEM (2 * FQ_B + 2 * FSTG_B)   // 147456

__device__ __forceinline__ void load_kv(uint32_t st,
                                        const __nv_bfloat16* khi, const __nv_bfloat16* klo,
                                        const __nv_bfloat16* vthi, const __nv_bfloat16* vtlo,
                                        int bh, int kt, int tid) {
    const int row = tid >> 3, seg = tid & 7;     // 64 rows x 8 segs = 512
    const uint32_t so = (uint32_t)(row * FPITCH + seg * 16);
    const size_t gk = (size_t)bh * NSEQ * HD + (size_t)(kt * 64 + row) * HD + seg * 8;
    const size_t gv = ((size_t)bh * HD + row) * NSEQ + kt * 64 + seg * 8;
    cp16(st + 0 * FT_B + so, khi + gk);
    cp16(st + 1 * FT_B + so, klo + gk);
    cp16(st + 2 * FT_B + so, vthi + gv);
    cp16(st + 3 * FT_B + so, vtlo + gv);
    CP_COMMIT();
}

__global__ void __launch_bounds__(512, 1) flash_mma(
    const __nv_bfloat16* __restrict__ FHhi, const __nv_bfloat16* __restrict__ FHlo,
    __nv_bfloat16* __restrict__ Ohi, __nv_bfloat16* __restrict__ Olo) {
    extern __shared__ __align__(128) char smem[];
    const uint32_t sbase = (uint32_t)__cvta_generic_to_shared(smem);
    const int tid = threadIdx.x, wid = tid >> 5, lane = tid & 31;
    const int bh = blockIdx.y;
    const int q0 = blockIdx.x * 256;

    const __nv_bfloat16* qhi = FHhi;
    const __nv_bfloat16* qlo = FHlo;
    const __nv_bfloat16* khi = FHhi + SLOT;
    const __nv_bfloat16* klo = FHlo + SLOT;
    const __nv_bfloat16* vthi = FHhi + 2 * SLOT;
    const __nv_bfloat16* vtlo = FHlo + 2 * SLOT;

    // Q tiles -> smem: 256 rows x 8 segs (hi + lo) = 2048 cp16 x2 over 512 thr
#pragma unroll
    for (int it = 0; it < 4; it++) {
        const int idx = tid + it * 512;
        const int row = idx >> 3, seg = idx & 7;
        const uint32_t so = (uint32_t)(row * FPITCH + seg * 16);
        const size_t gq = (size_t)bh * NSEQ * HD + (size_t)(q0 + row) * HD + seg * 8;
        cp16(sbase + so, qhi + gq);
        cp16(sbase + FQ_B + so, qlo + gq);
    }
    CP_COMMIT();
    const uint32_t stg0 = sbase + 2 * FQ_B;
    load_kv(stg0, khi, klo, vthi, vtlo, bh, 0, tid);
    load_kv(stg0 + FSTG_B, khi, klo, vthi, vtlo, bh, 1, tid);

    CP_WAIT(2);
    __syncthreads();

    uint32_t qfh[4][4], qfl[4][4];
    {
        const int a_r = wid * 16 + (lane & 15);
        const uint32_t a0 = (uint32_t)(a_r * FPITCH + ((lane >> 4) << 4));
#pragma unroll
        for (int kf = 0; kf < 4; kf++) {
            ldmx4(qfh[kf], sbase + a0 + kf * 32);
            ldmx4(qfl[kf], sbase + FQ_B + a0 + kf * 32);
        }
    }

    const uint32_t b_off0 =
        (uint32_t)(((lane & 7) + ((lane >> 4) << 3)) * FPITCH + (((lane >> 3) & 1) << 4));

    float o[8][4];
#pragma unroll
    for (int nf = 0; nf < 8; nf++)
#pragma unroll
        for (int t = 0; t < 4; t++) o[nf][t] = 0.f;
    float mA = -1e30f, mB = -1e30f, lA = 0.f, lB = 0.f;

    for (int kt = 0; kt < NSEQ / 64; kt++) {
        if (kt < NSEQ / 64 - 1) { CP_WAIT(1); } else { CP_WAIT(0); }
        __syncthreads();
        const uint32_t st = stg0 + (uint32_t)(kt & 1) * FSTG_B;

        float s[8][4];
#pragma unroll
        for (int nf = 0; nf < 8; nf++)
#pragma unroll
            for (int t = 0; t < 4; t++) s[nf][t] = 0.f;
#pragma unroll
        for (int kf = 0; kf < 4; kf++) {
#pragma unroll
            for (int nf2 = 0; nf2 < 4; nf2++) {
                const uint32_t bo = b_off0 + (uint32_t)(nf2 * 16 * FPITCH) + kf * 32;
                uint32_t kh4[4], kl4[4];
                ldmx4(kh4, st + 0 * FT_B + bo);
                ldmx4(kl4, st + 1 * FT_B + bo);
                mma16816(s[nf2 * 2], qfh[kf], &kh4[0]);
                mma16816(s[nf2 * 2], qfh[kf], &kl4[0]);
                mma16816(s[nf2 * 2], qfl[kf], &kh4[0]);
                mma16816(s[nf2 * 2 + 1], qfh[kf], &kh4[2]);
                mma16816(s[nf2 * 2 + 1], qfh[kf], &kl4[2]);
                mma16816(s[nf2 * 2 + 1], qfl[kf], &kh4[2]);
            }
        }

        float rmA = -1e30f, rmB = -1e30f;
#pragma unroll
        for (int nf = 0; nf < 8; nf++) {
            rmA = fmaxf(rmA, fmaxf(s[nf][0], s[nf][1]));
            rmB = fmaxf(rmB, fmaxf(s[nf][2], s[nf][3]));
        }
        rmA = fmaxf(rmA, __shfl_xor_sync(0xffffffffu, rmA, 1, 4));
        rmA = fmaxf(rmA, __shfl_xor_sync(0xffffffffu, rmA, 2, 4));
        rmB = fmaxf(rmB, __shfl_xor_sync(0xffffffffu, rmB, 1, 4));
        rmB = fmaxf(rmB, __shfl_xor_sync(0xffffffffu, rmB, 2, 4));
        const float mnA = fmaxf(mA, rmA);
        const float mnB = fmaxf(mB, rmB);
        const float cA = __expf(mA - mnA);
        const float cB = __expf(mB - mnB);
        mA = mnA; mB = mnB;
        float sumA = 0.f, sumB = 0.f;
#pragma unroll
        for (int nf = 0; nf < 8; nf++) {
            s[nf][0] = __expf(s[nf][0] - mnA);
            s[nf][1] = __expf(s[nf][1] - mnA);
            s[nf][2] = __expf(s[nf][2] - mnB);
            s[nf][3] = __expf(s[nf][3] - mnB);
            sumA += s[nf][0] + s[nf][1];
            sumB += s[nf][2] + s[nf][3];
        }
        sumA += __shfl_xor_sync(0xffffffffu, sumA, 1, 4);
        sumA += __shfl_xor_sync(0xffffffffu, sumA, 2, 4);
        sumB += __shfl_xor_sync(0xffffffffu, sumB, 1, 4);
        sumB += __shfl_xor_sync(0xffffffffu, sumB, 2, 4);
        lA = lA * cA + sumA;
        lB = lB * cB + sumB;
#pragma unroll
        for (int nf = 0; nf < 8; nf++) {
            o[nf][0] *= cA; o[nf][1] *= cA;
            o[nf][2] *= cB; o[nf][3] *= cB;
        }

#pragma unroll
        for (int kf = 0; kf < 4; kf++) {
            uint32_t pah[4], pal[4];
#pragma unroll
            for (int blk = 0; blk < 2; blk++) {
                const float p0 = s[2 * kf + blk][0], p1 = s[2 * kf + blk][1];
                const float p2 = s[2 * kf + blk][2], p3 = s[2 * kf + blk][3];
                const __nv_bfloat162 h01 = __floats2bfloat162_rn(p0, p1);
                const __nv_bfloat162 h23 = __floats2bfloat162_rn(p2, p3);
                const float2 f01 = __bfloat1622float2(h01);
                const float2 f23 = __bfloat1622float2(h23);
                pah[blk * 2 + 0] = *reinterpret_cast<const uint32_t*>(&h01);
                pah[blk * 2 + 1] = *reinterpret_cast<const uint32_t*>(&h23);
                pal[blk * 2 + 0] = pack_bf16x2(p0 - f01.x, p1 - f01.y);
                pal[blk * 2 + 1] = pack_bf16x2(p2 - f23.x, p3 - f23.y);
            }
#pragma unroll
            for (int nf2 = 0; nf2 < 4; nf2++) {
                const uint32_t bo = b_off0 + (uint32_t)(nf2 * 16 * FPITCH) + kf * 32;
                uint32_t vh4[4], vl4[4];
                ldmx4(vh4, st + 2 * FT_B + bo);
                ldmx4(vl4, st + 3 * FT_B + bo);
                mma16816(o[nf2 * 2], pah, &vh4[0]);
                mma16816(o[nf2 * 2], pah, &vl4[0]);
                mma16816(o[nf2 * 2], pal, &vh4[0]);
                mma16816(o[nf2 * 2 + 1], pah, &vh4[2]);
                mma16816(o[nf2 * 2 + 1], pah, &vl4[2]);
                mma16816(o[nf2 * 2 + 1], pal, &vh4[2]);
            }
        }

        __syncthreads();
        if (kt + 2 < NSEQ / 64)
            load_kv(st, khi, klo, vthi, vtlo, bh, kt + 2, tid);
    }

    const float invA = 1.0f / lA;
    const float invB = 1.0f / lB;
    const int b = bh >> 4, h = bh & 15;
    const int rA = q0 + wid * 16 + (lane >> 2);
    const int rB = rA + 8;
    const size_t baseA = ((size_t)(b * NSEQ + rA)) * DIMC + h * 64;
    const size_t baseB = ((size_t)(b * NSEQ + rB)) * DIMC + h * 64;
#pragma unroll
    for (int nf = 0; nf < 8; nf++) {
        const int col = nf * 8 + (lane & 3) * 2;
        const float a0 = o[nf][0] * invA, a1 = o[nf][1] * invA;
        const float b0 = o[nf][2] * invB, b1 = o[nf][3] * invB;
        const __nv_bfloat162 hA = __floats2bfloat162_rn(a0, a1);
        const float2 fA = __bfloat1622float2(hA);
        const __nv_bfloat162 lA2 = __floats2bfloat162_rn(a0 - fA.x, a1 - fA.y);
        const __nv_bfloat162 hB = __floats2bfloat162_rn(b0, b1);
        const float2 fB = __bfloat1622float2(hB);
        const __nv_bfloat162 lB2 = __floats2bfloat162_rn(b0 - fB.x, b1 - fB.y);
        *reinterpret_cast<__nv_bfloat162*>(Ohi + baseA + col) = hA;
        *reinterpret_cast<__nv_bfloat162*>(Olo + baseA + col) = lA2;
        *reinterpret_cast<__nv_bfloat162*>(Ohi + baseB + col) = hB;
        *reinterpret_cast<__nv_bfloat162*>(Olo + baseB + col) = lB2;
    }
}

// ---------------------------------------------------------------------------
extern "C" void kernel_launch(void* const* d_in, const int* in_sizes, int n_in,
                              void* d_out, int out_size) {
    const float* q    = (const float*)d_in[0];
    const float* k    = (const float*)d_in[1];
    const float* v    = (const float*)d_in[2];
    const float* gq   = (const float*)d_in[3];
    const float* bqln = (const float*)d_in[4];
    const float* gk   = (const float*)d_in[5];
    const float* bkln = (const float*)d_in[6];
    const float* gv   = (const float*)d_in[7];
    const float* bvln = (const float*)d_in[8];
    const float* Wq   = (const float*)d_in[9];
    const float* bq   = (const float*)d_in[10];
    const float* Wk   = (const float*)d_in[11];
    const float* bk   = (const float*)d_in[12];
    const float* Wv   = (const float*)d_in[13];
    const float* bv   = (const float*)d_in[14];
    const float* Wp   = (const float*)d_in[15];
    const float* bp   = (const float*)d_in[16];

    float* out = (float*)d_out;
    float* kh  = out + (size_t)MROWS * DIMC;
    float* vh  = kh + (size_t)MROWS * DIMC;

    __nv_bfloat16 *lnhi, *lnlo, *wthi, *wtlo, *fhhi, *fhlo, *oshi, *oslo;
    float* dummy;
    cudaGetSymbolAddress((void**)&lnhi, g_ln_hi);
    cudaGetSymbolAddress((void**)&lnlo, g_ln_lo);
    cudaGetSymbolAddress((void**)&wthi, g_wt_hi);
    cudaGetSymbolAddress((void**)&wtlo, g_wt_lo);
    cudaGetSymbolAddress((void**)&fhhi, g_fh_hi);
    cudaGetSymbolAddress((void**)&fhlo, g_fh_lo);
    cudaGetSymbolAddress((void**)&oshi, g_os_hi);
    cudaGetSymbolAddress((void**)&oslo, g_os_lo);
    cudaGetSymbolAddress((void**)&dummy, g_dummy);

    // 1) Fused LayerNorm + split (q/k/v in one launch)
    ln_split_fused<<<dim3(MROWS, 3), 256>>>(q, k, v, gq, bqln, gk, bkln, gv, bvln,
                                            lnhi, lnlo);

    // 2) Weight transpose + split
    wsplit_kernel<<<dim3(32, 32, 4), dim3(32, 8)>>>(Wq, Wk, Wv, Wp, wthi, wtlo);

    // 3) QKV projection (tensor cores), emits flash-ready bf16 hi/lo
    cudaFuncSetAttribute(mma_gemm<true>, cudaFuncAttributeMaxDynamicSharedMemorySize, GEMM_SMEM);
    cudaFuncSetAttribute(mma_gemm<false>, cudaFuncAttributeMaxDynamicSharedMemorySize, GEMM_SMEM);
    mma_gemm<true><<<dim3(4, 32, 3), 512, GEMM_SMEM>>>(
        lnhi, lnlo, wthi, wtlo, bq, bk, bv, dummy, kh, vh, fhhi, fhlo);

    // 4) Flash attention on tensor cores -> split bf16 row-major output
    cudaFuncSetAttribute(flash_mma, cudaFuncAttributeMaxDynamicSharedMemorySize, FLASH_SMEM);
    flash_mma<<<dim3(NSEQ / 256, BHNUM), 512, FLASH_SMEM>>>(fhhi, fhlo, oshi, oslo);

    // 5) Output projection
    mma_gemm<false><<<dim3(4, 32, 1), 512, GEMM_SMEM>>>(
        oshi, oslo, wthi + 3ull * DIMC * DIMC, wtlo + 3ull * DIMC * DIMC,
        bp, bp, bp, out, out, out, fhhi, fhlo);
}

// round 13
// speedup vs baseline: 2.9279x; 1.0275x over previous
#include <cuda_runtime.h>
#include <cuda_bf16.h>
#include <cstdint>
#include <math.h>

#define DIMC   1024
#define NSEQ   2048
#define BATCH  2
#define NHEADS 16
#define HD     64
#define MROWS  (BATCH * NSEQ)     // 4096
#define BHNUM  (BATCH * NHEADS)   // 32
#define SLOT   ((size_t)BHNUM * NSEQ * HD)   // elements per q/k/v slot

// ---------------------------------------------------------------------------
// Scratch (static device globals — no runtime allocation allowed)
// ---------------------------------------------------------------------------
__device__ __nv_bfloat16 g_ln_hi[3ull * MROWS * DIMC];
__device__ __nv_bfloat16 g_ln_lo[3ull * MROWS * DIMC];
__device__ __nv_bfloat16 g_wt_hi[4ull * DIMC * DIMC];    // W transposed [N][K]
__device__ __nv_bfloat16 g_wt_lo[4ull * DIMC * DIMC];
__device__ __nv_bfloat16 g_fh_hi[3ull * SLOT];           // q(head,scaled)/k(head)/vT
__device__ __nv_bfloat16 g_fh_lo[3ull * SLOT];
__device__ __nv_bfloat16 g_os_hi[(size_t)MROWS * DIMC];  // flash out split (row-major)
__device__ __nv_bfloat16 g_os_lo[(size_t)MROWS * DIMC];
__device__ float g_dummy[(size_t)MROWS * DIMC];          // unused fp32 sink for z=0

// ---------------------------------------------------------------------------
// PTX helpers (baseline ISA only)
// ---------------------------------------------------------------------------
__device__ __forceinline__ void cp16(uint32_t s, const void* g) {
    asm volatile("cp.async.cg.shared.global [%0], [%1], 16;\n"
                 :: "r"(s), "l"(__cvta_generic_to_global(g)) : "memory");
}
#define CP_COMMIT() asm volatile("cp.async.commit_group;\n" ::: "memory")
#define CP_WAIT(n)  asm volatile("cp.async.wait_group %0;\n" :: "n"(n) : "memory")
#define BAR_SYNC(id, cnt) \
    asm volatile("bar.sync %0, %1;" :: "r"(id), "r"(cnt) : "memory")

__device__ __forceinline__ void ldmx4(uint32_t* r, uint32_t addr) {
    asm volatile("ldmatrix.sync.aligned.m8n8.x4.shared.b16 {%0,%1,%2,%3}, [%4];"
                 : "=r"(r[0]), "=r"(r[1]), "=r"(r[2]), "=r"(r[3]) : "r"(addr));
}

__device__ __forceinline__ void mma16816(float* c, const uint32_t* a, const uint32_t* b) {
    asm volatile("mma.sync.aligned.m16n8k16.row.col.f32.bf16.bf16.f32 "
                 "{%0,%1,%2,%3}, {%4,%5,%6,%7}, {%8,%9}, {%0,%1,%2,%3};"
                 : "+f"(c[0]), "+f"(c[1]), "+f"(c[2]), "+f"(c[3])
                 : "r"(a[0]), "r"(a[1]), "r"(a[2]), "r"(a[3]), "r"(b[0]), "r"(b[1]));
}

__device__ __forceinline__ uint32_t pack_bf16x2(float a, float b) {
    __nv_bfloat162 t = __floats2bfloat162_rn(a, b);
    return *reinterpret_cast<uint32_t*>(&t);
}

// ---------------------------------------------------------------------------
// Fused LayerNorm + bf16 split for q/k/v (z = blockIdx.y)
// ---------------------------------------------------------------------------
__global__ void __launch_bounds__(256) ln_split_fused(
    const float* __restrict__ q, const float* __restrict__ k, const float* __restrict__ v,
    const float* __restrict__ gq, const float* __restrict__ bq,
    const float* __restrict__ gk, const float* __restrict__ bk,
    const float* __restrict__ gv, const float* __restrict__ bv,
    __nv_bfloat16* __restrict__ hi_base, __nv_bfloat16* __restrict__ lo_base) {
    const int z = blockIdx.y;
    const float* x = (z == 0) ? q : (z == 1) ? k : v;
    const float* g = (z == 0) ? gq : (z == 1) ? gk : gv;
    const float* b = (z == 0) ? bq : (z == 1) ? bk : bv;
    __nv_bfloat16* hi = hi_base + (size_t)z * MROWS * DIMC;
    __nv_bfloat16* lo = lo_base + (size_t)z * MROWS * DIMC;

    const int row = blockIdx.x;
    const int tid = threadIdx.x;
    const float4 vv = reinterpret_cast<const float4*>(x + (size_t)row * DIMC)[tid];
    float s  = vv.x + vv.y + vv.z + vv.w;
    float ss = vv.x * vv.x + vv.y * vv.y + vv.z * vv.z + vv.w * vv.w;
#pragma unroll
    for (int off = 16; off > 0; off >>= 1) {
        s  += __shfl_xor_sync(0xffffffffu, s, off);
        ss += __shfl_xor_sync(0xffffffffu, ss, off);
    }
    __shared__ float rs[8], rss[8];
    if ((tid & 31) == 0) { rs[tid >> 5] = s; rss[tid >> 5] = ss; }
    __syncthreads();
    float tot = 0.f, totss = 0.f;
#pragma unroll
    for (int i = 0; i < 8; i++) { tot += rs[i]; totss += rss[i]; }
    const float mean = tot * (1.0f / DIMC);
    const float var  = totss * (1.0f / DIMC) - mean * mean;
    const float rstd = rsqrtf(var + 1e-5f);
    const float4 g4 = reinterpret_cast<const float4*>(g)[tid];
    const float4 b4 = reinterpret_cast<const float4*>(b)[tid];
    float o[4];
    o[0] = (vv.x - mean) * rstd * g4.x + b4.x;
    o[1] = (vv.y - mean) * rstd * g4.y + b4.y;
    o[2] = (vv.z - mean) * rstd * g4.z + b4.z;
    o[3] = (vv.w - mean) * rstd * g4.w + b4.w;
    __nv_bfloat16 h[4], l[4];
#pragma unroll
    for (int i = 0; i < 4; i++) {
        h[i] = __float2bfloat16(o[i]);
        l[i] = __float2bfloat16(o[i] - __bfloat162float(h[i]));
    }
    __nv_bfloat162* H = reinterpret_cast<__nv_bfloat162*>(hi + (size_t)row * DIMC);
    __nv_bfloat162* L = reinterpret_cast<__nv_bfloat162*>(lo + (size_t)row * DIMC);
    H[tid * 2]     = __halves2bfloat162(h[0], h[1]);
    H[tid * 2 + 1] = __halves2bfloat162(h[2], h[3]);
    L[tid * 2]     = __halves2bfloat162(l[0], l[1]);
    L[tid * 2 + 1] = __halves2bfloat162(l[2], l[3]);
}

// ---------------------------------------------------------------------------
// Weight transpose + split
// ---------------------------------------------------------------------------
__global__ void __launch_bounds__(256) wsplit_kernel(const float* __restrict__ W0,
                                                     const float* __restrict__ W1,
                                                     const float* __restrict__ W2,
                                                     const float* __restrict__ W3,
                                                     __nv_bfloat16* __restrict__ hi,
                                                     __nv_bfloat16* __restrict__ lo) {
    const int z = blockIdx.z;
    const float* W = (z == 0) ? W0 : (z == 1) ? W1 : (z == 2) ? W2 : W3;
    const size_t ob = (size_t)z * DIMC * DIMC;
    __shared__ float t[32][33];
    const int tx = threadIdx.x, ty = threadIdx.y;
    const int n0 = blockIdx.x * 32, k0 = blockIdx.y * 32;
#pragma unroll
    for (int r = 0; r < 4; r++)
        t[ty + 8 * r][tx] = W[(size_t)(k0 + ty + 8 * r) * DIMC + n0 + tx];
    __syncthreads();
#pragma unroll
    for (int r = 0; r < 4; r++) {
        const float x = t[tx][ty + 8 * r];
        const __nv_bfloat16 h = __float2bfloat16(x);
        const __nv_bfloat16 l = __float2bfloat16(x - __bfloat162float(h));
        const size_t o = ob + (size_t)(n0 + ty + 8 * r) * DIMC + k0 + tx;
        hi[o] = h;
        lo[o] = l;
    }
}

// ---------------------------------------------------------------------------
// mma.sync bf16 GEMM, 3x split. Tile 128(M) x 256(N), BK=32, 512 threads,
// 16 warps (4x4), warp tile 32x64. 3-stage cp.async pipeline, ONE barrier
// per K-iteration; loads issued right after the wait (into the freed stage).
// ---------------------------------------------------------------------------
#define ATILE_B (128 * 80)           // 10240
#define BTILE_B (256 * 80)           // 20480
#define STAGE_B (2 * ATILE_B + 2 * BTILE_B)   // 61440
#define GEMM_SMEM (3 * STAGE_B)               // 184320

__device__ __forceinline__ void load_stage(uint32_t st,
                                           const __nv_bfloat16* Ahi, const __nv_bfloat16* Alo,
                                           const __nv_bfloat16* Bhi, const __nv_bfloat16* Blo,
                                           int bm, int bn, int k0, int tid) {
    {                                            // A: 128 rows x 4 segs = 512
        const int row = tid >> 2, seg = tid & 3;
        const uint32_t so = (uint32_t)(row * 80 + seg * 16);
        const size_t ga = (size_t)(bm + row) * DIMC + k0 + seg * 8;
        cp16(st + so, Ahi + ga);
        cp16(st + ATILE_B + so, Alo + ga);
    }
#pragma unroll
    for (int it = 0; it < 2; it++) {             // B: 256 rows x 4 segs = 1024
        const int idx = tid + it * 512;
        const int row = idx >> 2, seg = idx & 3;
        const uint32_t so = (uint32_t)(row * 80 + seg * 16);
        const size_t gb = (size_t)(bn + row) * DIMC + k0 + seg * 8;
        cp16(st + 2 * ATILE_B + so, Bhi + gb);
        cp16(st + 2 * ATILE_B + BTILE_B + so, Blo + gb);
    }
    CP_COMMIT();
}

template <bool CHEAD>
__global__ void __launch_bounds__(512, 1) mma_gemm(
    const __nv_bfloat16* __restrict__ Ahi_base, const __nv_bfloat16* __restrict__ Alo_base,
    const __nv_bfloat16* __restrict__ Bhi_base, const __nv_bfloat16* __restrict__ Blo_base,
    const float* b0, const float* b1, const float* b2,
    float* C0, float* C1, float* C2,
    __nv_bfloat16* FHhi, __nv_bfloat16* FHlo) {
    extern __shared__ __align__(128) char smem[];
    const uint32_t sbase = (uint32_t)__cvta_generic_to_shared(smem);
    const int tid = threadIdx.x, wid = tid >> 5, lane = tid & 31;
    const int z = blockIdx.z;
    const __nv_bfloat16* Ahi = Ahi_base + (size_t)z * MROWS * DIMC;
    const __nv_bfloat16* Alo = Alo_base + (size_t)z * MROWS * DIMC;
    const __nv_bfloat16* Bhi = Bhi_base + (size_t)z * DIMC * DIMC;
    const __nv_bfloat16* Blo = Blo_base + (size_t)z * DIMC * DIMC;
    const float* bias = (z == 0) ? b0 : (z == 1) ? b1 : b2;
    float* C = (z == 0) ? C0 : (z == 1) ? C1 : C2;
    const int bm = blockIdx.y * 128;
    const int bn = blockIdx.x * 256;
    const int wr = wid >> 2;          // 0..3 -> m offset 32*wr
    const int wc = wid & 3;           // 0..3 -> n offset 64*wc

    float acc[2][8][4];
#pragma unroll
    for (int i = 0; i < 2; i++)
#pragma unroll
        for (int j = 0; j < 8; j++)
#pragma unroll
            for (int t = 0; t < 4; t++) acc[i][j][t] = 0.f;

    const int a_r = wr * 32 + (lane & 15);
    const uint32_t a_off0 = (uint32_t)(a_r * 80 + ((lane >> 4) << 4));
    const int b_n = wc * 64 + (lane & 7) + ((lane >> 4) << 3);
    const uint32_t b_off0 = (uint32_t)(b_n * 80 + (((lane >> 3) & 1) << 4));

    load_stage(sbase, Ahi, Alo, Bhi, Blo, bm, bn, 0, tid);
    load_stage(sbase + STAGE_B, Ahi, Alo, Bhi, Blo, bm, bn, 32, tid);

    for (int i = 0; i < 32; i++) {
        if (i < 31) { CP_WAIT(1); } else { CP_WAIT(0); }
        __syncthreads();   // stage i%3 ready for everyone; stage (i+2)%3 free
        if (i + 2 < 32)
            load_stage(sbase + (uint32_t)((i + 2) % 3) * STAGE_B,
                       Ahi, Alo, Bhi, Blo, bm, bn, (i + 2) * 32, tid);
        const uint32_t st = sbase + (uint32_t)(i % 3) * STAGE_B;
#pragma unroll
        for (int h = 0; h < 2; h++) {
            const uint32_t hb = (uint32_t)(h * 32);
            uint32_t ah[2][4], al[2][4];
#pragma unroll
            for (int mf = 0; mf < 2; mf++) {
                const uint32_t ao = a_off0 + hb + (uint32_t)(mf * 16 * 80);
                ldmx4(ah[mf], st + ao);
                ldmx4(al[mf], st + ATILE_B + ao);
            }
            uint32_t bh[8][2], bl[8][2];
#pragma unroll
            for (int nf2 = 0; nf2 < 4; nf2++) {
                const uint32_t bo = b_off0 + hb + (uint32_t)(nf2 * 16 * 80);
                uint32_t r4[4];
                ldmx4(r4, st + 2 * ATILE_B + bo);
                bh[nf2 * 2][0] = r4[0]; bh[nf2 * 2][1] = r4[1];
                bh[nf2 * 2 + 1][0] = r4[2]; bh[nf2 * 2 + 1][1] = r4[3];
                ldmx4(r4, st + 2 * ATILE_B + BTILE_B + bo);
                bl[nf2 * 2][0] = r4[0]; bl[nf2 * 2][1] = r4[1];
                bl[nf2 * 2 + 1][0] = r4[2]; bl[nf2 * 2 + 1][1] = r4[3];
            }
#pragma unroll
            for (int mf = 0; mf < 2; mf++)
#pragma unroll
                for (int nf = 0; nf < 8; nf++) {
                    mma16816(acc[mf][nf], ah[mf], bh[nf]);
                    mma16816(acc[mf][nf], ah[mf], bl[nf]);
                    mma16816(acc[mf][nf], al[mf], bh[nf]);
                }
        }
    }

    const int lr = lane >> 2, lc = (lane & 3) * 2;
#pragma unroll
    for (int mf = 0; mf < 2; mf++) {
#pragma unroll
        for (int nf = 0; nf < 8; nf++) {
            const int col = bn + wc * 64 + nf * 8 + lc;
            const float bx = bias[col], by = bias[col + 1];
            const int r0 = bm + wr * 32 + mf * 16 + lr;
#pragma unroll
            for (int half = 0; half < 2; half++) {
                const int r = r0 + half * 8;
                const float a = acc[mf][nf][half * 2 + 0] + bx;
                const float c2 = acc[mf][nf][half * 2 + 1] + by;
                if (CHEAD) {
                    const int b = r >> 11, n = r & (NSEQ - 1);
                    const int hh = col >> 6, d0 = col & 63;
                    const size_t hoff = (((size_t)(b * NHEADS + hh) * NSEQ + n) << 6) + d0;
                    if (z == 0) {
                        const float sa = a * 0.125f, sb = c2 * 0.125f;
                        const __nv_bfloat162 h2 = __floats2bfloat162_rn(sa, sb);
                        const float2 f = __bfloat1622float2(h2);
                        const __nv_bfloat162 l2 = __floats2bfloat162_rn(sa - f.x, sb - f.y);
                        *reinterpret_cast<__nv_bfloat162*>(FHhi + hoff) = h2;
                        *reinterpret_cast<__nv_bfloat162*>(FHlo + hoff) = l2;
                    } else if (z == 1) {
                        float2 o; o.x = a; o.y = c2;
                        *reinterpret_cast<float2*>(C + hoff) = o;
                        const __nv_bfloat162 h2 = __floats2bfloat162_rn(a, c2);
                        const float2 f = __bfloat1622float2(h2);
                        const __nv_bfloat162 l2 = __floats2bfloat162_rn(a - f.x, c2 - f.y);
                        *reinterpret_cast<__nv_bfloat162*>(FHhi + SLOT + hoff) = h2;
                        *reinterpret_cast<__nv_bfloat162*>(FHlo + SLOT + hoff) = l2;
                    } else {
                        float2 o; o.x = a; o.y = c2;
                        *reinterpret_cast<float2*>(C + hoff) = o;
                        const __nv_bfloat16 ha = __float2bfloat16(a);
                        const __nv_bfloat16 hb2 = __float2bfloat16(c2);
                        const __nv_bfloat16 la = __float2bfloat16(a - __bfloat162float(ha));
                        const __nv_bfloat16 lb = __float2bfloat16(c2 - __bfloat162float(hb2));
                        const size_t tb = ((size_t)(b * NHEADS + hh) * HD + d0) * NSEQ + n;
                        FHhi[2 * SLOT + tb] = ha;
                        FHhi[2 * SLOT + tb + NSEQ] = hb2;
                        FHlo[2 * SLOT + tb] = la;
                        FHlo[2 * SLOT + tb + NSEQ] = lb;
                    }
                } else {
                    float2 o; o.x = a; o.y = c2;
                    *reinterpret_cast<float2*>(C + (size_t)r * DIMC + col) = o;
                }
            }
        }
    }
}

// ---------------------------------------------------------------------------
// Flash attention, split-KV: 512 threads = 2 independent warp-groups of 8.
// Group g handles K-tiles [16g, 16g+16) for the SAME 128 Q-rows, with its own
// KV double-buffer and named barrier. Exact fp32 (m,l,o) merge in smem at end.
// ---------------------------------------------------------------------------
#define FPITCH  144
#define FQT_B   (128 * FPITCH)           // 18432 per Q tile (hi or lo)
#define FQ2_B   (2 * FQT_B)              // 36864
#define FT_B    (64 * FPITCH)            // 9216 per K/V tile
#define FSTG_B  (4 * FT_B)               // 36864 per stage
#define FGRP_B  (2 * FSTG_B)             // 73728 per group (double buffer)
#define FLASH_SMEM (FQ2_B + 2 * FGRP_B)  // 184320
#define MERGE_OFF (FQ2_B + FGRP_B)       // merge buffers overlay group-1 region
#define OBUF_STRIDE 68                   // floats per row (padded)

__device__ __forceinline__ void load_kv(uint32_t st,
                                        const __nv_bfloat16* khi, const __nv_bfloat16* klo,
                                        const __nv_bfloat16* vthi, const __nv_bfloat16* vtlo,
                                        int bh, int kt, int gtid) {
#pragma unroll
    for (int it = 0; it < 2; it++) {
        const int idx = gtid + it * 256;           // 64 rows x 8 segs = 512
        const int row = idx >> 3, seg = idx & 7;
        const uint32_t so = (uint32_t)(row * FPITCH + seg * 16);
        const size_t gk = (size_t)bh * NSEQ * HD + (size_t)(kt * 64 + row) * HD + seg * 8;
        const size_t gv = ((size_t)bh * HD + row) * NSEQ + kt * 64 + seg * 8;
        cp16(st + 0 * FT_B + so, khi + gk);
        cp16(st + 1 * FT_B + so, klo + gk);
        cp16(st + 2 * FT_B + so, vthi + gv);
        cp16(st + 3 * FT_B + so, vtlo + gv);
    }
    CP_COMMIT();
}

__global__ void __launch_bounds__(512, 1) flash_mma(
    const __nv_bfloat16* __restrict__ FHhi, const __nv_bfloat16* __restrict__ FHlo,
    __nv_bfloat16* __restrict__ Ohi, __nv_bfloat16* __restrict__ Olo) {
    extern __shared__ __align__(128) char smem[];
    const uint32_t sbase = (uint32_t)__cvta_generic_to_shared(smem);
    const int tid = threadIdx.x, wid = tid >> 5, lane = tid & 31;
    const int g = wid >> 3;           // warp group 0/1
    const int gw = wid & 7;           // warp within group
    const int gtid = tid & 255;
    const int bh = blockIdx.y;
    const int q0 = blockIdx.x * 128;

    const __nv_bfloat16* qhi = FHhi;
    const __nv_bfloat16* qlo = FHlo;
    const __nv_bfloat16* khi = FHhi + SLOT;
    const __nv_bfloat16* klo = FHlo + SLOT;
    const __nv_bfloat16* vthi = FHhi + 2 * SLOT;
    const __nv_bfloat16* vtlo = FHlo + 2 * SLOT;

    // Q tiles -> smem (128 rows x 8 segs, hi + lo), all 512 threads
#pragma unroll
    for (int it = 0; it < 2; it++) {
        const int idx = tid + it * 512;
        const int row = idx >> 3, seg = idx & 7;
        const uint32_t so = (uint32_t)(row * FPITCH + seg * 16);
        const size_t gq = (size_t)bh * NSEQ * HD + (size_t)(q0 + row) * HD + seg * 8;
        cp16(sbase + so, qhi + gq);
        cp16(sbase + FQT_B + so, qlo + gq);
    }
    CP_COMMIT();

    const uint32_t stgbase = sbase + FQ2_B + (uint32_t)g * FGRP_B;
    const int kt0 = g * 16;
    load_kv(stgbase, khi, klo, vthi, vtlo, bh, kt0 + 0, gtid);
    load_kv(stgbase + FSTG_B, khi, klo, vthi, vtlo, bh, kt0 + 1, gtid);

    CP_WAIT(2);        // Q group complete (2 KV groups may remain in flight)
    __syncthreads();

    // Q fragments (A operand), 4 k16 frags, hi+lo
    uint32_t qfh[4][4], qfl[4][4];
    {
        const int a_r = gw * 16 + (lane & 15);
        const uint32_t a0 = (uint32_t)(a_r * FPITCH + ((lane >> 4) << 4));
#pragma unroll
        for (int kf = 0; kf < 4; kf++) {
            ldmx4(qfh[kf], sbase + a0 + kf * 32);
            ldmx4(qfl[kf], sbase + FQT_B + a0 + kf * 32);
        }
    }

    const uint32_t b_off0 =
        (uint32_t)(((lane & 7) + ((lane >> 4) << 3)) * FPITCH + (((lane >> 3) & 1) << 4));
    const int barid = 1 + g;

    float o[8][4];
#pragma unroll
    for (int nf = 0; nf < 8; nf++)
#pragma unroll
        for (int t = 0; t < 4; t++) o[nf][t] = 0.f;
    float mA = -1e30f, mB = -1e30f, lA = 0.f, lB = 0.f;

    for (int t = 0; t < 16; t++) {
        if (t < 15) { CP_WAIT(1); } else { CP_WAIT(0); }
        BAR_SYNC(barid, 256);
        const uint32_t st = stgbase + (uint32_t)(t & 1) * FSTG_B;

        // ---- S = Q K^T (Q pre-scaled by 0.125) ----
        float s[8][4];
#pragma unroll
        for (int nf = 0; nf < 8; nf++)
#pragma unroll
            for (int tt = 0; tt < 4; tt++) s[nf][tt] = 0.f;
#pragma unroll
        for (int kf = 0; kf < 4; kf++) {
#pragma unroll
            for (int nf2 = 0; nf2 < 4; nf2++) {
                const uint32_t bo = b_off0 + (uint32_t)(nf2 * 16 * FPITCH) + kf * 32;
                uint32_t kh4[4], kl4[4];
                ldmx4(kh4, st + 0 * FT_B + bo);
                ldmx4(kl4, st + 1 * FT_B + bo);
                mma16816(s[nf2 * 2], qfh[kf], &kh4[0]);
                mma16816(s[nf2 * 2], qfh[kf], &kl4[0]);
                mma16816(s[nf2 * 2], qfl[kf], &kh4[0]);
                mma16816(s[nf2 * 2 + 1], qfh[kf], &kh4[2]);
                mma16816(s[nf2 * 2 + 1], qfh[kf], &kl4[2]);
                mma16816(s[nf2 * 2 + 1], qfl[kf], &kh4[2]);
            }
        }

        // ---- online softmax (rows rA = lane>>2, rB = rA+8) ----
        float rmA = -1e30f, rmB = -1e30f;
#pragma unroll
        for (int nf = 0; nf < 8; nf++) {
            rmA = fmaxf(rmA, fmaxf(s[nf][0], s[nf][1]));
            rmB = fmaxf(rmB, fmaxf(s[nf][2], s[nf][3]));
        }
        rmA = fmaxf(rmA, __shfl_xor_sync(0xffffffffu, rmA, 1, 4));
        rmA = fmaxf(rmA, __shfl_xor_sync(0xffffffffu, rmA, 2, 4));
        rmB = fmaxf(rmB, __shfl_xor_sync(0xffffffffu, rmB, 1, 4));
        rmB = fmaxf(rmB, __shfl_xor_sync(0xffffffffu, rmB, 2, 4));
        const float mnA = fmaxf(mA, rmA);
        const float mnB = fmaxf(mB, rmB);
        const float cA = __expf(mA - mnA);
        const float cB = __expf(mB - mnB);
        mA = mnA; mB = mnB;
        float sumA = 0.f, sumB = 0.f;
#pragma unroll
        for (int nf = 0; nf < 8; nf++) {
            s[nf][0] = __expf(s[nf][0] - mnA);
            s[nf][1] = __expf(s[nf][1] - mnA);
            s[nf][2] = __expf(s[nf][2] - mnB);
            s[nf][3] = __expf(s[nf][3] - mnB);
            sumA += s[nf][0] + s[nf][1];
            sumB += s[nf][2] + s[nf][3];
        }
        sumA += __shfl_xor_sync(0xffffffffu, sumA, 1, 4);
        sumA += __shfl_xor_sync(0xffffffffu, sumA, 2, 4);
        sumB += __shfl_xor_sync(0xffffffffu, sumB, 1, 4);
        sumB += __shfl_xor_sync(0xffffffffu, sumB, 2, 4);
        lA = lA * cA + sumA;
        lB = lB * cB + sumB;
#pragma unroll
        for (int nf = 0; nf < 8; nf++) {
            o[nf][0] *= cA; o[nf][1] *= cA;
            o[nf][2] *= cB; o[nf][3] *= cB;
        }

        // ---- O += P V^T (register repack C-frag -> A-frag, hi/lo split) ----
#pragma unroll
        for (int kf = 0; kf < 4; kf++) {
            uint32_t pah[4], pal[4];
#pragma unroll
            for (int blk = 0; blk < 2; blk++) {
                const float p0 = s[2 * kf + blk][0], p1 = s[2 * kf + blk][1];
                const float p2 = s[2 * kf + blk][2], p3 = s[2 * kf + blk][3];
                const __nv_bfloat162 h01 = __floats2bfloat162_rn(p0, p1);
                const __nv_bfloat162 h23 = __floats2bfloat162_rn(p2, p3);
                const float2 f01 = __bfloat1622float2(h01);
                const float2 f23 = __bfloat1622float2(h23);
                pah[blk * 2 + 0] = *reinterpret_cast<const uint32_t*>(&h01);
                pah[blk * 2 + 1] = *reinterpret_cast<const uint32_t*>(&h23);
                pal[blk * 2 + 0] = pack_bf16x2(p0 - f01.x, p1 - f01.y);
                pal[blk * 2 + 1] = pack_bf16x2(p2 - f23.x, p3 - f23.y);
            }
#pragma unroll
            for (int nf2 = 0; nf2 < 4; nf2++) {
                const uint32_t bo = b_off0 + (uint32_t)(nf2 * 16 * FPITCH) + kf * 32;
                uint32_t vh4[4], vl4[4];
                ldmx4(vh4, st + 2 * FT_B + bo);
                ldmx4(vl4, st + 3 * FT_B + bo);
                mma16816(o[nf2 * 2], pah, &vh4[0]);
                mma16816(o[nf2 * 2], pah, &vl4[0]);
                mma16816(o[nf2 * 2], pal, &vh4[0]);
                mma16816(o[nf2 * 2 + 1], pah, &vh4[2]);
                mma16816(o[nf2 * 2 + 1], pah, &vl4[2]);
                mma16816(o[nf2 * 2 + 1], pal, &vh4[2]);
            }
        }

        BAR_SYNC(barid, 256);    // group done reading stage t&1
        if (t + 2 < 16)
            load_kv(st, khi, klo, vthi, vtlo, bh, kt0 + t + 2, gtid);
    }

    // ---- merge the two KV-halves (exact fp32) ----
    float* mbuf = reinterpret_cast<float*>(smem + MERGE_OFF);            // 128
    float* lbuf = reinterpret_cast<float*>(smem + MERGE_OFF + 512);      // 128
    float* obuf = reinterpret_cast<float*>(smem + MERGE_OFF + 1024);     // 128 x 68
    const int lr = gw * 16 + (lane >> 2);     // local row 0..127 (rA)
    if (g == 1) {
        if ((lane & 3) == 0) {
            mbuf[lr] = mA; lbuf[lr] = lA;
            mbuf[lr + 8] = mB; lbuf[lr + 8] = lB;
        }
#pragma unroll
        for (int nf = 0; nf < 8; nf++) {
            const int col = nf * 8 + (lane & 3) * 2;
            float2 pa; pa.x = o[nf][0]; pa.y = o[nf][1];
            float2 pb; pb.x = o[nf][2]; pb.y = o[nf][3];
            *reinterpret_cast<float2*>(&obuf[lr * OBUF_STRIDE + col]) = pa;
            *reinterpret_cast<float2*>(&obuf[(lr + 8) * OBUF_STRIDE + col]) = pb;
        }
    }
    __syncthreads();
    if (g == 0) {
        const float m1A = mbuf[lr], l1A = lbuf[lr];
        const float m1B = mbuf[lr + 8], l1B = lbuf[lr + 8];
        const float mfA = fmaxf(mA, m1A);
        const float mfB = fmaxf(mB, m1B);
        const float e0A = __expf(mA - mfA), e1A = __expf(m1A - mfA);
        const float e0B = __expf(mB - mfB), e1B = __expf(m1B - mfB);
        const float invA = 1.0f / (lA * e0A + l1A * e1A);
        const float invB = 1.0f / (lB * e0B + l1B * e1B);
        const int b = bh >> 4, h = bh & 15;
        const int rA = q0 + lr;
        const int rB = rA + 8;
        const size_t baseA = ((size_t)(b * NSEQ + rA)) * DIMC + h * 64;
        const size_t baseB = ((size_t)(b * NSEQ + rB)) * DIMC + h * 64;
#pragma unroll
        for (int nf = 0; nf < 8; nf++) {
            const int col = nf * 8 + (lane & 3) * 2;
            const float2 p1A = *reinterpret_cast<const float2*>(&obuf[lr * OBUF_STRIDE + col]);
            const float2 p1B =
                *reinterpret_cast<const float2*>(&obuf[(lr + 8) * OBUF_STRIDE + col]);
            const float a0 = (o[nf][0] * e0A + p1A.x * e1A) * invA;
            const float a1 = (o[nf][1] * e0A + p1A.y * e1A) * invA;
            const float b0 = (o[nf][2] * e0B + p1B.x * e1B) * invB;
            const float b1 = (o[nf][3] * e0B + p1B.y * e1B) * invB;
            const __nv_bfloat162 hA = __floats2bfloat162_rn(a0, a1);
            const float2 fA = __bfloat1622float2(hA);
            const __nv_bfloat162 lA2 = __floats2bfloat162_rn(a0 - fA.x, a1 - fA.y);
            const __nv_bfloat162 hB = __floats2bfloat162_rn(b0, b1);
            const float2 fB = __bfloat1622float2(hB);
            const __nv_bfloat162 lB2 = __floats2bfloat162_rn(b0 - fB.x, b1 - fB.y);
            *reinterpret_cast<__nv_bfloat162*>(Ohi + baseA + col) = hA;
            *reinterpret_cast<__nv_bfloat162*>(Olo + baseA + col) = lA2;
            *reinterpret_cast<__nv_bfloat162*>(Ohi + baseB + col) = hB;
            *reinterpret_cast<__nv_bfloat162*>(Olo + baseB + col) = lB2;
        }
    }
}

// ---------------------------------------------------------------------------
extern "C" void kernel_launch(void* const* d_in, const int* in_sizes, int n_in,
                              void* d_out, int out_size) {
    const float* q    = (const float*)d_in[0];
    const float* k    = (const float*)d_in[1];
    const float* v    = (const float*)d_in[2];
    const float* gq   = (const float*)d_in[3];
    const float* bqln = (const float*)d_in[4];
    const float* gk   = (const float*)d_in[5];
    const float* bkln = (const float*)d_in[6];
    const float* gv   = (const float*)d_in[7];
    const float* bvln = (const float*)d_in[8];
    const float* Wq   = (const float*)d_in[9];
    const float* bq   = (const float*)d_in[10];
    const float* Wk   = (const float*)d_in[11];
    const float* bk   = (const float*)d_in[12];
    const float* Wv   = (const float*)d_in[13];
    const float* bv   = (const float*)d_in[14];
    const float* Wp   = (const float*)d_in[15];
    const float* bp   = (const float*)d_in[16];

    float* out = (float*)d_out;
    float* kh  = out + (size_t)MROWS * DIMC;
    float* vh  = kh + (size_t)MROWS * DIMC;

    __nv_bfloat16 *lnhi, *lnlo, *wthi, *wtlo, *fhhi, *fhlo, *oshi, *oslo;
    float* dummy;
    cudaGetSymbolAddress((void**)&lnhi, g_ln_hi);
    cudaGetSymbolAddress((void**)&lnlo, g_ln_lo);
    cudaGetSymbolAddress((void**)&wthi, g_wt_hi);
    cudaGetSymbolAddress((void**)&wtlo, g_wt_lo);
    cudaGetSymbolAddress((void**)&fhhi, g_fh_hi);
    cudaGetSymbolAddress((void**)&fhlo, g_fh_lo);
    cudaGetSymbolAddress((void**)&oshi, g_os_hi);
    cudaGetSymbolAddress((void**)&oslo, g_os_lo);
    cudaGetSymbolAddress((void**)&dummy, g_dummy);

    // 1) Fused LayerNorm + split (q/k/v in one launch)
    ln_split_fused<<<dim3(MROWS, 3), 256>>>(q, k, v, gq, bqln, gk, bkln, gv, bvln,
                                            lnhi, lnlo);

    // 2) Weight transpose + split
    wsplit_kernel<<<dim3(32, 32, 4), dim3(32, 8)>>>(Wq, Wk, Wv, Wp, wthi, wtlo);

    // 3) QKV projection (tensor cores), emits flash-ready bf16 hi/lo
    cudaFuncSetAttribute(mma_gemm<true>, cudaFuncAttributeMaxDynamicSharedMemorySize, GEMM_SMEM);
    cudaFuncSetAttribute(mma_gemm<false>, cudaFuncAttributeMaxDynamicSharedMemorySize, GEMM_SMEM);
    mma_gemm<true><<<dim3(4, 32, 3), 512, GEMM_SMEM>>>(
        lnhi, lnlo, wthi, wtlo, bq, bk, bv, dummy, kh, vh, fhhi, fhlo);

    // 4) Flash attention (split-KV, 2 warp groups) -> split bf16 row-major
    cudaFuncSetAttribute(flash_mma, cudaFuncAttributeMaxDynamicSharedMemorySize, FLASH_SMEM);
    flash_mma<<<dim3(NSEQ / 128, BHNUM), 512, FLASH_SMEM>>>(fhhi, fhlo, oshi, oslo);

    // 5) Output projection
    mma_gemm<false><<<dim3(4, 32, 1), 512, GEMM_SMEM>>>(
        oshi, oslo, wthi + 3ull * DIMC * DIMC, wtlo + 3ull * DIMC * DIMC,
        bp, bp, bp, out, out, out, fhhi, fhlo);
}

// round 14
// speedup vs baseline: 3.4104x; 1.1648x over previous
#include <cuda_runtime.h>
#include <cuda_bf16.h>
#include <cuda_fp16.h>
#include <cstdint>
#include <math.h>

#define DIMC   1024
#define NSEQ   2048
#define BATCH  2
#define NHEADS 16
#define HD     64
#define MROWS  (BATCH * NSEQ)     // 4096
#define BHNUM  (BATCH * NHEADS)   // 32
#define SLOT   ((size_t)BHNUM * NSEQ * HD)   // elements per q/k/v slot

// ---------------------------------------------------------------------------
// Scratch (static device globals — no runtime allocation allowed)
// ---------------------------------------------------------------------------
__device__ __nv_bfloat16 g_ln_hi[3ull * MROWS * DIMC];
__device__ __nv_bfloat16 g_ln_lo[3ull * MROWS * DIMC];
__device__ __nv_bfloat16 g_wt_hi[4ull * DIMC * DIMC];    // W transposed [N][K]
__device__ __nv_bfloat16 g_wt_lo[4ull * DIMC * DIMC];
__device__ __half g_fh_hi[3ull * SLOT];                  // q hi / k hi / vT hi (fp16)
__device__ __half g_fh_lo[3ull * SLOT];                  // q lo / (unused) / vT lo
__device__ __nv_bfloat16 g_os_hi[(size_t)MROWS * DIMC];  // flash out split (row-major)
__device__ __nv_bfloat16 g_os_lo[(size_t)MROWS * DIMC];
__device__ float g_dummy[(size_t)MROWS * DIMC];          // unused fp32 sink for z=0

// ---------------------------------------------------------------------------
// PTX helpers (baseline ISA only)
// ---------------------------------------------------------------------------
__device__ __forceinline__ void cp16(uint32_t s, const void* g) {
    asm volatile("cp.async.cg.shared.global [%0], [%1], 16;\n"
                 :: "r"(s), "l"(__cvta_generic_to_global(g)) : "memory");
}
#define CP_COMMIT() asm volatile("cp.async.commit_group;\n" ::: "memory")
#define CP_WAIT(n)  asm volatile("cp.async.wait_group %0;\n" :: "n"(n) : "memory")
#define BAR_SYNC(id, cnt) \
    asm volatile("bar.sync %0, %1;" :: "r"(id), "r"(cnt) : "memory")

__device__ __forceinline__ void ldmx4(uint32_t* r, uint32_t addr) {
    asm volatile("ldmatrix.sync.aligned.m8n8.x4.shared.b16 {%0,%1,%2,%3}, [%4];"
                 : "=r"(r[0]), "=r"(r[1]), "=r"(r[2]), "=r"(r[3]) : "r"(addr));
}

__device__ __forceinline__ void mma16816(float* c, const uint32_t* a, const uint32_t* b) {
    asm volatile("mma.sync.aligned.m16n8k16.row.col.f32.bf16.bf16.f32 "
                 "{%0,%1,%2,%3}, {%4,%5,%6,%7}, {%8,%9}, {%0,%1,%2,%3};"
                 : "+f"(c[0]), "+f"(c[1]), "+f"(c[2]), "+f"(c[3])
                 : "r"(a[0]), "r"(a[1]), "r"(a[2]), "r"(a[3]), "r"(b[0]), "r"(b[1]));
}

__device__ __forceinline__ void mma16816h(float* c, const uint32_t* a, const uint32_t* b) {
    asm volatile("mma.sync.aligned.m16n8k16.row.col.f32.f16.f16.f32 "
                 "{%0,%1,%2,%3}, {%4,%5,%6,%7}, {%8,%9}, {%0,%1,%2,%3};"
                 : "+f"(c[0]), "+f"(c[1]), "+f"(c[2]), "+f"(c[3])
                 : "r"(a[0]), "r"(a[1]), "r"(a[2]), "r"(a[3]), "r"(b[0]), "r"(b[1]));
}

__device__ __forceinline__ uint32_t pack_h2(float a, float b) {
    __half2 t = __floats2half2_rn(a, b);
    return *reinterpret_cast<uint32_t*>(&t);
}

// ---------------------------------------------------------------------------
// Fused LayerNorm + bf16 split for q/k/v (z = blockIdx.y)
// ---------------------------------------------------------------------------
__global__ void __launch_bounds__(256) ln_split_fused(
    const float* __restrict__ q, const float* __restrict__ k, const float* __restrict__ v,
    const float* __restrict__ gq, const float* __restrict__ bq,
    const float* __restrict__ gk, const float* __restrict__ bk,
    const float* __restrict__ gv, const float* __restrict__ bv,
    __nv_bfloat16* __restrict__ hi_base, __nv_bfloat16* __restrict__ lo_base) {
    const int z = blockIdx.y;
    const float* x = (z == 0) ? q : (z == 1) ? k : v;
    const float* g = (z == 0) ? gq : (z == 1) ? gk : gv;
    const float* b = (z == 0) ? bq : (z == 1) ? bk : bv;
    __nv_bfloat16* hi = hi_base + (size_t)z * MROWS * DIMC;
    __nv_bfloat16* lo = lo_base + (size_t)z * MROWS * DIMC;

    const int row = blockIdx.x;
    const int tid = threadIdx.x;
    const float4 vv = reinterpret_cast<const float4*>(x + (size_t)row * DIMC)[tid];
    float s  = vv.x + vv.y + vv.z + vv.w;
    float ss = vv.x * vv.x + vv.y * vv.y + vv.z * vv.z + vv.w * vv.w;
#pragma unroll
    for (int off = 16; off > 0; off >>= 1) {
        s  += __shfl_xor_sync(0xffffffffu, s, off);
        ss += __shfl_xor_sync(0xffffffffu, ss, off);
    }
    __shared__ float rs[8], rss[8];
    if ((tid & 31) == 0) { rs[tid >> 5] = s; rss[tid >> 5] = ss; }
    __syncthreads();
    float tot = 0.f, totss = 0.f;
#pragma unroll
    for (int i = 0; i < 8; i++) { tot += rs[i]; totss += rss[i]; }
    const float mean = tot * (1.0f / DIMC);
    const float var  = totss * (1.0f / DIMC) - mean * mean;
    const float rstd = rsqrtf(var + 1e-5f);
    const float4 g4 = reinterpret_cast<const float4*>(g)[tid];
    const float4 b4 = reinterpret_cast<const float4*>(b)[tid];
    float o[4];
    o[0] = (vv.x - mean) * rstd * g4.x + b4.x;
    o[1] = (vv.y - mean) * rstd * g4.y + b4.y;
    o[2] = (vv.z - mean) * rstd * g4.z + b4.z;
    o[3] = (vv.w - mean) * rstd * g4.w + b4.w;
    __nv_bfloat16 h[4], l[4];
#pragma unroll
    for (int i = 0; i < 4; i++) {
        h[i] = __float2bfloat16(o[i]);
        l[i] = __float2bfloat16(o[i] - __bfloat162float(h[i]));
    }
    __nv_bfloat162* H = reinterpret_cast<__nv_bfloat162*>(hi + (size_t)row * DIMC);
    __nv_bfloat162* L = reinterpret_cast<__nv_bfloat162*>(lo + (size_t)row * DIMC);
    H[tid * 2]     = __halves2bfloat162(h[0], h[1]);
    H[tid * 2 + 1] = __halves2bfloat162(h[2], h[3]);
    L[tid * 2]     = __halves2bfloat162(l[0], l[1]);
    L[tid * 2 + 1] = __halves2bfloat162(l[2], l[3]);
}

// ---------------------------------------------------------------------------
// Weight transpose + split
// ---------------------------------------------------------------------------
__global__ void __launch_bounds__(256) wsplit_kernel(const float* __restrict__ W0,
                                                     const float* __restrict__ W1,
                                                     const float* __restrict__ W2,
                                                     const float* __restrict__ W3,
                                                     __nv_bfloat16* __restrict__ hi,
                                                     __nv_bfloat16* __restrict__ lo) {
    const int z = blockIdx.z;
    const float* W = (z == 0) ? W0 : (z == 1) ? W1 : (z == 2) ? W2 : W3;
    const size_t ob = (size_t)z * DIMC * DIMC;
    __shared__ float t[32][33];
    const int tx = threadIdx.x, ty = threadIdx.y;
    const int n0 = blockIdx.x * 32, k0 = blockIdx.y * 32;
#pragma unroll
    for (int r = 0; r < 4; r++)
        t[ty + 8 * r][tx] = W[(size_t)(k0 + ty + 8 * r) * DIMC + n0 + tx];
    __syncthreads();
#pragma unroll
    for (int r = 0; r < 4; r++) {
        const float x = t[tx][ty + 8 * r];
        const __nv_bfloat16 h = __float2bfloat16(x);
        const __nv_bfloat16 l = __float2bfloat16(x - __bfloat162float(h));
        const size_t o = ob + (size_t)(n0 + ty + 8 * r) * DIMC + k0 + tx;
        hi[o] = h;
        lo[o] = l;
    }
}

// ---------------------------------------------------------------------------
// mma.sync bf16 GEMM, 3x split. Tile 128(M) x 256(N), BK=32, 512 threads,
// 16 warps (4x4), warp tile 32x64. 3-stage cp.async pipeline, ONE barrier/iter.
// CHEAD epilogue emits fp16 hi/lo for flash (q scaled / k hi-only / v transp).
// ---------------------------------------------------------------------------
#define ATILE_B (128 * 80)           // 10240
#define BTILE_B (256 * 80)           // 20480
#define STAGE_B (2 * ATILE_B + 2 * BTILE_B)   // 61440
#define GEMM_SMEM (3 * STAGE_B)               // 184320

__device__ __forceinline__ void load_stage(uint32_t st,
                                           const __nv_bfloat16* Ahi, const __nv_bfloat16* Alo,
                                           const __nv_bfloat16* Bhi, const __nv_bfloat16* Blo,
                                           int bm, int bn, int k0, int tid) {
    {                                            // A: 128 rows x 4 segs = 512
        const int row = tid >> 2, seg = tid & 3;
        const uint32_t so = (uint32_t)(row * 80 + seg * 16);
        const size_t ga = (size_t)(bm + row) * DIMC + k0 + seg * 8;
        cp16(st + so, Ahi + ga);
        cp16(st + ATILE_B + so, Alo + ga);
    }
#pragma unroll
    for (int it = 0; it < 2; it++) {             // B: 256 rows x 4 segs = 1024
        const int idx = tid + it * 512;
        const int row = idx >> 2, seg = idx & 3;
        const uint32_t so = (uint32_t)(row * 80 + seg * 16);
        const size_t gb = (size_t)(bn + row) * DIMC + k0 + seg * 8;
        cp16(st + 2 * ATILE_B + so, Bhi + gb);
        cp16(st + 2 * ATILE_B + BTILE_B + so, Blo + gb);
    }
    CP_COMMIT();
}

template <bool CHEAD>
__global__ void __launch_bounds__(512, 1) mma_gemm(
    const __nv_bfloat16* __restrict__ Ahi_base, const __nv_bfloat16* __restrict__ Alo_base,
    const __nv_bfloat16* __restrict__ Bhi_base, const __nv_bfloat16* __restrict__ Blo_base,
    const float* b0, const float* b1, const float* b2,
    float* C0, float* C1, float* C2,
    __half* FHhi, __half* FHlo) {
    extern __shared__ __align__(128) char smem[];
    const uint32_t sbase = (uint32_t)__cvta_generic_to_shared(smem);
    const int tid = threadIdx.x, wid = tid >> 5, lane = tid & 31;
    const int z = blockIdx.z;
    const __nv_bfloat16* Ahi = Ahi_base + (size_t)z * MROWS * DIMC;
    const __nv_bfloat16* Alo = Alo_base + (size_t)z * MROWS * DIMC;
    const __nv_bfloat16* Bhi = Bhi_base + (size_t)z * DIMC * DIMC;
    const __nv_bfloat16* Blo = Blo_base + (size_t)z * DIMC * DIMC;
    const float* bias = (z == 0) ? b0 : (z == 1) ? b1 : b2;
    float* C = (z == 0) ? C0 : (z == 1) ? C1 : C2;
    const int bm = blockIdx.y * 128;
    const int bn = blockIdx.x * 256;
    const int wr = wid >> 2;          // 0..3 -> m offset 32*wr
    const int wc = wid & 3;           // 0..3 -> n offset 64*wc

    float acc[2][8][4];
#pragma unroll
    for (int i = 0; i < 2; i++)
#pragma unroll
        for (int j = 0; j < 8; j++)
#pragma unroll
            for (int t = 0; t < 4; t++) acc[i][j][t] = 0.f;

    const int a_r = wr * 32 + (lane & 15);
    const uint32_t a_off0 = (uint32_t)(a_r * 80 + ((lane >> 4) << 4));
    const int b_n = wc * 64 + (lane & 7) + ((lane >> 4) << 3);
    const uint32_t b_off0 = (uint32_t)(b_n * 80 + (((lane >> 3) & 1) << 4));

    load_stage(sbase, Ahi, Alo, Bhi, Blo, bm, bn, 0, tid);
    load_stage(sbase + STAGE_B, Ahi, Alo, Bhi, Blo, bm, bn, 32, tid);

    for (int i = 0; i < 32; i++) {
        if (i < 31) { CP_WAIT(1); } else { CP_WAIT(0); }
        __syncthreads();   // stage i%3 ready for everyone; stage (i+2)%3 free
        if (i + 2 < 32)
            load_stage(sbase + (uint32_t)((i + 2) % 3) * STAGE_B,
                       Ahi, Alo, Bhi, Blo, bm, bn, (i + 2) * 32, tid);
        const uint32_t st = sbase + (uint32_t)(i % 3) * STAGE_B;
#pragma unroll
        for (int h = 0; h < 2; h++) {
            const uint32_t hb = (uint32_t)(h * 32);
            uint32_t ah[2][4], al[2][4];
#pragma unroll
            for (int mf = 0; mf < 2; mf++) {
                const uint32_t ao = a_off0 + hb + (uint32_t)(mf * 16 * 80);
                ldmx4(ah[mf], st + ao);
                ldmx4(al[mf], st + ATILE_B + ao);
            }
            uint32_t bh[8][2], bl[8][2];
#pragma unroll
            for (int nf2 = 0; nf2 < 4; nf2++) {
                const uint32_t bo = b_off0 + hb + (uint32_t)(nf2 * 16 * 80);
                uint32_t r4[4];
                ldmx4(r4, st + 2 * ATILE_B + bo);
                bh[nf2 * 2][0] = r4[0]; bh[nf2 * 2][1] = r4[1];
                bh[nf2 * 2 + 1][0] = r4[2]; bh[nf2 * 2 + 1][1] = r4[3];
                ldmx4(r4, st + 2 * ATILE_B + BTILE_B + bo);
                bl[nf2 * 2][0] = r4[0]; bl[nf2 * 2][1] = r4[1];
                bl[nf2 * 2 + 1][0] = r4[2]; bl[nf2 * 2 + 1][1] = r4[3];
            }
#pragma unroll
            for (int mf = 0; mf < 2; mf++)
#pragma unroll
                for (int nf = 0; nf < 8; nf++) {
                    mma16816(acc[mf][nf], ah[mf], bh[nf]);
                    mma16816(acc[mf][nf], ah[mf], bl[nf]);
                    mma16816(acc[mf][nf], al[mf], bh[nf]);
                }
        }
    }

    const int lr = lane >> 2, lc = (lane & 3) * 2;
#pragma unroll
    for (int mf = 0; mf < 2; mf++) {
#pragma unroll
        for (int nf = 0; nf < 8; nf++) {
            const int col = bn + wc * 64 + nf * 8 + lc;
            const float bx = bias[col], by = bias[col + 1];
            const int r0 = bm + wr * 32 + mf * 16 + lr;
#pragma unroll
            for (int half = 0; half < 2; half++) {
                const int r = r0 + half * 8;
                const float a = acc[mf][nf][half * 2 + 0] + bx;
                const float c2 = acc[mf][nf][half * 2 + 1] + by;
                if (CHEAD) {
                    const int b = r >> 11, n = r & (NSEQ - 1);
                    const int hh = col >> 6, d0 = col & 63;
                    const size_t hoff = (((size_t)(b * NHEADS + hh) * NSEQ + n) << 6) + d0;
                    if (z == 0) {
                        // q: fp16 hi/lo, pre-scaled by 0.125
                        const float sa = a * 0.125f, sb = c2 * 0.125f;
                        const __half2 h2 = __floats2half2_rn(sa, sb);
                        const float2 f = __half22float2(h2);
                        const __half2 l2 = __floats2half2_rn(sa - f.x, sb - f.y);
                        *reinterpret_cast<__half2*>(FHhi + hoff) = h2;
                        *reinterpret_cast<__half2*>(FHlo + hoff) = l2;
                    } else if (z == 1) {
                        // k: fp32 output + fp16 hi only
                        float2 o; o.x = a; o.y = c2;
                        *reinterpret_cast<float2*>(C + hoff) = o;
                        *reinterpret_cast<__half2*>(FHhi + SLOT + hoff) =
                            __floats2half2_rn(a, c2);
                    } else {
                        // v: fp32 output + transposed fp16 hi/lo
                        float2 o; o.x = a; o.y = c2;
                        *reinterpret_cast<float2*>(C + hoff) = o;
                        const __half ha = __float2half_rn(a);
                        const __half hb2 = __float2half_rn(c2);
                        const __half la = __float2half_rn(a - __half2float(ha));
                        const __half lb = __float2half_rn(c2 - __half2float(hb2));
                        const size_t tb = ((size_t)(b * NHEADS + hh) * HD + d0) * NSEQ + n;
                        FHhi[2 * SLOT + tb] = ha;
                        FHhi[2 * SLOT + tb + NSEQ] = hb2;
                        FHlo[2 * SLOT + tb] = la;
                        FHlo[2 * SLOT + tb + NSEQ] = lb;
                    }
                } else {
                    float2 o; o.x = a; o.y = c2;
                    *reinterpret_cast<float2*>(C + (size_t)r * DIMC + col) = o;
                }
            }
        }
    }
}

// ---------------------------------------------------------------------------
// Flash attention, fp16 2-term splits, split-KV (2 warp-groups of 8).
// S = (Qhi+Qlo)·Khi  (K single-fp16);  O += Phi·(Vhi+Vlo)  (P single-fp16).
// Group g handles K-tiles [16g,16g+16) for the same 128 Q-rows, own KV
// double-buffer + named barrier. Exact fp32 (m,l,o) merge in smem at end.
// ---------------------------------------------------------------------------
#define FPITCH  144
#define FQT_B   (128 * FPITCH)           // 18432 per Q tile (hi or lo)
#define FQ2_B   (2 * FQT_B)              // 36864
#define FT_B    (64 * FPITCH)            // 9216 per K/V tile
#define FSTG_B  (3 * FT_B)               // 27648 per stage (Kh, Vh, Vl)
#define FGRP_B  (2 * FSTG_B)             // 55296 per group (double buffer)
#define FLASH_SMEM (FQ2_B + 2 * FGRP_B)  // 147456
#define MERGE_OFF (FQ2_B + FGRP_B)       // merge buffers overlay group-1 region
#define OBUF_STRIDE 68                   // floats per row (padded)

__device__ __forceinline__ void load_kv(uint32_t st,
                                        const __half* khi,
                                        const __half* vthi, const __half* vtlo,
                                        int bh, int kt, int gtid) {
#pragma unroll
    for (int it = 0; it < 2; it++) {
        const int idx = gtid + it * 256;           // 64 rows x 8 segs = 512
        const int row = idx >> 3, seg = idx & 7;
        const uint32_t so = (uint32_t)(row * FPITCH + seg * 16);
        const size_t gk = (size_t)bh * NSEQ * HD + (size_t)(kt * 64 + row) * HD + seg * 8;
        const size_t gv = ((size_t)bh * HD + row) * NSEQ + kt * 64 + seg * 8;
        cp16(st + 0 * FT_B + so, khi + gk);
        cp16(st + 1 * FT_B + so, vthi + gv);
        cp16(st + 2 * FT_B + so, vtlo + gv);
    }
    CP_COMMIT();
}

__global__ void __launch_bounds__(512, 1) flash_mma(
    const __half* __restrict__ FHhi, const __half* __restrict__ FHlo,
    __nv_bfloat16* __restrict__ Ohi, __nv_bfloat16* __restrict__ Olo) {
    extern __shared__ __align__(128) char smem[];
    const uint32_t sbase = (uint32_t)__cvta_generic_to_shared(smem);
    const int tid = threadIdx.x, wid = tid >> 5, lane = tid & 31;
    const int g = wid >> 3;           // warp group 0/1
    const int gw = wid & 7;           // warp within group
    const int gtid = tid & 255;
    const int bh = blockIdx.y;
    const int q0 = blockIdx.x * 128;

    const __half* qhi = FHhi;
    const __half* qlo = FHlo;
    const __half* khi = FHhi + SLOT;
    const __half* vthi = FHhi + 2 * SLOT;
    const __half* vtlo = FHlo + 2 * SLOT;

    // Q tiles -> smem (128 rows x 8 segs, hi + lo), all 512 threads
#pragma unroll
    for (int it = 0; it < 2; it++) {
        const int idx = tid + it * 512;
        const int row = idx >> 3, seg = idx & 7;
        const uint32_t so = (uint32_t)(row * FPITCH + seg * 16);
        const size_t gq = (size_t)bh * NSEQ * HD + (size_t)(q0 + row) * HD + seg * 8;
        cp16(sbase + so, qhi + gq);
        cp16(sbase + FQT_B + so, qlo + gq);
    }
    CP_COMMIT();

    const uint32_t stgbase = sbase + FQ2_B + (uint32_t)g * FGRP_B;
    const int kt0 = g * 16;
    load_kv(stgbase, khi, vthi, vtlo, bh, kt0 + 0, gtid);
    load_kv(stgbase + FSTG_B, khi, vthi, vtlo, bh, kt0 + 1, gtid);

    CP_WAIT(2);        // Q group complete (2 KV groups may remain in flight)
    __syncthreads();

    // Q fragments (A operand), 4 k16 frags, hi+lo
    uint32_t qfh[4][4], qfl[4][4];
    {
        const int a_r = gw * 16 + (lane & 15);
        const uint32_t a0 = (uint32_t)(a_r * FPITCH + ((lane >> 4) << 4));
#pragma unroll
        for (int kf = 0; kf < 4; kf++) {
            ldmx4(qfh[kf], sbase + a0 + kf * 32);
            ldmx4(qfl[kf], sbase + FQT_B + a0 + kf * 32);
        }
    }

    const uint32_t b_off0 =
        (uint32_t)(((lane & 7) + ((lane >> 4) << 3)) * FPITCH + (((lane >> 3) & 1) << 4));
    const int barid = 1 + g;

    float o[8][4];
#pragma unroll
    for (int nf = 0; nf < 8; nf++)
#pragma unroll
        for (int t = 0; t < 4; t++) o[nf][t] = 0.f;
    float mA = -1e30f, mB = -1e30f, lA = 0.f, lB = 0.f;

    for (int t = 0; t < 16; t++) {
        if (t < 15) { CP_WAIT(1); } else { CP_WAIT(0); }
        BAR_SYNC(barid, 256);
        const uint32_t st = stgbase + (uint32_t)(t & 1) * FSTG_B;

        // ---- S = (Qhi + Qlo) · Khi ----
        float s[8][4];
#pragma unroll
        for (int nf = 0; nf < 8; nf++)
#pragma unroll
            for (int tt = 0; tt < 4; tt++) s[nf][tt] = 0.f;
#pragma unroll
        for (int kf = 0; kf < 4; kf++) {
#pragma unroll
            for (int nf2 = 0; nf2 < 4; nf2++) {
                const uint32_t bo = b_off0 + (uint32_t)(nf2 * 16 * FPITCH) + kf * 32;
                uint32_t kh4[4];
                ldmx4(kh4, st + 0 * FT_B + bo);
                mma16816h(s[nf2 * 2], qfh[kf], &kh4[0]);
                mma16816h(s[nf2 * 2], qfl[kf], &kh4[0]);
                mma16816h(s[nf2 * 2 + 1], qfh[kf], &kh4[2]);
                mma16816h(s[nf2 * 2 + 1], qfl[kf], &kh4[2]);
            }
        }

        // ---- online softmax (rows rA = lane>>2, rB = rA+8) ----
        float rmA = -1e30f, rmB = -1e30f;
#pragma unroll
        for (int nf = 0; nf < 8; nf++) {
            rmA = fmaxf(rmA, fmaxf(s[nf][0], s[nf][1]));
            rmB = fmaxf(rmB, fmaxf(s[nf][2], s[nf][3]));
        }
        rmA = fmaxf(rmA, __shfl_xor_sync(0xffffffffu, rmA, 1, 4));
        rmA = fmaxf(rmA, __shfl_xor_sync(0xffffffffu, rmA, 2, 4));
        rmB = fmaxf(rmB, __shfl_xor_sync(0xffffffffu, rmB, 1, 4));
        rmB = fmaxf(rmB, __shfl_xor_sync(0xffffffffu, rmB, 2, 4));
        const float mnA = fmaxf(mA, rmA);
        const float mnB = fmaxf(mB, rmB);
        const float cA = __expf(mA - mnA);
        const float cB = __expf(mB - mnB);
        mA = mnA; mB = mnB;
        float sumA = 0.f, sumB = 0.f;
#pragma unroll
        for (int nf = 0; nf < 8; nf++) {
            s[nf][0] = __expf(s[nf][0] - mnA);
            s[nf][1] = __expf(s[nf][1] - mnA);
            s[nf][2] = __expf(s[nf][2] - mnB);
            s[nf][3] = __expf(s[nf][3] - mnB);
            sumA += s[nf][0] + s[nf][1];
            sumB += s[nf][2] + s[nf][3];
        }
        sumA += __shfl_xor_sync(0xffffffffu, sumA, 1, 4);
        sumA += __shfl_xor_sync(0xffffffffu, sumA, 2, 4);
        sumB += __shfl_xor_sync(0xffffffffu, sumB, 1, 4);
        sumB += __shfl_xor_sync(0xffffffffu, sumB, 2, 4);
        lA = lA * cA + sumA;
        lB = lB * cB + sumB;
#pragma unroll
        for (int nf = 0; nf < 8; nf++) {
            o[nf][0] *= cA; o[nf][1] *= cA;
            o[nf][2] *= cB; o[nf][3] *= cB;
        }

        // ---- O += Phi · (Vhi + Vlo) (P single-fp16, register repack) ----
#pragma unroll
        for (int kf = 0; kf < 4; kf++) {
            uint32_t pah[4];
#pragma unroll
            for (int blk = 0; blk < 2; blk++) {
                pah[blk * 2 + 0] = pack_h2(s[2 * kf + blk][0], s[2 * kf + blk][1]);
                pah[blk * 2 + 1] = pack_h2(s[2 * kf + blk][2], s[2 * kf + blk][3]);
            }
#pragma unroll
            for (int nf2 = 0; nf2 < 4; nf2++) {
                const uint32_t bo = b_off0 + (uint32_t)(nf2 * 16 * FPITCH) + kf * 32;
                uint32_t vh4[4], vl4[4];
                ldmx4(vh4, st + 1 * FT_B + bo);
                ldmx4(vl4, st + 2 * FT_B + bo);
                mma16816h(o[nf2 * 2], pah, &vh4[0]);
                mma16816h(o[nf2 * 2], pah, &vl4[0]);
                mma16816h(o[nf2 * 2 + 1], pah, &vh4[2]);
                mma16816h(o[nf2 * 2 + 1], pah, &vl4[2]);
            }
        }

        BAR_SYNC(barid, 256);    // group done reading stage t&1
        if (t + 2 < 16)
            load_kv(st, khi, vthi, vtlo, bh, kt0 + t + 2, gtid);
    }

    // ---- merge the two KV-halves (exact fp32) ----
    float* mbuf = reinterpret_cast<float*>(smem + MERGE_OFF);            // 128
    float* lbuf = reinterpret_cast<float*>(smem + MERGE_OFF + 512);      // 128
    float* obuf = reinterpret_cast<float*>(smem + MERGE_OFF + 1024);     // 128 x 68
    const int lr = gw * 16 + (lane >> 2);     // local row 0..127 (rA)
    if (g == 1) {
        if ((lane & 3) == 0) {
            mbuf[lr] = mA; lbuf[lr] = lA;
            mbuf[lr + 8] = mB; lbuf[lr + 8] = lB;
        }
#pragma unroll
        for (int nf = 0; nf < 8; nf++) {
            const int col = nf * 8 + (lane & 3) * 2;
            float2 pa; pa.x = o[nf][0]; pa.y = o[nf][1];
            float2 pb; pb.x = o[nf][2]; pb.y = o[nf][3];
            *reinterpret_cast<float2*>(&obuf[lr * OBUF_STRIDE + col]) = pa;
            *reinterpret_cast<float2*>(&obuf[(lr + 8) * OBUF_STRIDE + col]) = pb;
        }
    }
    __syncthreads();
    if (g == 0) {
        const float m1A = mbuf[lr], l1A = lbuf[lr];
        const float m1B = mbuf[lr + 8], l1B = lbuf[lr + 8];
        const float mfA = fmaxf(mA, m1A);
        const float mfB = fmaxf(mB, m1B);
        const float e0A = __expf(mA - mfA), e1A = __expf(m1A - mfA);
        const float e0B = __expf(mB - mfB), e1B = __expf(m1B - mfB);
        const float invA = 1.0f / (lA * e0A + l1A * e1A);
        const float invB = 1.0f / (lB * e0B + l1B * e1B);
        const int b = bh >> 4, h = bh & 15;
        const int rA = q0 + lr;
        const int rB = rA + 8;
        const size_t baseA = ((size_t)(b * NSEQ + rA)) * DIMC + h * 64;
        const size_t baseB = ((size_t)(b * NSEQ + rB)) * DIMC + h * 64;
#pragma unroll
        for (int nf = 0; nf < 8; nf++) {
            const int col = nf * 8 + (lane & 3) * 2;
            const float2 p1A = *reinterpret_cast<const float2*>(&obuf[lr * OBUF_STRIDE + col]);
            const float2 p1B =
                *reinterpret_cast<const float2*>(&obuf[(lr + 8) * OBUF_STRIDE + col]);
            const float a0 = (o[nf][0] * e0A + p1A.x * e1A) * invA;
            const float a1 = (o[nf][1] * e0A + p1A.y * e1A) * invA;
            const float b0 = (o[nf][2] * e0B + p1B.x * e1B) * invB;
            const float b1 = (o[nf][3] * e0B + p1B.y * e1B) * invB;
            const __nv_bfloat162 hA = __floats2bfloat162_rn(a0, a1);
            const float2 fA = __bfloat1622float2(hA);
            const __nv_bfloat162 lA2 = __floats2bfloat162_rn(a0 - fA.x, a1 - fA.y);
            const __nv_bfloat162 hB = __floats2bfloat162_rn(b0, b1);
            const float2 fB = __bfloat1622float2(hB);
            const __nv_bfloat162 lB2 = __floats2bfloat162_rn(b0 - fB.x, b1 - fB.y);
            *reinterpret_cast<__nv_bfloat162*>(Ohi + baseA + col) = hA;
            *reinterpret_cast<__nv_bfloat162*>(Olo + baseA + col) = lA2;
            *reinterpret_cast<__nv_bfloat162*>(Ohi + baseB + col) = hB;
            *reinterpret_cast<__nv_bfloat162*>(Olo + baseB + col) = lB2;
        }
    }
}

// ---------------------------------------------------------------------------
extern "C" void kernel_launch(void* const* d_in, const int* in_sizes, int n_in,
                              void* d_out, int out_size) {
    const float* q    = (const float*)d_in[0];
    const float* k    = (const float*)d_in[1];
    const float* v    = (const float*)d_in[2];
    const float* gq   = (const float*)d_in[3];
    const float* bqln = (const float*)d_in[4];
    const float* gk   = (const float*)d_in[5];
    const float* bkln = (const float*)d_in[6];
    const float* gv   = (const float*)d_in[7];
    const float* bvln = (const float*)d_in[8];
    const float* Wq   = (const float*)d_in[9];
    const float* bq   = (const float*)d_in[10];
    const float* Wk   = (const float*)d_in[11];
    const float* bk   = (const float*)d_in[12];
    const float* Wv   = (const float*)d_in[13];
    const float* bv   = (const float*)d_in[14];
    const float* Wp   = (const float*)d_in[15];
    const float* bp   = (const float*)d_in[16];

    float* out = (float*)d_out;
    float* kh  = out + (size_t)MROWS * DIMC;
    float* vh  = kh + (size_t)MROWS * DIMC;

    __nv_bfloat16 *lnhi, *lnlo, *wthi, *wtlo, *oshi, *oslo;
    __half *fhhi, *fhlo;
    float* dummy;
    cudaGetSymbolAddress((void**)&lnhi, g_ln_hi);
    cudaGetSymbolAddress((void**)&lnlo, g_ln_lo);
    cudaGetSymbolAddress((void**)&wthi, g_wt_hi);
    cudaGetSymbolAddress((void**)&wtlo, g_wt_lo);
    cudaGetSymbolAddress((void**)&fhhi, g_fh_hi);
    cudaGetSymbolAddress((void**)&fhlo, g_fh_lo);
    cudaGetSymbolAddress((void**)&oshi, g_os_hi);
    cudaGetSymbolAddress((void**)&oslo, g_os_lo);
    cudaGetSymbolAddress((void**)&dummy, g_dummy);

    // 1) Fused LayerNorm + split (q/k/v in one launch)
    ln_split_fused<<<dim3(MROWS, 3), 256>>>(q, k, v, gq, bqln, gk, bkln, gv, bvln,
                                            lnhi, lnlo);

    // 2) Weight transpose + split
    wsplit_kernel<<<dim3(32, 32, 4), dim3(32, 8)>>>(Wq, Wk, Wv, Wp, wthi, wtlo);

    // 3) QKV projection (tensor cores), emits flash-ready fp16 hi/lo
    cudaFuncSetAttribute(mma_gemm<true>, cudaFuncAttributeMaxDynamicSharedMemorySize, GEMM_SMEM);
    cudaFuncSetAttribute(mma_gemm<false>, cudaFuncAttributeMaxDynamicSharedMemorySize, GEMM_SMEM);
    mma_gemm<true><<<dim3(4, 32, 3), 512, GEMM_SMEM>>>(
        lnhi, lnlo, wthi, wtlo, bq, bk, bv, dummy, kh, vh, fhhi, fhlo);

    // 4) Flash attention (fp16 2-term, split-KV) -> split bf16 row-major
    cudaFuncSetAttribute(flash_mma, cudaFuncAttributeMaxDynamicSharedMemorySize, FLASH_SMEM);
    flash_mma<<<dim3(NSEQ / 128, BHNUM), 512, FLASH_SMEM>>>(fhhi, fhlo, oshi, oslo);

    // 5) Output projection (bf16 3-term, unchanged)
    mma_gemm<false><<<dim3(4, 32, 1), 512, GEMM_SMEM>>>(
        oshi, oslo, wthi + 3ull * DIMC * DIMC, wtlo + 3ull * DIMC * DIMC,
        bp, bp, bp, out, out, out, fhhi, fhlo);
}

// round 15
// speedup vs baseline: 4.1668x; 1.2218x over previous
#include <cuda_runtime.h>
#include <cuda_bf16.h>
#include <cuda_fp16.h>
#include <cstdint>
#include <math.h>

#define DIMC   1024
#define NSEQ   2048
#define BATCH  2
#define NHEADS 16
#define HD     64
#define MROWS  (BATCH * NSEQ)     // 4096
#define BHNUM  (BATCH * NHEADS)   // 32
#define SLOT   ((size_t)BHNUM * NSEQ * HD)   // elements per q/k/v slot

// ---------------------------------------------------------------------------
// Scratch (static device globals — no runtime allocation allowed)
// ---------------------------------------------------------------------------
__device__ __half g_ln_hi[3ull * MROWS * DIMC];          // LN out, fp16 hi
__device__ __half g_ln_lo[3ull * MROWS * DIMC];          // LN out, fp16 lo
__device__ __half g_wt[4ull * DIMC * DIMC];              // W transposed [N][K], fp16
__device__ __half g_fh_hi[3ull * SLOT];                  // q hi / k hi / vT hi (fp16)
__device__ __half g_fh_lo[3ull * SLOT];                  // q lo / (unused) / vT lo
__device__ __half g_os_hi[(size_t)MROWS * DIMC];         // flash out split (row-major)
__device__ __half g_os_lo[(size_t)MROWS * DIMC];
__device__ float g_dummy[(size_t)MROWS * DIMC];          // unused fp32 sink for z=0

// ---------------------------------------------------------------------------
// PTX helpers (baseline ISA only)
// ---------------------------------------------------------------------------
__device__ __forceinline__ void cp16(uint32_t s, const void* g) {
    asm volatile("cp.async.cg.shared.global [%0], [%1], 16;\n"
                 :: "r"(s), "l"(__cvta_generic_to_global(g)) : "memory");
}
#define CP_COMMIT() asm volatile("cp.async.commit_group;\n" ::: "memory")
#define CP_WAIT(n)  asm volatile("cp.async.wait_group %0;\n" :: "n"(n) : "memory")
#define BAR_SYNC(id, cnt) \
    asm volatile("bar.sync %0, %1;" :: "r"(id), "r"(cnt) : "memory")

__device__ __forceinline__ void ldmx4(uint32_t* r, uint32_t addr) {
    asm volatile("ldmatrix.sync.aligned.m8n8.x4.shared.b16 {%0,%1,%2,%3}, [%4];"
                 : "=r"(r[0]), "=r"(r[1]), "=r"(r[2]), "=r"(r[3]) : "r"(addr));
}

__device__ __forceinline__ void mma16816h(float* c, const uint32_t* a, const uint32_t* b) {
    asm volatile("mma.sync.aligned.m16n8k16.row.col.f32.f16.f16.f32 "
                 "{%0,%1,%2,%3}, {%4,%5,%6,%7}, {%8,%9}, {%0,%1,%2,%3};"
                 : "+f"(c[0]), "+f"(c[1]), "+f"(c[2]), "+f"(c[3])
                 : "r"(a[0]), "r"(a[1]), "r"(a[2]), "r"(a[3]), "r"(b[0]), "r"(b[1]));
}

__device__ __forceinline__ uint32_t pack_h2(float a, float b) {
    __half2 t = __floats2half2_rn(a, b);
    return *reinterpret_cast<uint32_t*>(&t);
}

// ---------------------------------------------------------------------------
// Fused LayerNorm + fp16 split for q/k/v (z = blockIdx.y)
// ---------------------------------------------------------------------------
__global__ void __launch_bounds__(256) ln_split_fused(
    const float* __restrict__ q, const float* __restrict__ k, const float* __restrict__ v,
    const float* __restrict__ gq, const float* __restrict__ bq,
    const float* __restrict__ gk, const float* __restrict__ bk,
    const float* __restrict__ gv, const float* __restrict__ bv,
    __half* __restrict__ hi_base, __half* __restrict__ lo_base) {
    const int z = blockIdx.y;
    const float* x = (z == 0) ? q : (z == 1) ? k : v;
    const float* g = (z == 0) ? gq : (z == 1) ? gk : gv;
    const float* b = (z == 0) ? bq : (z == 1) ? bk : bv;
    __half* hi = hi_base + (size_t)z * MROWS * DIMC;
    __half* lo = lo_base + (size_t)z * MROWS * DIMC;

    const int row = blockIdx.x;
    const int tid = threadIdx.x;
    const float4 vv = reinterpret_cast<const float4*>(x + (size_t)row * DIMC)[tid];
    float s  = vv.x + vv.y + vv.z + vv.w;
    float ss = vv.x * vv.x + vv.y * vv.y + vv.z * vv.z + vv.w * vv.w;
#pragma unroll
    for (int off = 16; off > 0; off >>= 1) {
        s  += __shfl_xor_sync(0xffffffffu, s, off);
        ss += __shfl_xor_sync(0xffffffffu, ss, off);
    }
    __shared__ float rs[8], rss[8];
    if ((tid & 31) == 0) { rs[tid >> 5] = s; rss[tid >> 5] = ss; }
    __syncthreads();
    float tot = 0.f, totss = 0.f;
#pragma unroll
    for (int i = 0; i < 8; i++) { tot += rs[i]; totss += rss[i]; }
    const float mean = tot * (1.0f / DIMC);
    const float var  = totss * (1.0f / DIMC) - mean * mean;
    const float rstd = rsqrtf(var + 1e-5f);
    const float4 g4 = reinterpret_cast<const float4*>(g)[tid];
    const float4 b4 = reinterpret_cast<const float4*>(b)[tid];
    float o[4];
    o[0] = (vv.x - mean) * rstd * g4.x + b4.x;
    o[1] = (vv.y - mean) * rstd * g4.y + b4.y;
    o[2] = (vv.z - mean) * rstd * g4.z + b4.z;
    o[3] = (vv.w - mean) * rstd * g4.w + b4.w;
    __half h[4], l[4];
#pragma unroll
    for (int i = 0; i < 4; i++) {
        h[i] = __float2half_rn(o[i]);
        l[i] = __float2half_rn(o[i] - __half2float(h[i]));
    }
    __half2* H = reinterpret_cast<__half2*>(hi + (size_t)row * DIMC);
    __half2* L = reinterpret_cast<__half2*>(lo + (size_t)row * DIMC);
    H[tid * 2]     = __halves2half2(h[0], h[1]);
    H[tid * 2 + 1] = __halves2half2(h[2], h[3]);
    L[tid * 2]     = __halves2half2(l[0], l[1]);
    L[tid * 2 + 1] = __halves2half2(l[2], l[3]);
}

// ---------------------------------------------------------------------------
// Weight transpose to fp16 (hi only): Wt[n][k] = fp16(W[k][n]); 4 weights.
// ---------------------------------------------------------------------------
__global__ void __launch_bounds__(256) wsplit_kernel(const float* __restrict__ W0,
                                                     const float* __restrict__ W1,
                                                     const float* __restrict__ W2,
                                                     const float* __restrict__ W3,
                                                     __half* __restrict__ hi) {
    const int z = blockIdx.z;
    const float* W = (z == 0) ? W0 : (z == 1) ? W1 : (z == 2) ? W2 : W3;
    const size_t ob = (size_t)z * DIMC * DIMC;
    __shared__ float t[32][33];
    const int tx = threadIdx.x, ty = threadIdx.y;
    const int n0 = blockIdx.x * 32, k0 = blockIdx.y * 32;
#pragma unroll
    for (int r = 0; r < 4; r++)
        t[ty + 8 * r][tx] = W[(size_t)(k0 + ty + 8 * r) * DIMC + n0 + tx];
    __syncthreads();
#pragma unroll
    for (int r = 0; r < 4; r++) {
        const float x = t[tx][ty + 8 * r];
        hi[ob + (size_t)(n0 + ty + 8 * r) * DIMC + k0 + tx] = __float2half_rn(x);
    }
}

// ---------------------------------------------------------------------------
// mma.sync fp16 GEMM, 2-term split: C = (Ahi+Alo) @ Whi^T + bias (fp32 out).
// Tile 128(M) x 256(N), BK=32, 512 threads, 16 warps (4x4), warp tile 32x64.
// 3-stage cp.async pipeline, ONE barrier per iteration.
// CHEAD epilogue emits fp16 hi/lo for flash (q scaled / k hi-only / v transp).
// ---------------------------------------------------------------------------
#define ATILE_B (128 * 80)           // 10240
#define BTILE_B (256 * 80)           // 20480
#define STAGE_B (2 * ATILE_B + BTILE_B)       // 40960
#define GEMM_SMEM (3 * STAGE_B)               // 122880

__device__ __forceinline__ void load_stage(uint32_t st,
                                           const __half* Ahi, const __half* Alo,
                                           const __half* B,
                                           int bm, int bn, int k0, int tid) {
    {                                            // A: 128 rows x 4 segs = 512
        const int row = tid >> 2, seg = tid & 3;
        const uint32_t so = (uint32_t)(row * 80 + seg * 16);
        const size_t ga = (size_t)(bm + row) * DIMC + k0 + seg * 8;
        cp16(st + so, Ahi + ga);
        cp16(st + ATILE_B + so, Alo + ga);
    }
#pragma unroll
    for (int it = 0; it < 2; it++) {             // B: 256 rows x 4 segs = 1024
        const int idx = tid + it * 512;
        const int row = idx >> 2, seg = idx & 3;
        const uint32_t so = (uint32_t)(row * 80 + seg * 16);
        const size_t gb = (size_t)(bn + row) * DIMC + k0 + seg * 8;
        cp16(st + 2 * ATILE_B + so, B + gb);
    }
    CP_COMMIT();
}

template <bool CHEAD>
__global__ void __launch_bounds__(512, 1) mma_gemm(
    const __half* __restrict__ Ahi_base, const __half* __restrict__ Alo_base,
    const __half* __restrict__ B_base,
    const float* b0, const float* b1, const float* b2,
    float* C0, float* C1, float* C2,
    __half* FHhi, __half* FHlo) {
    extern __shared__ __align__(128) char smem[];
    const uint32_t sbase = (uint32_t)__cvta_generic_to_shared(smem);
    const int tid = threadIdx.x, wid = tid >> 5, lane = tid & 31;
    const int z = blockIdx.z;
    const __half* Ahi = Ahi_base + (size_t)z * MROWS * DIMC;
    const __half* Alo = Alo_base + (size_t)z * MROWS * DIMC;
    const __half* B = B_base + (size_t)z * DIMC * DIMC;
    const float* bias = (z == 0) ? b0 : (z == 1) ? b1 : b2;
    float* C = (z == 0) ? C0 : (z == 1) ? C1 : C2;
    const int bm = blockIdx.y * 128;
    const int bn = blockIdx.x * 256;
    const int wr = wid >> 2;          // 0..3 -> m offset 32*wr
    const int wc = wid & 3;           // 0..3 -> n offset 64*wc

    float acc[2][8][4];
#pragma unroll
    for (int i = 0; i < 2; i++)
#pragma unroll
        for (int j = 0; j < 8; j++)
#pragma unroll
            for (int t = 0; t < 4; t++) acc[i][j][t] = 0.f;

    const int a_r = wr * 32 + (lane & 15);
    const uint32_t a_off0 = (uint32_t)(a_r * 80 + ((lane >> 4) << 4));
    const int b_n = wc * 64 + (lane & 7) + ((lane >> 4) << 3);
    const uint32_t b_off0 = (uint32_t)(b_n * 80 + (((lane >> 3) & 1) << 4));

    load_stage(sbase, Ahi, Alo, B, bm, bn, 0, tid);
    load_stage(sbase + STAGE_B, Ahi, Alo, B, bm, bn, 32, tid);

    for (int i = 0; i < 32; i++) {
        if (i < 31) { CP_WAIT(1); } else { CP_WAIT(0); }
        __syncthreads();   // stage i%3 ready; stage (i+2)%3 free
        if (i + 2 < 32)
            load_stage(sbase + (uint32_t)((i + 2) % 3) * STAGE_B,
                       Ahi, Alo, B, bm, bn, (i + 2) * 32, tid);
        const uint32_t st = sbase + (uint32_t)(i % 3) * STAGE_B;
#pragma unroll
        for (int h = 0; h < 2; h++) {
            const uint32_t hb = (uint32_t)(h * 32);
            uint32_t ah[2][4], al[2][4];
#pragma unroll
            for (int mf = 0; mf < 2; mf++) {
                const uint32_t ao = a_off0 + hb + (uint32_t)(mf * 16 * 80);
                ldmx4(ah[mf], st + ao);
                ldmx4(al[mf], st + ATILE_B + ao);
            }
            uint32_t bh[8][2];
#pragma unroll
            for (int nf2 = 0; nf2 < 4; nf2++) {
                const uint32_t bo = b_off0 + hb + (uint32_t)(nf2 * 16 * 80);
                uint32_t r4[4];
                ldmx4(r4, st + 2 * ATILE_B + bo);
                bh[nf2 * 2][0] = r4[0]; bh[nf2 * 2][1] = r4[1];
                bh[nf2 * 2 + 1][0] = r4[2]; bh[nf2 * 2 + 1][1] = r4[3];
            }
#pragma unroll
            for (int mf = 0; mf < 2; mf++)
#pragma unroll
                for (int nf = 0; nf < 8; nf++) {
                    mma16816h(acc[mf][nf], ah[mf], bh[nf]);
                    mma16816h(acc[mf][nf], al[mf], bh[nf]);
                }
        }
    }

    const int lr = lane >> 2, lc = (lane & 3) * 2;
#pragma unroll
    for (int mf = 0; mf < 2; mf++) {
#pragma unroll
        for (int nf = 0; nf < 8; nf++) {
            const int col = bn + wc * 64 + nf * 8 + lc;
            const float bx = bias[col], by = bias[col + 1];
            const int r0 = bm + wr * 32 + mf * 16 + lr;
#pragma unroll
            for (int half = 0; half < 2; half++) {
                const int r = r0 + half * 8;
                const float a = acc[mf][nf][half * 2 + 0] + bx;
                const float c2 = acc[mf][nf][half * 2 + 1] + by;
                if (CHEAD) {
                    const int b = r >> 11, n = r & (NSEQ - 1);
                    const int hh = col >> 6, d0 = col & 63;
                    const size_t hoff = (((size_t)(b * NHEADS + hh) * NSEQ + n) << 6) + d0;
                    if (z == 0) {
                        // q: fp16 hi/lo, pre-scaled by 0.125
                        const float sa = a * 0.125f, sb = c2 * 0.125f;
                        const __half2 h2 = __floats2half2_rn(sa, sb);
                        const float2 f = __half22float2(h2);
                        const __half2 l2 = __floats2half2_rn(sa - f.x, sb - f.y);
                        *reinterpret_cast<__half2*>(FHhi + hoff) = h2;
                        *reinterpret_cast<__half2*>(FHlo + hoff) = l2;
                    } else if (z == 1) {
                        // k: fp32 output + fp16 hi only
                        float2 o; o.x = a; o.y = c2;
                        *reinterpret_cast<float2*>(C + hoff) = o;
                        *reinterpret_cast<__half2*>(FHhi + SLOT + hoff) =
                            __floats2half2_rn(a, c2);
                    } else {
                        // v: fp32 output + transposed fp16 hi/lo
                        float2 o; o.x = a; o.y = c2;
                        *reinterpret_cast<float2*>(C + hoff) = o;
                        const __half ha = __float2half_rn(a);
                        const __half hb2 = __float2half_rn(c2);
                        const __half la = __float2half_rn(a - __half2float(ha));
                        const __half lb = __float2half_rn(c2 - __half2float(hb2));
                        const size_t tb = ((size_t)(b * NHEADS + hh) * HD + d0) * NSEQ + n;
                        FHhi[2 * SLOT + tb] = ha;
                        FHhi[2 * SLOT + tb + NSEQ] = hb2;
                        FHlo[2 * SLOT + tb] = la;
                        FHlo[2 * SLOT + tb + NSEQ] = lb;
                    }
                } else {
                    float2 o; o.x = a; o.y = c2;
                    *reinterpret_cast<float2*>(C + (size_t)r * DIMC + col) = o;
                }
            }
        }
    }
}

// ---------------------------------------------------------------------------
// Flash attention, fp16 2-term splits, split-KV (2 warp-groups of 8).
// S = (Qhi+Qlo)·Khi;  O += Phi·(Vhi+Vlo).  Output: fp16 hi/lo row-major.
// ---------------------------------------------------------------------------
#define FPITCH  144
#define FQT_B   (128 * FPITCH)           // 18432 per Q tile (hi or lo)
#define FQ2_B   (2 * FQT_B)              // 36864
#define FT_B    (64 * FPITCH)            // 9216 per K/V tile
#define FSTG_B  (3 * FT_B)               // 27648 per stage (Kh, Vh, Vl)
#define FGRP_B  (2 * FSTG_B)             // 55296 per group (double buffer)
#define FLASH_SMEM (FQ2_B + 2 * FGRP_B)  // 147456
#define MERGE_OFF (FQ2_B + FGRP_B)       // merge buffers overlay group-1 region
#define OBUF_STRIDE 68                   // floats per row (padded)

__device__ __forceinline__ void load_kv(uint32_t st,
                                        const __half* khi,
                                        const __half* vthi, const __half* vtlo,
                                        int bh, int kt, int gtid) {
#pragma unroll
    for (int it = 0; it < 2; it++) {
        const int idx = gtid + it * 256;           // 64 rows x 8 segs = 512
        const int row = idx >> 3, seg = idx & 7;
        const uint32_t so = (uint32_t)(row * FPITCH + seg * 16);
        const size_t gk = (size_t)bh * NSEQ * HD + (size_t)(kt * 64 + row) * HD + seg * 8;
        const size_t gv = ((size_t)bh * HD + row) * NSEQ + kt * 64 + seg * 8;
        cp16(st + 0 * FT_B + so, khi + gk);
        cp16(st + 1 * FT_B + so, vthi + gv);
        cp16(st + 2 * FT_B + so, vtlo + gv);
    }
    CP_COMMIT();
}

__global__ void __launch_bounds__(512, 1) flash_mma(
    const __half* __restrict__ FHhi, const __half* __restrict__ FHlo,
    __half* __restrict__ Ohi, __half* __restrict__ Olo) {
    extern __shared__ __align__(128) char smem[];
    const uint32_t sbase = (uint32_t)__cvta_generic_to_shared(smem);
    const int tid = threadIdx.x, wid = tid >> 5, lane = tid & 31;
    const int g = wid >> 3;           // warp group 0/1
    const int gw = wid & 7;           // warp within group
    const int gtid = tid & 255;
    const int bh = blockIdx.y;
    const int q0 = blockIdx.x * 128;

    const __half* qhi = FHhi;
    const __half* qlo = FHlo;
    const __half* khi = FHhi + SLOT;
    const __half* vthi = FHhi + 2 * SLOT;
    const __half* vtlo = FHlo + 2 * SLOT;

    // Q tiles -> smem (128 rows x 8 segs, hi + lo), all 512 threads
#pragma unroll
    for (int it = 0; it < 2; it++) {
        const int idx = tid + it * 512;
        const int row = idx >> 3, seg = idx & 7;
        const uint32_t so = (uint32_t)(row * FPITCH + seg * 16);
        const size_t gq = (size_t)bh * NSEQ * HD + (size_t)(q0 + row) * HD + seg * 8;
        cp16(sbase + so, qhi + gq);
        cp16(sbase + FQT_B + so, qlo + gq);
    }
    CP_COMMIT();

    const uint32_t stgbase = sbase + FQ2_B + (uint32_t)g * FGRP_B;
    const int kt0 = g * 16;
    load_kv(stgbase, khi, vthi, vtlo, bh, kt0 + 0, gtid);
    load_kv(stgbase + FSTG_B, khi, vthi, vtlo, bh, kt0 + 1, gtid);

    CP_WAIT(2);        // Q group complete (2 KV groups may remain in flight)
    __syncthreads();

    // Q fragments (A operand), 4 k16 frags, hi+lo
    uint32_t qfh[4][4], qfl[4][4];
    {
        const int a_r = gw * 16 + (lane & 15);
        const uint32_t a0 = (uint32_t)(a_r * FPITCH + ((lane >> 4) << 4));
#pragma unroll
        for (int kf = 0; kf < 4; kf++) {
            ldmx4(qfh[kf], sbase + a0 + kf * 32);
            ldmx4(qfl[kf], sbase + FQT_B + a0 + kf * 32);
        }
    }

    const uint32_t b_off0 =
        (uint32_t)(((lane & 7) + ((lane >> 4) << 3)) * FPITCH + (((lane >> 3) & 1) << 4));
    const int barid = 1 + g;

    float o[8][4];
#pragma unroll
    for (int nf = 0; nf < 8; nf++)
#pragma unroll
        for (int t = 0; t < 4; t++) o[nf][t] = 0.f;
    float mA = -1e30f, mB = -1e30f, lA = 0.f, lB = 0.f;

    for (int t = 0; t < 16; t++) {
        if (t < 15) { CP_WAIT(1); } else { CP_WAIT(0); }
        BAR_SYNC(barid, 256);
        const uint32_t st = stgbase + (uint32_t)(t & 1) * FSTG_B;

        // ---- S = (Qhi + Qlo) · Khi ----
        float s[8][4];
#pragma unroll
        for (int nf = 0; nf < 8; nf++)
#pragma unroll
            for (int tt = 0; tt < 4; tt++) s[nf][tt] = 0.f;
#pragma unroll
        for (int kf = 0; kf < 4; kf++) {
#pragma unroll
            for (int nf2 = 0; nf2 < 4; nf2++) {
                const uint32_t bo = b_off0 + (uint32_t)(nf2 * 16 * FPITCH) + kf * 32;
                uint32_t kh4[4];
                ldmx4(kh4, st + 0 * FT_B + bo);
                mma16816h(s[nf2 * 2], qfh[kf], &kh4[0]);
                mma16816h(s[nf2 * 2], qfl[kf], &kh4[0]);
                mma16816h(s[nf2 * 2 + 1], qfh[kf], &kh4[2]);
                mma16816h(s[nf2 * 2 + 1], qfl[kf], &kh4[2]);
            }
        }

        // ---- online softmax (rows rA = lane>>2, rB = rA+8) ----
        float rmA = -1e30f, rmB = -1e30f;
#pragma unroll
        for (int nf = 0; nf < 8; nf++) {
            rmA = fmaxf(rmA, fmaxf(s[nf][0], s[nf][1]));
            rmB = fmaxf(rmB, fmaxf(s[nf][2], s[nf][3]));
        }
        rmA = fmaxf(rmA, __shfl_xor_sync(0xffffffffu, rmA, 1, 4));
        rmA = fmaxf(rmA, __shfl_xor_sync(0xffffffffu, rmA, 2, 4));
        rmB = fmaxf(rmB, __shfl_xor_sync(0xffffffffu, rmB, 1, 4));
        rmB = fmaxf(rmB, __shfl_xor_sync(0xffffffffu, rmB, 2, 4));
        const float mnA = fmaxf(mA, rmA);
        const float mnB = fmaxf(mB, rmB);
        const float cA = __expf(mA - mnA);
        const float cB = __expf(mB - mnB);
        mA = mnA; mB = mnB;
        float sumA = 0.f, sumB = 0.f;
#pragma unroll
        for (int nf = 0; nf < 8; nf++) {
            s[nf][0] = __expf(s[nf][0] - mnA);
            s[nf][1] = __expf(s[nf][1] - mnA);
            s[nf][2] = __expf(s[nf][2] - mnB);
            s[nf][3] = __expf(s[nf][3] - mnB);
            sumA += s[nf][0] + s[nf][1];
            sumB += s[nf][2] + s[nf][3];
        }
        sumA += __shfl_xor_sync(0xffffffffu, sumA, 1, 4);
        sumA += __shfl_xor_sync(0xffffffffu, sumA, 2, 4);
        sumB += __shfl_xor_sync(0xffffffffu, sumB, 1, 4);
        sumB += __shfl_xor_sync(0xffffffffu, sumB, 2, 4);
        lA = lA * cA + sumA;
        lB = lB * cB + sumB;
#pragma unroll
        for (int nf = 0; nf < 8; nf++) {
            o[nf][0] *= cA; o[nf][1] *= cA;
            o[nf][2] *= cB; o[nf][3] *= cB;
        }

        // ---- O += Phi · (Vhi + Vlo) (P single-fp16, register repack) ----
#pragma unroll
        for (int kf = 0; kf < 4; kf++) {
            uint32_t pah[4];
#pragma unroll
            for (int blk = 0; blk < 2; blk++) {
                pah[blk * 2 + 0] = pack_h2(s[2 * kf + blk][0], s[2 * kf + blk][1]);
                pah[blk * 2 + 1] = pack_h2(s[2 * kf + blk][2], s[2 * kf + blk][3]);
            }
#pragma unroll
            for (int nf2 = 0; nf2 < 4; nf2++) {
                const uint32_t bo = b_off0 + (uint32_t)(nf2 * 16 * FPITCH) + kf * 32;
                uint32_t vh4[4], vl4[4];
                ldmx4(vh4, st + 1 * FT_B + bo);
                ldmx4(vl4, st + 2 * FT_B + bo);
                mma16816h(o[nf2 * 2], pah, &vh4[0]);
                mma16816h(o[nf2 * 2], pah, &vl4[0]);
                mma16816h(o[nf2 * 2 + 1], pah, &vh4[2]);
                mma16816h(o[nf2 * 2 + 1], pah, &vl4[2]);
            }
        }

        BAR_SYNC(barid, 256);    // group done reading stage t&1
        if (t + 2 < 16)
            load_kv(st, khi, vthi, vtlo, bh, kt0 + t + 2, gtid);
    }

    // ---- merge the two KV-halves (exact fp32) ----
    float* mbuf = reinterpret_cast<float*>(smem + MERGE_OFF);            // 128
    float* lbuf = reinterpret_cast<float*>(smem + MERGE_OFF + 512);      // 128
    float* obuf = reinterpret_cast<float*>(smem + MERGE_OFF + 1024);     // 128 x 68
    const int lr = gw * 16 + (lane >> 2);     // local row 0..127 (rA)
    if (g == 1) {
        if ((lane & 3) == 0) {
            mbuf[lr] = mA; lbuf[lr] = lA;
            mbuf[lr + 8] = mB; lbuf[lr + 8] = lB;
        }
#pragma unroll
        for (int nf = 0; nf < 8; nf++) {
            const int col = nf * 8 + (lane & 3) * 2;
            float2 pa; pa.x = o[nf][0]; pa.y = o[nf][1];
            float2 pb; pb.x = o[nf][2]; pb.y = o[nf][3];
            *reinterpret_cast<float2*>(&obuf[lr * OBUF_STRIDE + col]) = pa;
            *reinterpret_cast<float2*>(&obuf[(lr + 8) * OBUF_STRIDE + col]) = pb;
        }
    }
    __syncthreads();
    if (g == 0) {
        const float m1A = mbuf[lr], l1A = lbuf[lr];
        const float m1B = mbuf[lr + 8], l1B = lbuf[lr + 8];
        const float mfA = fmaxf(mA, m1A);
        const float mfB = fmaxf(mB, m1B);
        const float e0A = __expf(mA - mfA), e1A = __expf(m1A - mfA);
        const float e0B = __expf(mB - mfB), e1B = __expf(m1B - mfB);
        const float invA = 1.0f / (lA * e0A + l1A * e1A);
        const float invB = 1.0f / (lB * e0B + l1B * e1B);
        const int b = bh >> 4, h = bh & 15;
        const int rA = q0 + lr;
        const int rB = rA + 8;
        const size_t baseA = ((size_t)(b * NSEQ + rA)) * DIMC + h * 64;
        const size_t baseB = ((size_t)(b * NSEQ + rB)) * DIMC + h * 64;
#pragma unroll
        for (int nf = 0; nf < 8; nf++) {
            const int col = nf * 8 + (lane & 3) * 2;
            const float2 p1A = *reinterpret_cast<const float2*>(&obuf[lr * OBUF_STRIDE + col]);
            const float2 p1B =
                *reinterpret_cast<const float2*>(&obuf[(lr + 8) * OBUF_STRIDE + col]);
            const float a0 = (o[nf][0] * e0A + p1A.x * e1A) * invA;
            const float a1 = (o[nf][1] * e0A + p1A.y * e1A) * invA;
            const float b0 = (o[nf][2] * e0B + p1B.x * e1B) * invB;
            const float b1 = (o[nf][3] * e0B + p1B.y * e1B) * invB;
            const __half2 hA = __floats2half2_rn(a0, a1);
            const float2 fA = __half22float2(hA);
            const __half2 lA2 = __floats2half2_rn(a0 - fA.x, a1 - fA.y);
            const __half2 hB = __floats2half2_rn(b0, b1);
            const float2 fB = __half22float2(hB);
            const __half2 lB2 = __floats2half2_rn(b0 - fB.x, b1 - fB.y);
            *reinterpret_cast<__half2*>(Ohi + baseA + col) = hA;
            *reinterpret_cast<__half2*>(Olo + baseA + col) = lA2;
            *reinterpret_cast<__half2*>(Ohi + baseB + col) = hB;
            *reinterpret_cast<__half2*>(Olo + baseB + col) = lB2;
        }
    }
}

// ---------------------------------------------------------------------------
extern "C" void kernel_launch(void* const* d_in, const int* in_sizes, int n_in,
                              void* d_out, int out_size) {
    const float* q    = (const float*)d_in[0];
    const float* k    = (const float*)d_in[1];
    const float* v    = (const float*)d_in[2];
    const float* gq   = (const float*)d_in[3];
    const float* bqln = (const float*)d_in[4];
    const float* gk   = (const float*)d_in[5];
    const float* bkln = (const float*)d_in[6];
    const float* gv   = (const float*)d_in[7];
    const float* bvln = (const float*)d_in[8];
    const float* Wq   = (const float*)d_in[9];
    const float* bq   = (const float*)d_in[10];
    const float* Wk   = (const float*)d_in[11];
    const float* bk   = (const float*)d_in[12];
    const float* Wv   = (const float*)d_in[13];
    const float* bv   = (const float*)d_in[14];
    const float* Wp   = (const float*)d_in[15];
    const float* bp   = (const float*)d_in[16];

    float* out = (float*)d_out;
    float* kh  = out + (size_t)MROWS * DIMC;
    float* vh  = kh + (size_t)MROWS * DIMC;

    __half *lnhi, *lnlo, *wt, *fhhi, *fhlo, *oshi, *oslo;
    float* dummy;
    cudaGetSymbolAddress((void**)&lnhi, g_ln_hi);
    cudaGetSymbolAddress((void**)&lnlo, g_ln_lo);
    cudaGetSymbolAddress((void**)&wt, g_wt);
    cudaGetSymbolAddress((void**)&fhhi, g_fh_hi);
    cudaGetSymbolAddress((void**)&fhlo, g_fh_lo);
    cudaGetSymbolAddress((void**)&oshi, g_os_hi);
    cudaGetSymbolAddress((void**)&oslo, g_os_lo);
    cudaGetSymbolAddress((void**)&dummy, g_dummy);

    // 1) Fused LayerNorm + fp16 split (q/k/v in one launch)
    ln_split_fused<<<dim3(MROWS, 3), 256>>>(q, k, v, gq, bqln, gk, bkln, gv, bvln,
                                            lnhi, lnlo);

    // 2) Weight transpose to fp16
    wsplit_kernel<<<dim3(32, 32, 4), dim3(32, 8)>>>(Wq, Wk, Wv, Wp, wt);

    // 3) QKV projection (fp16 2-term), emits flash-ready fp16 hi/lo
    cudaFuncSetAttribute(mma_gemm<true>, cudaFuncAttributeMaxDynamicSharedMemorySize, GEMM_SMEM);
    cudaFuncSetAttribute(mma_gemm<false>, cudaFuncAttributeMaxDynamicSharedMemorySize, GEMM_SMEM);
    mma_gemm<true><<<dim3(4, 32, 3), 512, GEMM_SMEM>>>(
        lnhi, lnlo, wt, bq, bk, bv, dummy, kh, vh, fhhi, fhlo);

    // 4) Flash attention (fp16 2-term, split-KV) -> fp16 hi/lo row-major
    cudaFuncSetAttribute(flash_mma, cudaFuncAttributeMaxDynamicSharedMemorySize, FLASH_SMEM);
    flash_mma<<<dim3(NSEQ / 128, BHNUM), 512, FLASH_SMEM>>>(fhhi, fhlo, oshi, oslo);

    // 5) Output projection (fp16 2-term)
    mma_gemm<false><<<dim3(4, 32, 1), 512, GEMM_SMEM>>>(
        oshi, oslo, wt + 3ull * DIMC * DIMC,
        bp, bp, bp, out, out, out, fhhi, fhlo);
}

// round 16
// speedup vs baseline: 6.3636x; 1.5272x over previous
#include <cuda_runtime.h>
#include <cuda_fp16.h>
#include <cstdint>
#include <math.h>

#define DIMC   1024
#define NSEQ   2048
#define BATCH  2
#define NHEADS 16
#define HD     64
#define MROWS  (BATCH * NSEQ)     // 4096
#define BHNUM  (BATCH * NHEADS)   // 32
#define SLOT   ((size_t)BHNUM * NSEQ * HD)   // elements per q/k/v slot

// ---------------------------------------------------------------------------
// Scratch (static device globals — no runtime allocation allowed)
// ---------------------------------------------------------------------------
__device__ __half g_ln[3ull * MROWS * DIMC];      // LN out, fp16
__device__ __half g_wt[4ull * DIMC * DIMC];       // W transposed [N][K], fp16
__device__ __half g_fh[3ull * SLOT];              // q(head,scaled)/k(head)/vT, fp16
__device__ __half g_os[(size_t)MROWS * DIMC];     // flash out, row-major fp16
__device__ float g_dummy[(size_t)MROWS * DIMC];   // unused fp32 sink for z=0

// ---------------------------------------------------------------------------
// PTX helpers (baseline ISA only)
// ---------------------------------------------------------------------------
__device__ __forceinline__ void cp16(uint32_t s, const void* g) {
    asm volatile("cp.async.cg.shared.global [%0], [%1], 16;\n"
                 :: "r"(s), "l"(__cvta_generic_to_global(g)) : "memory");
}
#define CP_COMMIT() asm volatile("cp.async.commit_group;\n" ::: "memory")
#define CP_WAIT(n)  asm volatile("cp.async.wait_group %0;\n" :: "n"(n) : "memory")
#define BAR_SYNC(id, cnt) \
    asm volatile("bar.sync %0, %1;" :: "r"(id), "r"(cnt) : "memory")

__device__ __forceinline__ void ldmx4(uint32_t* r, uint32_t addr) {
    asm volatile("ldmatrix.sync.aligned.m8n8.x4.shared.b16 {%0,%1,%2,%3}, [%4];"
                 : "=r"(r[0]), "=r"(r[1]), "=r"(r[2]), "=r"(r[3]) : "r"(addr));
}

__device__ __forceinline__ void mma16816h(float* c, const uint32_t* a, const uint32_t* b) {
    asm volatile("mma.sync.aligned.m16n8k16.row.col.f32.f16.f16.f32 "
                 "{%0,%1,%2,%3}, {%4,%5,%6,%7}, {%8,%9}, {%0,%1,%2,%3};"
                 : "+f"(c[0]), "+f"(c[1]), "+f"(c[2]), "+f"(c[3])
                 : "r"(a[0]), "r"(a[1]), "r"(a[2]), "r"(a[3]), "r"(b[0]), "r"(b[1]));
}

__device__ __forceinline__ uint32_t pack_h2(float a, float b) {
    __half2 t = __floats2half2_rn(a, b);
    return *reinterpret_cast<uint32_t*>(&t);
}

// ---------------------------------------------------------------------------
// Fused LayerNorm -> fp16 for q/k/v (z = blockIdx.y)
// ---------------------------------------------------------------------------
__global__ void __launch_bounds__(256) ln_fused(
    const float* __restrict__ q, const float* __restrict__ k, const float* __restrict__ v,
    const float* __restrict__ gq, const float* __restrict__ bq,
    const float* __restrict__ gk, const float* __restrict__ bk,
    const float* __restrict__ gv, const float* __restrict__ bv,
    __half* __restrict__ out_base) {
    const int z = blockIdx.y;
    const float* x = (z == 0) ? q : (z == 1) ? k : v;
    const float* g = (z == 0) ? gq : (z == 1) ? gk : gv;
    const float* b = (z == 0) ? bq : (z == 1) ? bk : bv;
    __half* outp = out_base + (size_t)z * MROWS * DIMC;

    const int row = blockIdx.x;
    const int tid = threadIdx.x;
    const float4 vv = reinterpret_cast<const float4*>(x + (size_t)row * DIMC)[tid];
    float s  = vv.x + vv.y + vv.z + vv.w;
    float ss = vv.x * vv.x + vv.y * vv.y + vv.z * vv.z + vv.w * vv.w;
#pragma unroll
    for (int off = 16; off > 0; off >>= 1) {
        s  += __shfl_xor_sync(0xffffffffu, s, off);
        ss += __shfl_xor_sync(0xffffffffu, ss, off);
    }
    __shared__ float rs[8], rss[8];
    if ((tid & 31) == 0) { rs[tid >> 5] = s; rss[tid >> 5] = ss; }
    __syncthreads();
    float tot = 0.f, totss = 0.f;
#pragma unroll
    for (int i = 0; i < 8; i++) { tot += rs[i]; totss += rss[i]; }
    const float mean = tot * (1.0f / DIMC);
    const float var  = totss * (1.0f / DIMC) - mean * mean;
    const float rstd = rsqrtf(var + 1e-5f);
    const float4 g4 = reinterpret_cast<const float4*>(g)[tid];
    const float4 b4 = reinterpret_cast<const float4*>(b)[tid];
    float o[4];
    o[0] = (vv.x - mean) * rstd * g4.x + b4.x;
    o[1] = (vv.y - mean) * rstd * g4.y + b4.y;
    o[2] = (vv.z - mean) * rstd * g4.z + b4.z;
    o[3] = (vv.w - mean) * rstd * g4.w + b4.w;
    __half2* H = reinterpret_cast<__half2*>(outp + (size_t)row * DIMC);
    H[tid * 2]     = __floats2half2_rn(o[0], o[1]);
    H[tid * 2 + 1] = __floats2half2_rn(o[2], o[3]);
}

// ---------------------------------------------------------------------------
// Weight transpose to fp16: Wt[n][k] = fp16(W[k][n]); 4 weights via z.
// ---------------------------------------------------------------------------
__global__ void __launch_bounds__(256) wsplit_kernel(const float* __restrict__ W0,
                                                     const float* __restrict__ W1,
                                                     const float* __restrict__ W2,
                                                     const float* __restrict__ W3,
                                                     __half* __restrict__ hi) {
    const int z = blockIdx.z;
    const float* W = (z == 0) ? W0 : (z == 1) ? W1 : (z == 2) ? W2 : W3;
    const size_t ob = (size_t)z * DIMC * DIMC;
    __shared__ float t[32][33];
    const int tx = threadIdx.x, ty = threadIdx.y;
    const int n0 = blockIdx.x * 32, k0 = blockIdx.y * 32;
#pragma unroll
    for (int r = 0; r < 4; r++)
        t[ty + 8 * r][tx] = W[(size_t)(k0 + ty + 8 * r) * DIMC + n0 + tx];
    __syncthreads();
#pragma unroll
    for (int r = 0; r < 4; r++) {
        const float x = t[tx][ty + 8 * r];
        hi[ob + (size_t)(n0 + ty + 8 * r) * DIMC + k0 + tx] = __float2half_rn(x);
    }
}

// ---------------------------------------------------------------------------
// mma.sync fp16 GEMM (single-term operands, fp32 accum):
// C[4096,1024] = A @ Wt^T + bias. Tile 128(M)x256(N), BK=32, 512 threads,
// 16 warps (4x4), warp tile 32x64. 3-stage cp.async pipeline, ONE barrier/iter.
// CHEAD epilogue emits fp16 for flash (q scaled / k head / v transposed).
// ---------------------------------------------------------------------------
#define ATILE_B (128 * 80)           // 10240
#define BTILE_B (256 * 80)           // 20480
#define STAGE_B (ATILE_B + BTILE_B)           // 30720
#define GEMM_SMEM (3 * STAGE_B)               // 92160

__device__ __forceinline__ void load_stage(uint32_t st,
                                           const __half* A, const __half* B,
                                           int bm, int bn, int k0, int tid) {
    {                                            // A: 128 rows x 4 segs = 512
        const int row = tid >> 2, seg = tid & 3;
        const uint32_t so = (uint32_t)(row * 80 + seg * 16);
        cp16(st + so, A + (size_t)(bm + row) * DIMC + k0 + seg * 8);
    }
#pragma unroll
    for (int it = 0; it < 2; it++) {             // B: 256 rows x 4 segs = 1024
        const int idx = tid + it * 512;
        const int row = idx >> 2, seg = idx & 3;
        const uint32_t so = (uint32_t)(row * 80 + seg * 16);
        cp16(st + ATILE_B + so, B + (size_t)(bn + row) * DIMC + k0 + seg * 8);
    }
    CP_COMMIT();
}

template <bool CHEAD>
__global__ void __launch_bounds__(512, 1) mma_gemm(
    const __half* __restrict__ A_base, const __half* __restrict__ B_base,
    const float* b0, const float* b1, const float* b2,
    float* C0, float* C1, float* C2,
    __half* FH) {
    extern __shared__ __align__(128) char smem[];
    const uint32_t sbase = (uint32_t)__cvta_generic_to_shared(smem);
    const int tid = threadIdx.x, wid = tid >> 5, lane = tid & 31;
    const int z = blockIdx.z;
    const __half* A = A_base + (size_t)z * MROWS * DIMC;
    const __half* B = B_base + (size_t)z * DIMC * DIMC;
    const float* bias = (z == 0) ? b0 : (z == 1) ? b1 : b2;
    float* C = (z == 0) ? C0 : (z == 1) ? C1 : C2;
    const int bm = blockIdx.y * 128;
    const int bn = blockIdx.x * 256;
    const int wr = wid >> 2;          // 0..3 -> m offset 32*wr
    const int wc = wid & 3;           // 0..3 -> n offset 64*wc

    float acc[2][8][4];
#pragma unroll
    for (int i = 0; i < 2; i++)
#pragma unroll
        for (int j = 0; j < 8; j++)
#pragma unroll
            for (int t = 0; t < 4; t++) acc[i][j][t] = 0.f;

    const int a_r = wr * 32 + (lane & 15);
    const uint32_t a_off0 = (uint32_t)(a_r * 80 + ((lane >> 4) << 4));
    const int b_n = wc * 64 + (lane & 7) + ((lane >> 4) << 3);
    const uint32_t b_off0 = (uint32_t)(b_n * 80 + (((lane >> 3) & 1) << 4));

    load_stage(sbase, A, B, bm, bn, 0, tid);
    load_stage(sbase + STAGE_B, A, B, bm, bn, 32, tid);

    for (int i = 0; i < 32; i++) {
        if (i < 31) { CP_WAIT(1); } else { CP_WAIT(0); }
        __syncthreads();   // stage i%3 ready; stage (i+2)%3 free
        if (i + 2 < 32)
            load_stage(sbase + (uint32_t)((i + 2) % 3) * STAGE_B,
                       A, B, bm, bn, (i + 2) * 32, tid);
        const uint32_t st = sbase + (uint32_t)(i % 3) * STAGE_B;
#pragma unroll
        for (int h = 0; h < 2; h++) {
            const uint32_t hb = (uint32_t)(h * 32);
            uint32_t ah[2][4];
#pragma unroll
            for (int mf = 0; mf < 2; mf++)
                ldmx4(ah[mf], st + a_off0 + hb + (uint32_t)(mf * 16 * 80));
            uint32_t bh[8][2];
#pragma unroll
            for (int nf2 = 0; nf2 < 4; nf2++) {
                uint32_t r4[4];
                ldmx4(r4, st + ATILE_B + b_off0 + hb + (uint32_t)(nf2 * 16 * 80));
                bh[nf2 * 2][0] = r4[0]; bh[nf2 * 2][1] = r4[1];
                bh[nf2 * 2 + 1][0] = r4[2]; bh[nf2 * 2 + 1][1] = r4[3];
            }
#pragma unroll
            for (int mf = 0; mf < 2; mf++)
#pragma unroll
                for (int nf = 0; nf < 8; nf++)
                    mma16816h(acc[mf][nf], ah[mf], bh[nf]);
        }
    }

    const int lr = lane >> 2, lc = (lane & 3) * 2;
#pragma unroll
    for (int mf = 0; mf < 2; mf++) {
#pragma unroll
        for (int nf = 0; nf < 8; nf++) {
            const int col = bn + wc * 64 + nf * 8 + lc;
            const float bx = bias[col], by = bias[col + 1];
            const int r0 = bm + wr * 32 + mf * 16 + lr;
#pragma unroll
            for (int half = 0; half < 2; half++) {
                const int r = r0 + half * 8;
                const float a = acc[mf][nf][half * 2 + 0] + bx;
                const float c2 = acc[mf][nf][half * 2 + 1] + by;
                if (CHEAD) {
                    const int b = r >> 11, n = r & (NSEQ - 1);
                    const int hh = col >> 6, d0 = col & 63;
                    const size_t hoff = (((size_t)(b * NHEADS + hh) * NSEQ + n) << 6) + d0;
                    if (z == 0) {
                        // q: fp16, pre-scaled by 0.125
                        *reinterpret_cast<__half2*>(FH + hoff) =
                            __floats2half2_rn(a * 0.125f, c2 * 0.125f);
                    } else if (z == 1) {
                        // k: fp32 output + fp16
                        float2 o; o.x = a; o.y = c2;
                        *reinterpret_cast<float2*>(C + hoff) = o;
                        *reinterpret_cast<__half2*>(FH + SLOT + hoff) =
                            __floats2half2_rn(a, c2);
                    } else {
                        // v: fp32 output + transposed fp16
                        float2 o; o.x = a; o.y = c2;
                        *reinterpret_cast<float2*>(C + hoff) = o;
                        const size_t tb = ((size_t)(b * NHEADS + hh) * HD + d0) * NSEQ + n;
                        FH[2 * SLOT + tb] = __float2half_rn(a);
                        FH[2 * SLOT + tb + NSEQ] = __float2half_rn(c2);
                    }
                } else {
                    float2 o; o.x = a; o.y = c2;
                    *reinterpret_cast<float2*>(C + (size_t)r * DIMC + col) = o;
                }
            }
        }
    }
}

// ---------------------------------------------------------------------------
// Flash attention, single fp16 operands (fp32 accum), split-KV (2 warp-groups).
// S = Q·K^T (Q pre-scaled);  O += P·V^T.  Output: fp16 row-major.
// Group g handles K-tiles [16g,16g+16) for the same 128 Q-rows, own KV
// double-buffer + named barrier. Exact fp32 (m,l,o) merge in smem at end.
// ---------------------------------------------------------------------------
#define FPITCH  144
#define FQT_B   (128 * FPITCH)           // 18432 Q tile
#define FT_B    (64 * FPITCH)            // 9216 per K/V tile
#define FSTG_B  (2 * FT_B)               // 18432 per stage (K, V)
#define FGRP_B  (2 * FSTG_B)             // 36864 per group (double buffer)
#define FLASH_SMEM (FQT_B + 2 * FGRP_B)  // 92160
#define MERGE_OFF (FQT_B + FGRP_B)       // merge buffers overlay group-1 region
#define OBUF_STRIDE 68                   // floats per row (padded)

__device__ __forceinline__ void load_kv(uint32_t st,
                                        const __half* khi, const __half* vthi,
                                        int bh, int kt, int gtid) {
#pragma unroll
    for (int it = 0; it < 2; it++) {
        const int idx = gtid + it * 256;           // 64 rows x 8 segs = 512
        const int row = idx >> 3, seg = idx & 7;
        const uint32_t so = (uint32_t)(row * FPITCH + seg * 16);
        const size_t gk = (size_t)bh * NSEQ * HD + (size_t)(kt * 64 + row) * HD + seg * 8;
        const size_t gv = ((size_t)bh * HD + row) * NSEQ + kt * 64 + seg * 8;
        cp16(st + 0 * FT_B + so, khi + gk);
        cp16(st + 1 * FT_B + so, vthi + gv);
    }
    CP_COMMIT();
}

__global__ void __launch_bounds__(512, 1) flash_mma(
    const __half* __restrict__ FH, __half* __restrict__ O) {
    extern __shared__ __align__(128) char smem[];
    const uint32_t sbase = (uint32_t)__cvta_generic_to_shared(smem);
    const int tid = threadIdx.x, wid = tid >> 5, lane = tid & 31;
    const int g = wid >> 3;           // warp group 0/1
    const int gw = wid & 7;           // warp within group
    const int gtid = tid & 255;
    const int bh = blockIdx.y;
    const int q0 = blockIdx.x * 128;

    const __half* qh = FH;
    const __half* kh = FH + SLOT;
    const __half* vth = FH + 2 * SLOT;

    // Q tile -> smem (128 rows x 8 segs), all 512 threads
    {
        const int idx = tid;
        const int row = idx >> 2, seg = (idx & 3) * 2;   // 2 cp per thread
        const uint32_t so = (uint32_t)(row * FPITCH + seg * 16);
        const size_t gq = (size_t)bh * NSEQ * HD + (size_t)(q0 + row) * HD + seg * 8;
        cp16(sbase + so, qh + gq);
        cp16(sbase + so + 16, qh + gq + 8);
    }
    CP_COMMIT();

    const uint32_t stgbase = sbase + FQT_B + (uint32_t)g * FGRP_B;
    const int kt0 = g * 16;
    load_kv(stgbase, kh, vth, bh, kt0 + 0, gtid);
    load_kv(stgbase + FSTG_B, kh, vth, bh, kt0 + 1, gtid);

    CP_WAIT(2);        // Q group complete
    __syncthreads();

    // Q fragments (A operand), 4 k16 frags
    uint32_t qf[4][4];
    {
        const int a_r = gw * 16 + (lane & 15);
        const uint32_t a0 = (uint32_t)(a_r * FPITCH + ((lane >> 4) << 4));
#pragma unroll
        for (int kf = 0; kf < 4; kf++)
            ldmx4(qf[kf], sbase + a0 + kf * 32);
    }

    const uint32_t b_off0 =
        (uint32_t)(((lane & 7) + ((lane >> 4) << 3)) * FPITCH + (((lane >> 3) & 1) << 4));
    const int barid = 1 + g;

    float o[8][4];
#pragma unroll
    for (int nf = 0; nf < 8; nf++)
#pragma unroll
        for (int t = 0; t < 4; t++) o[nf][t] = 0.f;
    float mA = -1e30f, mB = -1e30f, lA = 0.f, lB = 0.f;

    for (int t = 0; t < 16; t++) {
        if (t < 15) { CP_WAIT(1); } else { CP_WAIT(0); }
        BAR_SYNC(barid, 256);
        const uint32_t st = stgbase + (uint32_t)(t & 1) * FSTG_B;

        // ---- S = Q · K^T (Q pre-scaled by 0.125) ----
        float s[8][4];
#pragma unroll
        for (int nf = 0; nf < 8; nf++)
#pragma unroll
            for (int tt = 0; tt < 4; tt++) s[nf][tt] = 0.f;
#pragma unroll
        for (int kf = 0; kf < 4; kf++) {
#pragma unroll
            for (int nf2 = 0; nf2 < 4; nf2++) {
                const uint32_t bo = b_off0 + (uint32_t)(nf2 * 16 * FPITCH) + kf * 32;
                uint32_t kh4[4];
                ldmx4(kh4, st + 0 * FT_B + bo);
                mma16816h(s[nf2 * 2], qf[kf], &kh4[0]);
                mma16816h(s[nf2 * 2 + 1], qf[kf], &kh4[2]);
            }
        }

        // ---- online softmax (rows rA = lane>>2, rB = rA+8) ----
        float rmA = -1e30f, rmB = -1e30f;
#pragma unroll
        for (int nf = 0; nf < 8; nf++) {
            rmA = fmaxf(rmA, fmaxf(s[nf][0], s[nf][1]));
            rmB = fmaxf(rmB, fmaxf(s[nf][2], s[nf][3]));
        }
        rmA = fmaxf(rmA, __shfl_xor_sync(0xffffffffu, rmA, 1, 4));
        rmA = fmaxf(rmA, __shfl_xor_sync(0xffffffffu, rmA, 2, 4));
        rmB = fmaxf(rmB, __shfl_xor_sync(0xffffffffu, rmB, 1, 4));
        rmB = fmaxf(rmB, __shfl_xor_sync(0xffffffffu, rmB, 2, 4));
        const float mnA = fmaxf(mA, rmA);
        const float mnB = fmaxf(mB, rmB);
        const float cA = __expf(mA - mnA);
        const float cB = __expf(mB - mnB);
        mA = mnA; mB = mnB;
        float sumA = 0.f, sumB = 0.f;
#pragma unroll
        for (int nf = 0; nf < 8; nf++) {
            s[nf][0] = __expf(s[nf][0] - mnA);
            s[nf][1] = __expf(s[nf][1] - mnA);
            s[nf][2] = __expf(s[nf][2] - mnB);
            s[nf][3] = __expf(s[nf][3] - mnB);
            sumA += s[nf][0] + s[nf][1];
            sumB += s[nf][2] + s[nf][3];
        }
        sumA += __shfl_xor_sync(0xffffffffu, sumA, 1, 4);
        sumA += __shfl_xor_sync(0xffffffffu, sumA, 2, 4);
        sumB += __shfl_xor_sync(0xffffffffu, sumB, 1, 4);
        sumB += __shfl_xor_sync(0xffffffffu, sumB, 2, 4);
        lA = lA * cA + sumA;
        lB = lB * cB + sumB;
#pragma unroll
        for (int nf = 0; nf < 8; nf++) {
            o[nf][0] *= cA; o[nf][1] *= cA;
            o[nf][2] *= cB; o[nf][3] *= cB;
        }

        // ---- O += P · V^T (P fp16, register repack) ----
#pragma unroll
        for (int kf = 0; kf < 4; kf++) {
            uint32_t pah[4];
#pragma unroll
            for (int blk = 0; blk < 2; blk++) {
                pah[blk * 2 + 0] = pack_h2(s[2 * kf + blk][0], s[2 * kf + blk][1]);
                pah[blk * 2 + 1] = pack_h2(s[2 * kf + blk][2], s[2 * kf + blk][3]);
            }
#pragma unroll
            for (int nf2 = 0; nf2 < 4; nf2++) {
                const uint32_t bo = b_off0 + (uint32_t)(nf2 * 16 * FPITCH) + kf * 32;
                uint32_t vh4[4];
                ldmx4(vh4, st + 1 * FT_B + bo);
                mma16816h(o[nf2 * 2], pah, &vh4[0]);
                mma16816h(o[nf2 * 2 + 1], pah, &vh4[2]);
            }
        }

        BAR_SYNC(barid, 256);    // group done reading stage t&1
        if (t + 2 < 16)
            load_kv(st, kh, vth, bh, kt0 + t + 2, gtid);
    }

    // ---- merge the two KV-halves (exact fp32) ----
    float* mbuf = reinterpret_cast<float*>(smem + MERGE_OFF);            // 128
    float* lbuf = reinterpret_cast<float*>(smem + MERGE_OFF + 512);      // 128
    float* obuf = reinterpret_cast<float*>(smem + MERGE_OFF + 1024);     // 128 x 68
    const int lr = gw * 16 + (lane >> 2);     // local row 0..127 (rA)
    if (g == 1) {
        if ((lane & 3) == 0) {
            mbuf[lr] = mA; lbuf[lr] = lA;
            mbuf[lr + 8] = mB; lbuf[lr + 8] = lB;
        }
#pragma unroll
        for (int nf = 0; nf < 8; nf++) {
            const int col = nf * 8 + (lane & 3) * 2;
            float2 pa; pa.x = o[nf][0]; pa.y = o[nf][1];
            float2 pb; pb.x = o[nf][2]; pb.y = o[nf][3];
            *reinterpret_cast<float2*>(&obuf[lr * OBUF_STRIDE + col]) = pa;
            *reinterpret_cast<float2*>(&obuf[(lr + 8) * OBUF_STRIDE + col]) = pb;
        }
    }
    __syncthreads();
    if (g == 0) {
        const float m1A = mbuf[lr], l1A = lbuf[lr];
        const float m1B = mbuf[lr + 8], l1B = lbuf[lr + 8];
        const float mfA = fmaxf(mA, m1A);
        const float mfB = fmaxf(mB, m1B);
        const float e0A = __expf(mA - mfA), e1A = __expf(m1A - mfA);
        const float e0B = __expf(mB - mfB), e1B = __expf(m1B - mfB);
        const float invA = 1.0f / (lA * e0A + l1A * e1A);
        const float invB = 1.0f / (lB * e0B + l1B * e1B);
        const int b = bh >> 4, h = bh & 15;
        const int rA = q0 + lr;
        const int rB = rA + 8;
        const size_t baseA = ((size_t)(b * NSEQ + rA)) * DIMC + h * 64;
        const size_t baseB = ((size_t)(b * NSEQ + rB)) * DIMC + h * 64;
#pragma unroll
        for (int nf = 0; nf < 8; nf++) {
            const int col = nf * 8 + (lane & 3) * 2;
            const float2 p1A = *reinterpret_cast<const float2*>(&obuf[lr * OBUF_STRIDE + col]);
            const float2 p1B =
                *reinterpret_cast<const float2*>(&obuf[(lr + 8) * OBUF_STRIDE + col]);
            const float a0 = (o[nf][0] * e0A + p1A.x * e1A) * invA;
            const float a1 = (o[nf][1] * e0A + p1A.y * e1A) * invA;
            const float b0 = (o[nf][2] * e0B + p1B.x * e1B) * invB;
            const float b1 = (o[nf][3] * e0B + p1B.y * e1B) * invB;
            *reinterpret_cast<__half2*>(O + baseA + col) = __floats2half2_rn(a0, a1);
            *reinterpret_cast<__half2*>(O + baseB + col) = __floats2half2_rn(b0, b1);
        }
    }
}

// ---------------------------------------------------------------------------
extern "C" void kernel_launch(void* const* d_in, const int* in_sizes, int n_in,
                              void* d_out, int out_size) {
    const float* q    = (const float*)d_in[0];
    const float* k    = (const float*)d_in[1];
    const float* v    = (const float*)d_in[2];
    const float* gq   = (const float*)d_in[3];
    const float* bqln = (const float*)d_in[4];
    const float* gk   = (const float*)d_in[5];
    const float* bkln = (const float*)d_in[6];
    const float* gv   = (const float*)d_in[7];
    const float* bvln = (const float*)d_in[8];
    const float* Wq   = (const float*)d_in[9];
    const float* bq   = (const float*)d_in[10];
    const float* Wk   = (const float*)d_in[11];
    const float* bk   = (const float*)d_in[12];
    const float* Wv   = (const float*)d_in[13];
    const float* bv   = (const float*)d_in[14];
    const float* Wp   = (const float*)d_in[15];
    const float* bp   = (const float*)d_in[16];

    float* out = (float*)d_out;
    float* kh  = out + (size_t)MROWS * DIMC;
    float* vh  = kh + (size_t)MROWS * DIMC;

    __half *ln, *wt, *fh, *os;
    float* dummy;
    cudaGetSymbolAddress((void**)&ln, g_ln);
    cudaGetSymbolAddress((void**)&wt, g_wt);
    cudaGetSymbolAddress((void**)&fh, g_fh);
    cudaGetSymbolAddress((void**)&os, g_os);
    cudaGetSymbolAddress((void**)&dummy, g_dummy);

    // 1) Fused LayerNorm -> fp16 (q/k/v in one launch)
    ln_fused<<<dim3(MROWS, 3), 256>>>(q, k, v, gq, bqln, gk, bkln, gv, bvln, ln);

    // 2) Weight transpose to fp16
    wsplit_kernel<<<dim3(32, 32, 4), dim3(32, 8)>>>(Wq, Wk, Wv, Wp, wt);

    // 3) QKV projection (fp16, fp32 accum), emits flash-ready fp16
    cudaFuncSetAttribute(mma_gemm<true>, cudaFuncAttributeMaxDynamicSharedMemorySize, GEMM_SMEM);
    cudaFuncSetAttribute(mma_gemm<false>, cudaFuncAttributeMaxDynamicSharedMemorySize, GEMM_SMEM);
    mma_gemm<true><<<dim3(4, 32, 3), 512, GEMM_SMEM>>>(
        ln, wt, bq, bk, bv, dummy, kh, vh, fh);

    // 4) Flash attention (fp16, split-KV) -> fp16 row-major
    cudaFuncSetAttribute(flash_mma, cudaFuncAttributeMaxDynamicSharedMemorySize, FLASH_SMEM);
    flash_mma<<<dim3(NSEQ / 128, BHNUM), 512, FLASH_SMEM>>>(fh, os);

    // 5) Output projection (fp16, fp32 accum)
    mma_gemm<false><<<dim3(4, 32, 1), 512, GEMM_SMEM>>>(
        os, wt + 3ull * DIMC * DIMC, bp, bp, bp, out, out, out, fh);
}

// round 17
// speedup vs baseline: 6.4516x; 1.0138x over previous
#include <cuda_runtime.h>
#include <cuda_fp16.h>
#include <cstdint>
#include <math.h>

#define DIMC   1024
#define NSEQ   2048
#define BATCH  2
#define NHEADS 16
#define HD     64
#define MROWS  (BATCH * NSEQ)     // 4096
#define BHNUM  (BATCH * NHEADS)   // 32
#define SLOT   ((size_t)BHNUM * NSEQ * HD)   // elements per q/k/v slot

// ---------------------------------------------------------------------------
// Scratch (static device globals — no runtime allocation allowed)
// ---------------------------------------------------------------------------
__device__ __half g_ln[3ull * MROWS * DIMC];      // LN out, fp16
__device__ __half g_wt[4ull * DIMC * DIMC];       // W transposed [N][K], fp16
__device__ __half g_fh[3ull * SLOT];              // q(head,scaled)/k(head)/vT, fp16
__device__ __half g_os[(size_t)MROWS * DIMC];     // flash out, row-major fp16
__device__ float g_dummy[(size_t)MROWS * DIMC];   // unused fp32 sink for z=0

// ---------------------------------------------------------------------------
// PTX helpers (baseline ISA only)
// ---------------------------------------------------------------------------
__device__ __forceinline__ void cp16(uint32_t s, const void* g) {
    asm volatile("cp.async.cg.shared.global [%0], [%1], 16;\n"
                 :: "r"(s), "l"(__cvta_generic_to_global(g)) : "memory");
}
#define CP_COMMIT() asm volatile("cp.async.commit_group;\n" ::: "memory")
#define CP_WAIT(n)  asm volatile("cp.async.wait_group %0;\n" :: "n"(n) : "memory")
#define BAR_SYNC(id, cnt) \
    asm volatile("bar.sync %0, %1;" :: "r"(id), "r"(cnt) : "memory")

__device__ __forceinline__ void ldmx4(uint32_t* r, uint32_t addr) {
    asm volatile("ldmatrix.sync.aligned.m8n8.x4.shared.b16 {%0,%1,%2,%3}, [%4];"
                 : "=r"(r[0]), "=r"(r[1]), "=r"(r[2]), "=r"(r[3]) : "r"(addr));
}

__device__ __forceinline__ void mma16816h(float* c, const uint32_t* a, const uint32_t* b) {
    asm volatile("mma.sync.aligned.m16n8k16.row.col.f32.f16.f16.f32 "
                 "{%0,%1,%2,%3}, {%4,%5,%6,%7}, {%8,%9}, {%0,%1,%2,%3};"
                 : "+f"(c[0]), "+f"(c[1]), "+f"(c[2]), "+f"(c[3])
                 : "r"(a[0]), "r"(a[1]), "r"(a[2]), "r"(a[3]), "r"(b[0]), "r"(b[1]));
}

__device__ __forceinline__ uint32_t pack_h2(float a, float b) {
    __half2 t = __floats2half2_rn(a, b);
    return *reinterpret_cast<uint32_t*>(&t);
}

// ex2.approx: exponentials are computed in log2 domain (log2e folded into Q scale)
__device__ __forceinline__ float ex2f(float x) {
    float y;
    asm("ex2.approx.f32 %0, %1;" : "=f"(y) : "f"(x));
    return y;
}

// ---------------------------------------------------------------------------
// Fused LayerNorm -> fp16 for q/k/v (z = blockIdx.y)
// ---------------------------------------------------------------------------
__global__ void __launch_bounds__(256) ln_fused(
    const float* __restrict__ q, const float* __restrict__ k, const float* __restrict__ v,
    const float* __restrict__ gq, const float* __restrict__ bq,
    const float* __restrict__ gk, const float* __restrict__ bk,
    const float* __restrict__ gv, const float* __restrict__ bv,
    __half* __restrict__ out_base) {
    const int z = blockIdx.y;
    const float* x = (z == 0) ? q : (z == 1) ? k : v;
    const float* g = (z == 0) ? gq : (z == 1) ? gk : gv;
    const float* b = (z == 0) ? bq : (z == 1) ? bk : bv;
    __half* outp = out_base + (size_t)z * MROWS * DIMC;

    const int row = blockIdx.x;
    const int tid = threadIdx.x;
    const float4 vv = reinterpret_cast<const float4*>(x + (size_t)row * DIMC)[tid];
    float s  = vv.x + vv.y + vv.z + vv.w;
    float ss = vv.x * vv.x + vv.y * vv.y + vv.z * vv.z + vv.w * vv.w;
#pragma unroll
    for (int off = 16; off > 0; off >>= 1) {
        s  += __shfl_xor_sync(0xffffffffu, s, off);
        ss += __shfl_xor_sync(0xffffffffu, ss, off);
    }
    __shared__ float rs[8], rss[8];
    if ((tid & 31) == 0) { rs[tid >> 5] = s; rss[tid >> 5] = ss; }
    __syncthreads();
    float tot = 0.f, totss = 0.f;
#pragma unroll
    for (int i = 0; i < 8; i++) { tot += rs[i]; totss += rss[i]; }
    const float mean = tot * (1.0f / DIMC);
    const float var  = totss * (1.0f / DIMC) - mean * mean;
    const float rstd = rsqrtf(var + 1e-5f);
    const float4 g4 = reinterpret_cast<const float4*>(g)[tid];
    const float4 b4 = reinterpret_cast<const float4*>(b)[tid];
    float o[4];
    o[0] = (vv.x - mean) * rstd * g4.x + b4.x;
    o[1] = (vv.y - mean) * rstd * g4.y + b4.y;
    o[2] = (vv.z - mean) * rstd * g4.z + b4.z;
    o[3] = (vv.w - mean) * rstd * g4.w + b4.w;
    __half2* H = reinterpret_cast<__half2*>(outp + (size_t)row * DIMC);
    H[tid * 2]     = __floats2half2_rn(o[0], o[1]);
    H[tid * 2 + 1] = __floats2half2_rn(o[2], o[3]);
}

// ---------------------------------------------------------------------------
// Weight transpose to fp16: Wt[n][k] = fp16(W[k][n]); 4 weights via z.
// ---------------------------------------------------------------------------
__global__ void __launch_bounds__(256) wsplit_kernel(const float* __restrict__ W0,
                                                     const float* __restrict__ W1,
                                                     const float* __restrict__ W2,
                                                     const float* __restrict__ W3,
                                                     __half* __restrict__ hi) {
    const int z = blockIdx.z;
    const float* W = (z == 0) ? W0 : (z == 1) ? W1 : (z == 2) ? W2 : W3;
    const size_t ob = (size_t)z * DIMC * DIMC;
    __shared__ float t[32][33];
    const int tx = threadIdx.x, ty = threadIdx.y;
    const int n0 = blockIdx.x * 32, k0 = blockIdx.y * 32;
#pragma unroll
    for (int r = 0; r < 4; r++)
        t[ty + 8 * r][tx] = W[(size_t)(k0 + ty + 8 * r) * DIMC + n0 + tx];
    __syncthreads();
#pragma unroll
    for (int r = 0; r < 4; r++) {
        const float x = t[tx][ty + 8 * r];
        hi[ob + (size_t)(n0 + ty + 8 * r) * DIMC + k0 + tx] = __float2half_rn(x);
    }
}

// ---------------------------------------------------------------------------
// mma.sync fp16 GEMM (single-term operands, fp32 accum):
// C[4096,1024] = A @ Wt^T + bias. Tile 128(M)x256(N), BK=32, 512 threads,
// 16 warps (4x4), warp tile 32x64. 3-stage cp.async pipeline, ONE barrier/iter.
// CHEAD epilogue emits fp16 for flash (q scaled by 0.125*log2e / k / vT).
// ---------------------------------------------------------------------------
#define ATILE_B (128 * 80)           // 10240
#define BTILE_B (256 * 80)           // 20480
#define STAGE_B (ATILE_B + BTILE_B)           // 30720
#define GEMM_SMEM (3 * STAGE_B)               // 92160
#define QSCALE 0.18033688f           // 0.125 * log2(e)

__device__ __forceinline__ void load_stage(uint32_t st,
                                           const __half* A, const __half* B,
                                           int bm, int bn, int k0, int tid) {
    {                                            // A: 128 rows x 4 segs = 512
        const int row = tid >> 2, seg = tid & 3;
        const uint32_t so = (uint32_t)(row * 80 + seg * 16);
        cp16(st + so, A + (size_t)(bm + row) * DIMC + k0 + seg * 8);
    }
#pragma unroll
    for (int it = 0; it < 2; it++) {             // B: 256 rows x 4 segs = 1024
        const int idx = tid + it * 512;
        const int row = idx >> 2, seg = idx & 3;
        const uint32_t so = (uint32_t)(row * 80 + seg * 16);
        cp16(st + ATILE_B + so, B + (size_t)(bn + row) * DIMC + k0 + seg * 8);
    }
    CP_COMMIT();
}

template <bool CHEAD>
__global__ void __launch_bounds__(512, 1) mma_gemm(
    const __half* __restrict__ A_base, const __half* __restrict__ B_base,
    const float* b0, const float* b1, const float* b2,
    float* C0, float* C1, float* C2,
    __half* FH) {
    extern __shared__ __align__(128) char smem[];
    const uint32_t sbase = (uint32_t)__cvta_generic_to_shared(smem);
    const int tid = threadIdx.x, wid = tid >> 5, lane = tid & 31;
    const int z = blockIdx.z;
    const __half* A = A_base + (size_t)z * MROWS * DIMC;
    const __half* B = B_base + (size_t)z * DIMC * DIMC;
    const float* bias = (z == 0) ? b0 : (z == 1) ? b1 : b2;
    float* C = (z == 0) ? C0 : (z == 1) ? C1 : C2;
    const int bm = blockIdx.y * 128;
    const int bn = blockIdx.x * 256;
    const int wr = wid >> 2;          // 0..3 -> m offset 32*wr
    const int wc = wid & 3;           // 0..3 -> n offset 64*wc

    float acc[2][8][4];
#pragma unroll
    for (int i = 0; i < 2; i++)
#pragma unroll
        for (int j = 0; j < 8; j++)
#pragma unroll
            for (int t = 0; t < 4; t++) acc[i][j][t] = 0.f;

    const int a_r = wr * 32 + (lane & 15);
    const uint32_t a_off0 = (uint32_t)(a_r * 80 + ((lane >> 4) << 4));
    const int b_n = wc * 64 + (lane & 7) + ((lane >> 4) << 3);
    const uint32_t b_off0 = (uint32_t)(b_n * 80 + (((lane >> 3) & 1) << 4));

    load_stage(sbase, A, B, bm, bn, 0, tid);
    load_stage(sbase + STAGE_B, A, B, bm, bn, 32, tid);

    for (int i = 0; i < 32; i++) {
        if (i < 31) { CP_WAIT(1); } else { CP_WAIT(0); }
        __syncthreads();   // stage i%3 ready; stage (i+2)%3 free
        if (i + 2 < 32)
            load_stage(sbase + (uint32_t)((i + 2) % 3) * STAGE_B,
                       A, B, bm, bn, (i + 2) * 32, tid);
        const uint32_t st = sbase + (uint32_t)(i % 3) * STAGE_B;
#pragma unroll
        for (int h = 0; h < 2; h++) {
            const uint32_t hb = (uint32_t)(h * 32);
            uint32_t ah[2][4];
#pragma unroll
            for (int mf = 0; mf < 2; mf++)
                ldmx4(ah[mf], st + a_off0 + hb + (uint32_t)(mf * 16 * 80));
            uint32_t bh[8][2];
#pragma unroll
            for (int nf2 = 0; nf2 < 4; nf2++) {
                uint32_t r4[4];
                ldmx4(r4, st + ATILE_B + b_off0 + hb + (uint32_t)(nf2 * 16 * 80));
                bh[nf2 * 2][0] = r4[0]; bh[nf2 * 2][1] = r4[1];
                bh[nf2 * 2 + 1][0] = r4[2]; bh[nf2 * 2 + 1][1] = r4[3];
            }
#pragma unroll
            for (int mf = 0; mf < 2; mf++)
#pragma unroll
                for (int nf = 0; nf < 8; nf++)
                    mma16816h(acc[mf][nf], ah[mf], bh[nf]);
        }
    }

    const int lr = lane >> 2, lc = (lane & 3) * 2;
#pragma unroll
    for (int mf = 0; mf < 2; mf++) {
#pragma unroll
        for (int nf = 0; nf < 8; nf++) {
            const int col = bn + wc * 64 + nf * 8 + lc;
            const float bx = bias[col], by = bias[col + 1];
            const int r0 = bm + wr * 32 + mf * 16 + lr;
#pragma unroll
            for (int half = 0; half < 2; half++) {
                const int r = r0 + half * 8;
                const float a = acc[mf][nf][half * 2 + 0] + bx;
                const float c2 = acc[mf][nf][half * 2 + 1] + by;
                if (CHEAD) {
                    const int b = r >> 11, n = r & (NSEQ - 1);
                    const int hh = col >> 6, d0 = col & 63;
                    const size_t hoff = (((size_t)(b * NHEADS + hh) * NSEQ + n) << 6) + d0;
                    if (z == 0) {
                        // q: fp16, pre-scaled by 0.125*log2e (log2-domain logits)
                        *reinterpret_cast<__half2*>(FH + hoff) =
                            __floats2half2_rn(a * QSCALE, c2 * QSCALE);
                    } else if (z == 1) {
                        // k: fp32 output + fp16
                        float2 o; o.x = a; o.y = c2;
                        *reinterpret_cast<float2*>(C + hoff) = o;
                        *reinterpret_cast<__half2*>(FH + SLOT + hoff) =
                            __floats2half2_rn(a, c2);
                    } else {
                        // v: fp32 output + transposed fp16
                        float2 o; o.x = a; o.y = c2;
                        *reinterpret_cast<float2*>(C + hoff) = o;
                        const size_t tb = ((size_t)(b * NHEADS + hh) * HD + d0) * NSEQ + n;
                        FH[2 * SLOT + tb] = __float2half_rn(a);
                        FH[2 * SLOT + tb + NSEQ] = __float2half_rn(c2);
                    }
                } else {
                    float2 o; o.x = a; o.y = c2;
                    *reinterpret_cast<float2*>(C + (size_t)r * DIMC + col) = o;
                }
            }
        }
    }
}

// ---------------------------------------------------------------------------
// Flash attention, fp16 operands, log2-domain softmax, row-sum via MMA.
// Split-KV (2 warp-groups of 8); exact fp32 (m,l,o) merge in smem at end.
// ---------------------------------------------------------------------------
#define FPITCH  144
#define FQT_B   (128 * FPITCH)           // 18432 Q tile
#define FT_B    (64 * FPITCH)            // 9216 per K/V tile
#define FSTG_B  (2 * FT_B)               // 18432 per stage (K, V)
#define FGRP_B  (2 * FSTG_B)             // 36864 per group (double buffer)
#define FLASH_SMEM (FQT_B + 2 * FGRP_B)  // 92160
#define MERGE_OFF (FQT_B + FGRP_B)       // merge buffers overlay group-1 region
#define OBUF_STRIDE 68                   // floats per row (padded)

__device__ __forceinline__ void load_kv(uint32_t st,
                                        const __half* khi, const __half* vthi,
                                        int bh, int kt, int gtid) {
#pragma unroll
    for (int it = 0; it < 2; it++) {
        const int idx = gtid + it * 256;           // 64 rows x 8 segs = 512
        const int row = idx >> 3, seg = idx & 7;
        const uint32_t so = (uint32_t)(row * FPITCH + seg * 16);
        const size_t gk = (size_t)bh * NSEQ * HD + (size_t)(kt * 64 + row) * HD + seg * 8;
        const size_t gv = ((size_t)bh * HD + row) * NSEQ + kt * 64 + seg * 8;
        cp16(st + 0 * FT_B + so, khi + gk);
        cp16(st + 1 * FT_B + so, vthi + gv);
    }
    CP_COMMIT();
}

__global__ void __launch_bounds__(512, 1) flash_mma(
    const __half* __restrict__ FH, __half* __restrict__ O) {
    extern __shared__ __align__(128) char smem[];
    const uint32_t sbase = (uint32_t)__cvta_generic_to_shared(smem);
    const int tid = threadIdx.x, wid = tid >> 5, lane = tid & 31;
    const int g = wid >> 3;           // warp group 0/1
    const int gw = wid & 7;           // warp within group
    const int gtid = tid & 255;
    const int bh = blockIdx.y;
    const int q0 = blockIdx.x * 128;

    const __half* qh = FH;
    const __half* kh = FH + SLOT;
    const __half* vth = FH + 2 * SLOT;

    // Q tile -> smem (128 rows x 8 segs), all 512 threads
    {
        const int idx = tid;
        const int row = idx >> 2, seg = (idx & 3) * 2;   // 2 cp per thread
        const uint32_t so = (uint32_t)(row * FPITCH + seg * 16);
        const size_t gq = (size_t)bh * NSEQ * HD + (size_t)(q0 + row) * HD + seg * 8;
        cp16(sbase + so, qh + gq);
        cp16(sbase + so + 16, qh + gq + 8);
    }
    CP_COMMIT();

    const uint32_t stgbase = sbase + FQT_B + (uint32_t)g * FGRP_B;
    const int kt0 = g * 16;
    load_kv(stgbase, kh, vth, bh, kt0 + 0, gtid);
    load_kv(stgbase + FSTG_B, kh, vth, bh, kt0 + 1, gtid);

    CP_WAIT(2);        // Q group complete
    __syncthreads();

    // Q fragments (A operand), 4 k16 frags
    uint32_t qf[4][4];
    {
        const int a_r = gw * 16 + (lane & 15);
        const uint32_t a0 = (uint32_t)(a_r * FPITCH + ((lane >> 4) << 4));
#pragma unroll
        for (int kf = 0; kf < 4; kf++)
            ldmx4(qf[kf], sbase + a0 + kf * 32);
    }

    const uint32_t b_off0 =
        (uint32_t)(((lane & 7) + ((lane >> 4) << 3)) * FPITCH + (((lane >> 3) & 1) << 4));
    const int barid = 1 + g;
    const uint32_t ones2[2] = {0x3C003C00u, 0x3C003C00u};   // fp16 1.0 x4

    float o[8][4];
#pragma unroll
    for (int nf = 0; nf < 8; nf++)
#pragma unroll
        for (int t = 0; t < 4; t++) o[nf][t] = 0.f;
    float ls[4] = {0.f, 0.f, 0.f, 0.f};   // row-sum accumulator (via MMA)
    float mA = -1e30f, mB = -1e30f;

    for (int t = 0; t < 16; t++) {
        if (t < 15) { CP_WAIT(1); } else { CP_WAIT(0); }
        BAR_SYNC(barid, 256);
        const uint32_t st = stgbase + (uint32_t)(t & 1) * FSTG_B;

        // ---- S = Q · K^T (log2-domain: Q pre-scaled by 0.125*log2e) ----
        float s[8][4];
#pragma unroll
        for (int nf = 0; nf < 8; nf++)
#pragma unroll
            for (int tt = 0; tt < 4; tt++) s[nf][tt] = 0.f;
#pragma unroll
        for (int kf = 0; kf < 4; kf++) {
#pragma unroll
            for (int nf2 = 0; nf2 < 4; nf2++) {
                const uint32_t bo = b_off0 + (uint32_t)(nf2 * 16 * FPITCH) + kf * 32;
                uint32_t kh4[4];
                ldmx4(kh4, st + 0 * FT_B + bo);
                mma16816h(s[nf2 * 2], qf[kf], &kh4[0]);
                mma16816h(s[nf2 * 2 + 1], qf[kf], &kh4[2]);
            }
        }

        // ---- online softmax, log2 domain (rows rA = lane>>2, rB = rA+8) ----
        float rmA = -1e30f, rmB = -1e30f;
#pragma unroll
        for (int nf = 0; nf < 8; nf++) {
            rmA = fmaxf(rmA, fmaxf(s[nf][0], s[nf][1]));
            rmB = fmaxf(rmB, fmaxf(s[nf][2], s[nf][3]));
        }
        rmA = fmaxf(rmA, __shfl_xor_sync(0xffffffffu, rmA, 1, 4));
        rmA = fmaxf(rmA, __shfl_xor_sync(0xffffffffu, rmA, 2, 4));
        rmB = fmaxf(rmB, __shfl_xor_sync(0xffffffffu, rmB, 1, 4));
        rmB = fmaxf(rmB, __shfl_xor_sync(0xffffffffu, rmB, 2, 4));
        const float mnA = fmaxf(mA, rmA);
        const float mnB = fmaxf(mB, rmB);
        const float cA = ex2f(mA - mnA);
        const float cB = ex2f(mB - mnB);
        mA = mnA; mB = mnB;
#pragma unroll
        for (int nf = 0; nf < 8; nf++) {
            s[nf][0] = ex2f(s[nf][0] - mnA);
            s[nf][1] = ex2f(s[nf][1] - mnA);
            s[nf][2] = ex2f(s[nf][2] - mnB);
            s[nf][3] = ex2f(s[nf][3] - mnB);
        }
#pragma unroll
        for (int nf = 0; nf < 8; nf++) {
            o[nf][0] *= cA; o[nf][1] *= cA;
            o[nf][2] *= cB; o[nf][3] *= cB;
        }
        ls[0] *= cA; ls[1] *= cA; ls[2] *= cB; ls[3] *= cB;

        // ---- O += P · V^T;  ls += P · ones (row sums on the tensor pipe) ----
#pragma unroll
        for (int kf = 0; kf < 4; kf++) {
            uint32_t pah[4];
#pragma unroll
            for (int blk = 0; blk < 2; blk++) {
                pah[blk * 2 + 0] = pack_h2(s[2 * kf + blk][0], s[2 * kf + blk][1]);
                pah[blk * 2 + 1] = pack_h2(s[2 * kf + blk][2], s[2 * kf + blk][3]);
            }
            mma16816h(ls, pah, ones2);
#pragma unroll
            for (int nf2 = 0; nf2 < 4; nf2++) {
                const uint32_t bo = b_off0 + (uint32_t)(nf2 * 16 * FPITCH) + kf * 32;
                uint32_t vh4[4];
                ldmx4(vh4, st + 1 * FT_B + bo);
                mma16816h(o[nf2 * 2], pah, &vh4[0]);
                mma16816h(o[nf2 * 2 + 1], pah, &vh4[2]);
            }
        }

        BAR_SYNC(barid, 256);    // group done reading stage t&1
        if (t + 2 < 16)
            load_kv(st, kh, vth, bh, kt0 + t + 2, gtid);
    }
    const float lA = ls[0];   // every column of the C-frag holds the row sum
    const float lB = ls[2];

    // ---- merge the two KV-halves (exact fp32, log2-domain maxes) ----
    float* mbuf = reinterpret_cast<float*>(smem + MERGE_OFF);            // 128
    float* lbuf = reinterpret_cast<float*>(smem + MERGE_OFF + 512);      // 128
    float* obuf = reinterpret_cast<float*>(smem + MERGE_OFF + 1024);     // 128 x 68
    const int lr = gw * 16 + (lane >> 2);     // local row 0..127 (rA)
    if (g == 1) {
        if ((lane & 3) == 0) {
            mbuf[lr] = mA; lbuf[lr] = lA;
            mbuf[lr + 8] = mB; lbuf[lr + 8] = lB;
        }
#pragma unroll
        for (int nf = 0; nf < 8; nf++) {
            const int col = nf * 8 + (lane & 3) * 2;
            float2 pa; pa.x = o[nf][0]; pa.y = o[nf][1];
            float2 pb; pb.x = o[nf][2]; pb.y = o[nf][3];
            *reinterpret_cast<float2*>(&obuf[lr * OBUF_STRIDE + col]) = pa;
            *reinterpret_cast<float2*>(&obuf[(lr + 8) * OBUF_STRIDE + col]) = pb;
        }
    }
    __syncthreads();
    if (g == 0) {
        const float m1A = mbuf[lr], l1A = lbuf[lr];
        const float m1B = mbuf[lr + 8], l1B = lbuf[lr + 8];
        const float mfA = fmaxf(mA, m1A);
        const float mfB = fmaxf(mB, m1B);
        const float e0A = ex2f(mA - mfA), e1A = ex2f(m1A - mfA);
        const float e0B = ex2f(mB - mfB), e1B = ex2f(m1B - mfB);
        const float invA = 1.0f / (lA * e0A + l1A * e1A);
        const float invB = 1.0f / (lB * e0B + l1B * e1B);
        const int b = bh >> 4, h = bh & 15;
        const int rA = q0 + lr;
        const int rB = rA + 8;
        const size_t baseA = ((size_t)(b * NSEQ + rA)) * DIMC + h * 64;
        const size_t baseB = ((size_t)(b * NSEQ + rB)) * DIMC + h * 64;
#pragma unroll
        for (int nf = 0; nf < 8; nf++) {
            const int col = nf * 8 + (lane & 3) * 2;
            const float2 p1A = *reinterpret_cast<const float2*>(&obuf[lr * OBUF_STRIDE + col]);
            const float2 p1B =
                *reinterpret_cast<const float2*>(&obuf[(lr + 8) * OBUF_STRIDE + col]);
            const float a0 = (o[nf][0] * e0A + p1A.x * e1A) * invA;
            const float a1 = (o[nf][1] * e0A + p1A.y * e1A) * invA;
            const float b0 = (o[nf][2] * e0B + p1B.x * e1B) * invB;
            const float b1 = (o[nf][3] * e0B + p1B.y * e1B) * invB;
            *reinterpret_cast<__half2*>(O + baseA + col) = __floats2half2_rn(a0, a1);
            *reinterpret_cast<__half2*>(O + baseB + col) = __floats2half2_rn(b0, b1);
        }
    }
}

// ---------------------------------------------------------------------------
extern "C" void kernel_launch(void* const* d_in, const int* in_sizes, int n_in,
                              void* d_out, int out_size) {
    const float* q    = (const float*)d_in[0];
    const float* k    = (const float*)d_in[1];
    const float* v    = (const float*)d_in[2];
    const float* gq   = (const float*)d_in[3];
    const float* bqln = (const float*)d_in[4];
    const float* gk   = (const float*)d_in[5];
    const float* bkln = (const float*)d_in[6];
    const float* gv   = (const float*)d_in[7];
    const float* bvln = (const float*)d_in[8];
    const float* Wq   = (const float*)d_in[9];
    const float* bq   = (const float*)d_in[10];
    const float* Wk   = (const float*)d_in[11];
    const float* bk   = (const float*)d_in[12];
    const float* Wv   = (const float*)d_in[13];
    const float* bv   = (const float*)d_in[14];
    const float* Wp   = (const float*)d_in[15];
    const float* bp   = (const float*)d_in[16];

    float* out = (float*)d_out;
    float* kh  = out + (size_t)MROWS * DIMC;
    float* vh  = kh + (size_t)MROWS * DIMC;

    __half *ln, *wt, *fh, *os;
    float* dummy;
    cudaGetSymbolAddress((void**)&ln, g_ln);
    cudaGetSymbolAddress((void**)&wt, g_wt);
    cudaGetSymbolAddress((void**)&fh, g_fh);
    cudaGetSymbolAddress((void**)&os, g_os);
    cudaGetSymbolAddress((void**)&dummy, g_dummy);

    // 1) Fused LayerNorm -> fp16 (q/k/v in one launch)
    ln_fused<<<dim3(MROWS, 3), 256>>>(q, k, v, gq, bqln, gk, bkln, gv, bvln, ln);

    // 2) Weight transpose to fp16
    wsplit_kernel<<<dim3(32, 32, 4), dim3(32, 8)>>>(Wq, Wk, Wv, Wp, wt);

    // 3) QKV projection (fp16, fp32 accum), emits flash-ready fp16
    cudaFuncSetAttribute(mma_gemm<true>, cudaFuncAttributeMaxDynamicSharedMemorySize, GEMM_SMEM);
    cudaFuncSetAttribute(mma_gemm<false>, cudaFuncAttributeMaxDynamicSharedMemorySize, GEMM_SMEM);
    mma_gemm<true><<<dim3(4, 32, 3), 512, GEMM_SMEM>>>(
        ln, wt, bq, bk, bv, dummy, kh, vh, fh);

    // 4) Flash attention (fp16, log2-softmax, split-KV) -> fp16 row-major
    cudaFuncSetAttribute(flash_mma, cudaFuncAttributeMaxDynamicSharedMemorySize, FLASH_SMEM);
    flash_mma<<<dim3(NSEQ / 128, BHNUM), 512, FLASH_SMEM>>>(fh, os);

    // 5) Output projection (fp16, fp32 accum)
    mma_gemm<false><<<dim3(4, 32, 1), 512, GEMM_SMEM>>>(
        os, wt + 3ull * DIMC * DIMC, bp, bp, bp, out, out, out, fh);
}